// round 5
// baseline (speedup 1.0000x reference)
#include <cuda_runtime.h>
#include <cuda_bf16.h>
#include <math.h>
#include <stdint.h>

#define BB  2
#define SS  2048
#define DD  1024
#define HH  16
#define DKK 64
#define MM  (BB*SS)   // 4096 rows

// scale folded into Q: 1/sqrt(64) * log2(e)
#define SC2 0.18033688011112042f

// ---------------------------------------------------------------------------
// Scratch (allocation-free rule: __device__ globals)
// ---------------------------------------------------------------------------
__device__ __align__(16) float g_PE[SS*DKK];
__device__ __align__(16) float g_Kraw[MM*DD];
__device__ __align__(16) float g_Y[MM*DD];

__device__ __align__(16) __nv_bfloat16 g_Xhi[MM*DD];
__device__ __align__(16) __nv_bfloat16 g_Xlo[MM*DD];
__device__ __align__(16) __nv_bfloat16 g_Wh[3*DD*DD];
__device__ __align__(16) __nv_bfloat16 g_Wl[3*DD*DD];
__device__ __align__(16) __nv_bfloat16 g_Woh[DD*DD];
__device__ __align__(16) __nv_bfloat16 g_Wol[DD*DD];
__device__ __align__(16) __nv_bfloat16 g_Ahi[MM*DD];
__device__ __align__(16) __nv_bfloat16 g_Alo[MM*DD];

// attention operands, head-split [B*H][S][64], bf16 hi/lo
__device__ __align__(16) __nv_bfloat16 g_Qhi[MM*DD];
__device__ __align__(16) __nv_bfloat16 g_Qlo[MM*DD];
__device__ __align__(16) __nv_bfloat16 g_Khi[MM*DD];
__device__ __align__(16) __nv_bfloat16 g_Klo[MM*DD];
__device__ __align__(16) __nv_bfloat16 g_Vhi[MM*DD];
__device__ __align__(16) __nv_bfloat16 g_Vlo[MM*DD];

// ---------------------------------------------------------------------------
// PTX helpers (baseline sm_103-safe)
// ---------------------------------------------------------------------------
__device__ __forceinline__ uint32_t smem_u32(const void* p) {
    uint32_t a;
    asm("{ .reg .u64 t; cvta.to.shared.u64 t, %1; cvt.u32.u64 %0, t; }"
        : "=r"(a) : "l"(p));
    return a;
}

#define CPA16(dst, src) \
    asm volatile("cp.async.cg.shared.global [%0], [%1], 16;" :: "r"(dst), "l"(src) : "memory")
#define CPA_COMMIT() asm volatile("cp.async.commit_group;" ::: "memory")
#define CPA_WAIT1()  asm volatile("cp.async.wait_group 1;" ::: "memory")
#define CPA_WAIT0()  asm volatile("cp.async.wait_group 0;" ::: "memory")

__device__ __forceinline__ void ldsm_x4(uint32_t* r, uint32_t addr) {
    asm volatile("ldmatrix.sync.aligned.m8n8.x4.shared.b16 {%0,%1,%2,%3}, [%4];"
                 : "=r"(r[0]), "=r"(r[1]), "=r"(r[2]), "=r"(r[3]) : "r"(addr));
}
__device__ __forceinline__ void ldsm_x4_t(uint32_t* r, uint32_t addr) {
    asm volatile("ldmatrix.sync.aligned.m8n8.x4.trans.shared.b16 {%0,%1,%2,%3}, [%4];"
                 : "=r"(r[0]), "=r"(r[1]), "=r"(r[2]), "=r"(r[3]) : "r"(addr));
}

__device__ __forceinline__ void mma_bf16(float* c, const uint32_t* a, const uint32_t* b) {
    asm volatile(
        "mma.sync.aligned.m16n8k16.row.col.f32.bf16.bf16.f32 "
        "{%0,%1,%2,%3}, {%4,%5,%6,%7}, {%8,%9}, {%0,%1,%2,%3};"
        : "+f"(c[0]), "+f"(c[1]), "+f"(c[2]), "+f"(c[3])
        : "r"(a[0]), "r"(a[1]), "r"(a[2]), "r"(a[3]), "r"(b[0]), "r"(b[1]));
}

__device__ __forceinline__ float ex2(float x) {
    float r;
    asm("ex2.approx.ftz.f32 %0, %1;" : "=f"(r) : "f"(x));
    return r;
}
__device__ __forceinline__ uint32_t pk_bf2(float a, float b) {
    uint32_t r;
    asm("cvt.rn.bf16x2.f32 %0, %1, %2;" : "=r"(r) : "f"(b), "f"(a));
    return r;
}
__device__ __forceinline__ float bf_lo(uint32_t r) { return __uint_as_float(r << 16); }
__device__ __forceinline__ float bf_hi(uint32_t r) { return __uint_as_float(r & 0xFFFF0000u); }

// ---------------------------------------------------------------------------
__global__ void pe_kernel() {
    int idx = blockIdx.x * blockDim.x + threadIdx.x;
    if (idx >= SS * DKK) return;
    int s  = idx >> 6;
    int dk = idx & 63;
    int i  = dk >> 1;
    float freq = expf(-((float)(2 * i) / 64.0f) * 9.210340371976184f);
    float ang  = (float)s * freq;
    g_PE[idx]  = (dk & 1) ? cosf(ang) : sinf(ang);
}

// ---------------------------------------------------------------------------
// fp32 -> bf16 hi/lo split
// ---------------------------------------------------------------------------
__global__ void conv_kernel(const float* __restrict__ src,
                            __nv_bfloat16* __restrict__ hi,
                            __nv_bfloat16* __restrict__ lo, int n4) {
    int i = blockIdx.x * blockDim.x + threadIdx.x;
    if (i >= n4) return;
    float4 v = ((const float4*)src)[i];
    __nv_bfloat16 h0 = __float2bfloat16(v.x);
    __nv_bfloat16 h1 = __float2bfloat16(v.y);
    __nv_bfloat16 h2 = __float2bfloat16(v.z);
    __nv_bfloat16 h3 = __float2bfloat16(v.w);
    __nv_bfloat16 l0 = __float2bfloat16(v.x - __bfloat162float(h0));
    __nv_bfloat16 l1 = __float2bfloat16(v.y - __bfloat162float(h1));
    __nv_bfloat16 l2 = __float2bfloat16(v.z - __bfloat162float(h2));
    __nv_bfloat16 l3 = __float2bfloat16(v.w - __bfloat162float(h3));
    __nv_bfloat162* hp = (__nv_bfloat162*)hi;
    __nv_bfloat162* lp = (__nv_bfloat162*)lo;
    hp[2*i]   = __nv_bfloat162(h0, h1);
    hp[2*i+1] = __nv_bfloat162(h2, h3);
    lp[2*i]   = __nv_bfloat162(l0, l1);
    lp[2*i+1] = __nv_bfloat162(l2, l3);
}

// ---------------------------------------------------------------------------
// bf16x3 HMMA GEMM mainloop (proven; unchanged)
// ---------------------------------------------------------------------------
#define ROWB 80
#define MATB (128 * ROWB)
#define STG  (4 * MATB)
#define DYN_SMEM (2 * STG)

__device__ __forceinline__ void mma_gemm(
    const __nv_bfloat16* __restrict__ Ah, const __nv_bfloat16* __restrict__ Al,
    const __nv_bfloat16* __restrict__ Bh, const __nv_bfloat16* __restrict__ Bl,
    char* dyn, float acc[2][8][4])
{
    int t    = threadIdx.x;
    int lane = t & 31;
    int wid  = t >> 5;
    int wm   = wid >> 1;
    int wn   = wid & 1;
    uint32_t sbase = smem_u32(dyn);

    const char* mats[4] = {(const char*)Ah, (const char*)Al,
                           (const char*)Bh, (const char*)Bl};

#pragma unroll
    for (int tm = 0; tm < 2; tm++)
#pragma unroll
        for (int tn = 0; tn < 8; tn++)
#pragma unroll
            for (int u = 0; u < 4; u++) acc[tm][tn][u] = 0.0f;

    int idx0 = t * 8;
    auto load_stage = [&](int st, int kb) {
        uint32_t stb = sbase + st * STG;
#pragma unroll
        for (int q = 0; q < 8; q++) {
            int idx = idx0 + q;
            int mat = idx >> 9;
            int r   = (idx >> 2) & 127;
            int c16 = idx & 3;
            uint32_t dst = stb + mat * MATB + r * ROWB + c16 * 16;
            const char* src = mats[mat] + ((size_t)r * 1024 + kb + c16 * 8) * 2;
            CPA16(dst, src);
        }
        CPA_COMMIT();
    };

    int a_row = wm * 32 + (lane & 15);
    int b_row = wn * 64 + (lane & 7) + 8 * (lane >> 4);

    load_stage(0, 0);

    for (int it = 0; it < 32; it++) {
        int st = it & 1;
        if (it + 1 < 32) {
            load_stage(st ^ 1, (it + 1) * 32);
            CPA_WAIT1();
        } else {
            CPA_WAIT0();
        }
        __syncthreads();

        uint32_t stb = sbase + st * STG;
#pragma unroll
        for (int ks = 0; ks < 2; ks++) {
            int k0 = ks * 16;
            uint32_t aH[2][4], aL[2][4], bH[8][2], bL[8][2];
            int a_col = (k0 + 8 * (lane >> 4)) * 2;
            int b_col = (k0 + 8 * ((lane >> 3) & 1)) * 2;
#pragma unroll
            for (int tm = 0; tm < 2; tm++) {
                uint32_t off = (uint32_t)((a_row + 16 * tm) * ROWB + a_col);
                ldsm_x4(aH[tm], stb + 0 * MATB + off);
                ldsm_x4(aL[tm], stb + 1 * MATB + off);
            }
#pragma unroll
            for (int tp = 0; tp < 4; tp++) {
                uint32_t off = (uint32_t)((b_row + 16 * tp) * ROWB + b_col);
                ldsm_x4(&bH[2 * tp][0], stb + 2 * MATB + off);
                ldsm_x4(&bL[2 * tp][0], stb + 3 * MATB + off);
            }
#pragma unroll
            for (int tm = 0; tm < 2; tm++)
#pragma unroll
                for (int tn = 0; tn < 8; tn++) {
                    mma_bf16(acc[tm][tn], aH[tm], bH[tn]);
                    mma_bf16(acc[tm][tn], aH[tm], bL[tn]);
                    mma_bf16(acc[tm][tn], aL[tm], bH[tn]);
                }
        }
        __syncthreads();
    }
}

// ---------------------------------------------------------------------------
// QKV GEMM. z=0: Q -> (acc+PE)*SC2 split bf16; z=1: K fp32; z=2: V split bf16
// ---------------------------------------------------------------------------
__global__ __launch_bounds__(256) void qkv_mma() {
    extern __shared__ char dyn[];
    float acc[2][8][4];

    int z  = blockIdx.z;
    int m0 = blockIdx.y * 128;
    int n0 = blockIdx.x * 128;

    mma_gemm(g_Xhi + (size_t)m0 * 1024, g_Xlo + (size_t)m0 * 1024,
             g_Wh + (size_t)z * DD * DD + (size_t)n0 * 1024,
             g_Wl + (size_t)z * DD * DD + (size_t)n0 * 1024,
             dyn, acc);

    int t = threadIdx.x, lane = t & 31, wid = t >> 5;
    int wm = wid >> 1, wn = wid & 1;

#pragma unroll
    for (int tm = 0; tm < 2; tm++)
#pragma unroll
        for (int tn = 0; tn < 8; tn++) {
            int c  = n0 + wn * 64 + tn * 8 + (lane & 3) * 2;
            int h  = c >> 6, dk = c & 63;
#pragma unroll
            for (int half = 0; half < 2; half++) {
                int m = m0 + wm * 32 + tm * 16 + (lane >> 2) + 8 * half;
                int b = m >> 11, s = m & 2047;
                float vx = acc[tm][tn][2 * half + 0];
                float vy = acc[tm][tn][2 * half + 1];
                size_t off = ((size_t)((b * 16 + h) * 2048 + s)) * 64 + dk;
                if (z == 1) {
                    float2 v; v.x = vx; v.y = vy;
                    *(float2*)&g_Kraw[off] = v;
                } else {
                    if (z == 0) {
                        float2 pe = *(const float2*)&g_PE[s * 64 + dk];
                        vx = (vx + pe.x) * SC2;
                        vy = (vy + pe.y) * SC2;
                    }
                    __nv_bfloat16 hx = __float2bfloat16(vx);
                    __nv_bfloat16 hy = __float2bfloat16(vy);
                    __nv_bfloat16 lx = __float2bfloat16(vx - __bfloat162float(hx));
                    __nv_bfloat16 ly = __float2bfloat16(vy - __bfloat162float(hy));
                    __nv_bfloat162* oh = (__nv_bfloat162*)((z == 0) ? g_Qhi : g_Vhi);
                    __nv_bfloat162* ol = (__nv_bfloat162*)((z == 0) ? g_Qlo : g_Vlo);
                    oh[off >> 1] = __nv_bfloat162(hx, hy);
                    ol[off >> 1] = __nv_bfloat162(lx, ly);
                }
            }
        }
}

// ---------------------------------------------------------------------------
// EMA smear on K + PE add, output split to bf16 hi/lo
// ---------------------------------------------------------------------------
__global__ void smear_kernel(const float* __restrict__ alpha) {
    int idx = blockIdx.x * blockDim.x + threadIdx.x;
    int dk = idx & 63;
    int s  = (idx >> 6) & 2047;
    int h  = (idx >> 17) & 15;
    float kc = g_Kraw[idx];
    float v;
    if (s == 0) {
        v = kc;
    } else {
        float a = 1.0f / (1.0f + expf(-alpha[h * 2047 + (s - 1)]));
        v = a * kc + (1.0f - a) * g_Kraw[idx - 64];
    }
    v += g_PE[s * 64 + dk];
    __nv_bfloat16 hv = __float2bfloat16(v);
    g_Khi[idx] = hv;
    g_Klo[idx] = __float2bfloat16(v - __bfloat162float(hv));
}

// ---------------------------------------------------------------------------
// Causal flash attention, bf16x3 HMMA, 2-stage double-buffered KV pipeline.
// BM=64, BN=64, 128 threads (4 warps, 16 q-rows each).
// Dynamic smem: 2 stages x 4 mats x 64 rows x 144B = 73728 B.
// ---------------------------------------------------------------------------
#define ASTR 144
#define AMAT (64 * ASTR)       // 9216
#define ASTG (4 * AMAT)        // 36864
#define ATT_SMEM (2 * ASTG)    // 73728

__global__ __launch_bounds__(128) void attn_mma() {
    extern __shared__ __align__(16) char asm_dyn[];
    uint32_t sb = smem_u32(asm_dyn);

    int t = threadIdx.x, lane = t & 31, w = t >> 5;
    int qt = 31 - (int)blockIdx.x;          // heavy tiles first
    int qb = qt * 64;
    int bh = blockIdx.y;
    size_t base = (size_t)bh * SS * DKK;

    // ---- stage Q tile into stage 0 (hi -> mat0, lo -> mat1), extract frags ----
    {
        const char* qsrc[2] = {(const char*)(g_Qhi + base), (const char*)(g_Qlo + base)};
#pragma unroll
        for (int q = 0; q < 8; q++) {
            int idx = t * 8 + q;
            int mat = idx >> 9;
            int r   = (idx >> 3) & 63;
            int c   = idx & 7;
            CPA16(sb + mat * AMAT + r * ASTR + c * 16,
                  qsrc[mat] + ((size_t)(qb + r) * 64 + c * 8) * 2);
        }
        CPA_COMMIT(); CPA_WAIT0();
        __syncthreads();
    }

    uint32_t qh[4][4], ql[4][4];
    {
        int ar = w * 16 + (lane & 15);
#pragma unroll
        for (int k = 0; k < 4; k++) {
            uint32_t acol = (uint32_t)(k * 32 + (lane >> 4) * 16);
            ldsm_x4(qh[k], sb + 0 * AMAT + ar * ASTR + acol);
            ldsm_x4(ql[k], sb + 1 * AMAT + ar * ASTR + acol);
        }
    }
    __syncthreads();   // Q frags extracted before stage 0 is reused for KV

    float o[8][4];
    float m2[2], lsum[2];
#pragma unroll
    for (int j = 0; j < 8; j++)
#pragma unroll
        for (int u = 0; u < 4; u++) o[j][u] = 0.0f;
    m2[0] = m2[1] = -1e30f;
    lsum[0] = lsum[1] = 0.0f;

    const char* kvsrc[4] = {(const char*)(g_Khi + base), (const char*)(g_Klo + base),
                            (const char*)(g_Vhi + base), (const char*)(g_Vlo + base)};

    // one group per tile: K hi/lo + V hi/lo (32KB)
    auto load_kv = [&](int kb, int st) {
        uint32_t stb = sb + st * ASTG;
#pragma unroll
        for (int q = 0; q < 16; q++) {
            int idx = t * 16 + q;
            int mat = idx >> 9;
            int r   = (idx >> 3) & 63;
            int c   = idx & 7;
            CPA16(stb + mat * AMAT + r * ASTR + c * 16,
                  kvsrc[mat] + ((size_t)(kb + r) * 64 + c * 8) * 2);
        }
        CPA_COMMIT();
    };

    int r0 = (lane >> 2);
    int ntiles = qt + 1;

    load_kv(0, 0);

    for (int tile = 0; tile < ntiles; tile++) {
        int st = tile & 1;
        if (tile + 1 < ntiles) {
            load_kv((tile + 1) * 64, st ^ 1);
            CPA_WAIT1();
        } else {
            CPA_WAIT0();
        }
        __syncthreads();

        uint32_t stb = sb + st * ASTG;

        // ---- S = Q K^T (bf16x3) ----
        float s[8][4];
#pragma unroll
        for (int j = 0; j < 8; j++)
#pragma unroll
            for (int u = 0; u < 4; u++) s[j][u] = 0.0f;

        {
            int b_row = (lane & 7) + 8 * (lane >> 4);
#pragma unroll
            for (int k = 0; k < 4; k++) {
                uint32_t bcol = (uint32_t)((k * 16 + 8 * ((lane >> 3) & 1)) * 2);
                uint32_t kH[8][2], kL[8][2];
#pragma unroll
                for (int tp = 0; tp < 4; tp++) {
                    uint32_t off = (uint32_t)((b_row + 16 * tp) * ASTR) + bcol;
                    ldsm_x4(&kH[2 * tp][0], stb + 0 * AMAT + off);
                    ldsm_x4(&kL[2 * tp][0], stb + 1 * AMAT + off);
                }
#pragma unroll
                for (int j = 0; j < 8; j++) {
                    mma_bf16(s[j], qh[k], kH[j]);
                    mma_bf16(s[j], qh[k], kL[j]);
                    mma_bf16(s[j], ql[k], kH[j]);
                }
            }
        }

        // ---- mask (diagonal tile) ----
        if (tile == ntiles - 1) {
#pragma unroll
            for (int j = 0; j < 8; j++)
#pragma unroll
                for (int u = 0; u < 4; u++) {
                    int row = (w * 16) + r0 + 8 * (u >> 1);
                    int col = j * 8 + 2 * (lane & 3) + (u & 1);
                    if (col > row) s[j][u] = -1e30f;
                }
        }

        // ---- online softmax (base 2), per row half ----
#pragma unroll
        for (int h = 0; h < 2; h++) {
            float mx = -1e30f;
#pragma unroll
            for (int j = 0; j < 8; j++) {
                mx = fmaxf(mx, s[j][2 * h + 0]);
                mx = fmaxf(mx, s[j][2 * h + 1]);
            }
            mx = fmaxf(mx, __shfl_xor_sync(0xffffffffu, mx, 1));
            mx = fmaxf(mx, __shfl_xor_sync(0xffffffffu, mx, 2));
            float mnew = fmaxf(m2[h], mx);
            float corr = ex2(m2[h] - mnew);
            m2[h] = mnew;
            float rs = 0.0f;
#pragma unroll
            for (int j = 0; j < 8; j++) {
                float p0 = ex2(s[j][2 * h + 0] - mnew);
                float p1 = ex2(s[j][2 * h + 1] - mnew);
                s[j][2 * h + 0] = p0;
                s[j][2 * h + 1] = p1;
                rs += p0 + p1;
            }
            lsum[h] = lsum[h] * corr + rs;
#pragma unroll
            for (int j = 0; j < 8; j++) {
                o[j][2 * h + 0] *= corr;
                o[j][2 * h + 1] *= corr;
            }
        }

        // ---- P fragments (C->A remap, hi/lo split in registers) ----
        uint32_t pH[4][4], pL[4][4];
#pragma unroll
        for (int kk = 0; kk < 4; kk++) {
            int j = 2 * kk;
#pragma unroll
            for (int q = 0; q < 4; q++) {
                int jj = j + (q >> 1);
                float a = s[jj][(q & 1) * 2 + 0];
                float b = s[jj][(q & 1) * 2 + 1];
                uint32_t hi2 = pk_bf2(a, b);
                pH[kk][q] = hi2;
                pL[kk][q] = pk_bf2(a - bf_lo(hi2), b - bf_hi(hi2));
            }
        }

        // ---- O += P V (bf16x3), V via ldmatrix.trans ----
        {
            int vrow = (lane & 7) + 8 * ((lane >> 3) & 1);
            uint32_t vcol = (uint32_t)(16 * (lane >> 4));
#pragma unroll
            for (int kk = 0; kk < 4; kk++) {
                uint32_t vH[8][2], vL[8][2];
#pragma unroll
                for (int jj = 0; jj < 4; jj++) {
                    uint32_t off = (uint32_t)((kk * 16 + vrow) * ASTR) + (uint32_t)(jj * 32) + vcol;
                    ldsm_x4_t(&vH[2 * jj][0], stb + 2 * AMAT + off);
                    ldsm_x4_t(&vL[2 * jj][0], stb + 3 * AMAT + off);
                }
#pragma unroll
                for (int j = 0; j < 8; j++) {
                    mma_bf16(o[j], pH[kk], vH[j]);
                    mma_bf16(o[j], pL[kk], vH[j]);
                    mma_bf16(o[j], pH[kk], vL[j]);
                }
            }
        }
        __syncthreads();   // all warps done reading stage st before it is refilled
    }

    // ---- epilogue: normalize, split to bf16 hi/lo, store ----
#pragma unroll
    for (int h = 0; h < 2; h++) {
        lsum[h] += __shfl_xor_sync(0xffffffffu, lsum[h], 1);
        lsum[h] += __shfl_xor_sync(0xffffffffu, lsum[h], 2);
        lsum[h] = 1.0f / lsum[h];
    }

    int b = bh >> 4, hh = bh & 15;
#pragma unroll
    for (int j = 0; j < 8; j++) {
        int dk = j * 8 + 2 * (lane & 3);
#pragma unroll
        for (int h = 0; h < 2; h++) {
            int srow = qb + w * 16 + r0 + 8 * h;
            float f0 = o[j][2 * h + 0] * lsum[h];
            float f1 = o[j][2 * h + 1] * lsum[h];
            __nv_bfloat16 h0 = __float2bfloat16(f0);
            __nv_bfloat16 h1 = __float2bfloat16(f1);
            __nv_bfloat16 l0 = __float2bfloat16(f0 - __bfloat162float(h0));
            __nv_bfloat16 l1 = __float2bfloat16(f1 - __bfloat162float(h1));
            size_t off = ((size_t)(b * SS + srow) * DD + hh * 64 + dk) >> 1;
            ((__nv_bfloat162*)g_Ahi)[off] = __nv_bfloat162(h0, h1);
            ((__nv_bfloat162*)g_Alo)[off] = __nv_bfloat162(l0, l1);
        }
    }
}

// ---------------------------------------------------------------------------
// Output projection GEMM: Y = attn @ Wo^T + X
// ---------------------------------------------------------------------------
__global__ __launch_bounds__(256) void oproj_mma(const float* __restrict__ X) {
    extern __shared__ char dyn[];
    float acc[2][8][4];

    int m0 = blockIdx.y * 128;
    int n0 = blockIdx.x * 128;

    mma_gemm(g_Ahi + (size_t)m0 * 1024, g_Alo + (size_t)m0 * 1024,
             g_Woh + (size_t)n0 * 1024, g_Wol + (size_t)n0 * 1024,
             dyn, acc);

    int t = threadIdx.x, lane = t & 31, wid = t >> 5;
    int wm = wid >> 1, wn = wid & 1;
#pragma unroll
    for (int tm = 0; tm < 2; tm++)
#pragma unroll
        for (int tn = 0; tn < 8; tn++) {
            int c = n0 + wn * 64 + tn * 8 + (lane & 3) * 2;
#pragma unroll
            for (int half = 0; half < 2; half++) {
                int m = m0 + wm * 32 + tm * 16 + (lane >> 2) + 8 * half;
                float2 xr = *(const float2*)&X[(size_t)m * 1024 + c];
                float2 v;
                v.x = acc[tm][tn][2 * half + 0] + xr.x;
                v.y = acc[tm][tn][2 * half + 1] + xr.y;
                *(float2*)&g_Y[(size_t)m * 1024 + c] = v;
            }
        }
}

// ---------------------------------------------------------------------------
// LayerNorm over D=1024 per row
// ---------------------------------------------------------------------------
__global__ void ln_kernel(const float* __restrict__ gamma,
                          const float* __restrict__ beta,
                          float* __restrict__ out)
{
    int row = blockIdx.x;
    int t   = threadIdx.x;
    const float* y = g_Y + (size_t)row * 1024;

    float x[4];
    float s = 0.0f;
#pragma unroll
    for (int u = 0; u < 4; u++) { x[u] = y[t + 256 * u]; s += x[u]; }

    __shared__ float red[32];
#pragma unroll
    for (int off = 16; off; off >>= 1) s += __shfl_xor_sync(0xffffffffu, s, off);
    if ((t & 31) == 0) red[t >> 5] = s;
    __syncthreads();
    if (t == 0) {
        float tot = 0.0f;
        for (int w = 0; w < 8; w++) tot += red[w];
        red[8] = tot;
    }
    __syncthreads();
    float mean = red[8] * (1.0f / 1024.0f);

    float vs = 0.0f;
#pragma unroll
    for (int u = 0; u < 4; u++) { float d = x[u] - mean; vs += d * d; }
#pragma unroll
    for (int off = 16; off; off >>= 1) vs += __shfl_xor_sync(0xffffffffu, vs, off);
    if ((t & 31) == 0) red[16 + (t >> 5)] = vs;
    __syncthreads();
    if (t == 0) {
        float tot = 0.0f;
        for (int w = 0; w < 8; w++) tot += red[16 + w];
        red[24] = tot;
    }
    __syncthreads();
    float var  = red[24] * (1.0f / 1024.0f);
    float rstd = rsqrtf(var + 1e-5f);

#pragma unroll
    for (int u = 0; u < 4; u++) {
        int c = t + 256 * u;
        out[(size_t)row * 1024 + c] = (x[u] - mean) * rstd * gamma[c] + beta[c];
    }
}

// ---------------------------------------------------------------------------
extern "C" void kernel_launch(void* const* d_in, const int* in_sizes, int n_in,
                              void* d_out, int out_size)
{
    const float* X     = (const float*)d_in[0];
    const float* Wq    = (const float*)d_in[1];
    const float* Wk    = (const float*)d_in[2];
    const float* Wv    = (const float*)d_in[3];
    const float* Wo    = (const float*)d_in[4];
    const float* alpha = (const float*)d_in[5];
    const float* lns   = (const float*)d_in[6];
    const float* lnb   = (const float*)d_in[7];
    float* out = (float*)d_out;

    static int attr_set = 0;
    if (!attr_set) {
        cudaFuncSetAttribute(qkv_mma,   cudaFuncAttributeMaxDynamicSharedMemorySize, DYN_SMEM);
        cudaFuncSetAttribute(oproj_mma, cudaFuncAttributeMaxDynamicSharedMemorySize, DYN_SMEM);
        cudaFuncSetAttribute(attn_mma,  cudaFuncAttributeMaxDynamicSharedMemorySize, ATT_SMEM);
        attr_set = 1;
    }

    __nv_bfloat16 *Whi, *Wlo, *Xhi, *Xlo, *Woh, *Wol;
    cudaGetSymbolAddress((void**)&Whi, g_Wh);
    cudaGetSymbolAddress((void**)&Wlo, g_Wl);
    cudaGetSymbolAddress((void**)&Xhi, g_Xhi);
    cudaGetSymbolAddress((void**)&Xlo, g_Xlo);
    cudaGetSymbolAddress((void**)&Woh, g_Woh);
    cudaGetSymbolAddress((void**)&Wol, g_Wol);

    pe_kernel<<<(SS * DKK + 255) / 256, 256>>>();
    conv_kernel<<<4096, 256>>>(X, Xhi, Xlo, MM * DD / 4);
    conv_kernel<<<1024, 256>>>(Wq, Whi,             Wlo,             DD * DD / 4);
    conv_kernel<<<1024, 256>>>(Wk, Whi + DD * DD,   Wlo + DD * DD,   DD * DD / 4);
    conv_kernel<<<1024, 256>>>(Wv, Whi + 2*DD*DD,   Wlo + 2*DD*DD,   DD * DD / 4);
    conv_kernel<<<1024, 256>>>(Wo, Woh, Wol, DD * DD / 4);

    qkv_mma<<<dim3(8, 32, 3), 256, DYN_SMEM>>>();
    smear_kernel<<<(MM * DD) / 256, 256>>>(alpha);
    attn_mma<<<dim3(32, 32), 128, ATT_SMEM>>>();
    oproj_mma<<<dim3(8, 32), 256, DYN_SMEM>>>(X);
    ln_kernel<<<MM, 256>>>(lns, lnb, out);
}

// round 6
// speedup vs baseline: 1.0625x; 1.0625x over previous
#include <cuda_runtime.h>
#include <cuda_bf16.h>
#include <math.h>
#include <stdint.h>

#define BB  2
#define SS  2048
#define DD  1024
#define HH  16
#define DKK 64
#define MM  (BB*SS)   // 4096 rows

// scale folded into Q: 1/sqrt(64) * log2(e)
#define SC2 0.18033688011112042f

// ---------------------------------------------------------------------------
// Scratch (allocation-free rule: __device__ globals)
// ---------------------------------------------------------------------------
__device__ __align__(16) float g_PE[SS*DKK];
__device__ __align__(16) float g_Kraw[MM*DD];
__device__ __align__(16) float g_Y[MM*DD];

__device__ __align__(16) __nv_bfloat16 g_Xhi[MM*DD];
__device__ __align__(16) __nv_bfloat16 g_Xlo[MM*DD];
__device__ __align__(16) __nv_bfloat16 g_Wh[3*DD*DD];
__device__ __align__(16) __nv_bfloat16 g_Wl[3*DD*DD];
__device__ __align__(16) __nv_bfloat16 g_Woh[DD*DD];
__device__ __align__(16) __nv_bfloat16 g_Wol[DD*DD];
__device__ __align__(16) __nv_bfloat16 g_Ahi[MM*DD];
__device__ __align__(16) __nv_bfloat16 g_Alo[MM*DD];

// attention operands, head-split [B*H][S][64], bf16 hi/lo
__device__ __align__(16) __nv_bfloat16 g_Qhi[MM*DD];
__device__ __align__(16) __nv_bfloat16 g_Qlo[MM*DD];
__device__ __align__(16) __nv_bfloat16 g_Khi[MM*DD];
__device__ __align__(16) __nv_bfloat16 g_Klo[MM*DD];
__device__ __align__(16) __nv_bfloat16 g_Vhi[MM*DD];
__device__ __align__(16) __nv_bfloat16 g_Vlo[MM*DD];

// ---------------------------------------------------------------------------
// PTX helpers (baseline sm_103-safe)
// ---------------------------------------------------------------------------
__device__ __forceinline__ uint32_t smem_u32(const void* p) {
    uint32_t a;
    asm("{ .reg .u64 t; cvta.to.shared.u64 t, %1; cvt.u32.u64 %0, t; }"
        : "=r"(a) : "l"(p));
    return a;
}

#define CPA16(dst, src) \
    asm volatile("cp.async.cg.shared.global [%0], [%1], 16;" :: "r"(dst), "l"(src) : "memory")
#define CPA_COMMIT() asm volatile("cp.async.commit_group;" ::: "memory")
#define CPA_WAIT1()  asm volatile("cp.async.wait_group 1;" ::: "memory")
#define CPA_WAIT0()  asm volatile("cp.async.wait_group 0;" ::: "memory")

__device__ __forceinline__ void ldsm_x4(uint32_t* r, uint32_t addr) {
    asm volatile("ldmatrix.sync.aligned.m8n8.x4.shared.b16 {%0,%1,%2,%3}, [%4];"
                 : "=r"(r[0]), "=r"(r[1]), "=r"(r[2]), "=r"(r[3]) : "r"(addr));
}
__device__ __forceinline__ void ldsm_x4_t(uint32_t* r, uint32_t addr) {
    asm volatile("ldmatrix.sync.aligned.m8n8.x4.trans.shared.b16 {%0,%1,%2,%3}, [%4];"
                 : "=r"(r[0]), "=r"(r[1]), "=r"(r[2]), "=r"(r[3]) : "r"(addr));
}

__device__ __forceinline__ void mma_bf16(float* c, const uint32_t* a, const uint32_t* b) {
    asm volatile(
        "mma.sync.aligned.m16n8k16.row.col.f32.bf16.bf16.f32 "
        "{%0,%1,%2,%3}, {%4,%5,%6,%7}, {%8,%9}, {%0,%1,%2,%3};"
        : "+f"(c[0]), "+f"(c[1]), "+f"(c[2]), "+f"(c[3])
        : "r"(a[0]), "r"(a[1]), "r"(a[2]), "r"(a[3]), "r"(b[0]), "r"(b[1]));
}

__device__ __forceinline__ float ex2(float x) {
    float r;
    asm("ex2.approx.ftz.f32 %0, %1;" : "=f"(r) : "f"(x));
    return r;
}
__device__ __forceinline__ uint32_t pk_bf2(float a, float b) {
    uint32_t r;
    asm("cvt.rn.bf16x2.f32 %0, %1, %2;" : "=r"(r) : "f"(b), "f"(a));
    return r;
}
__device__ __forceinline__ float bf_lo(uint32_t r) { return __uint_as_float(r << 16); }
__device__ __forceinline__ float bf_hi(uint32_t r) { return __uint_as_float(r & 0xFFFF0000u); }

// ---------------------------------------------------------------------------
__global__ void pe_kernel() {
    int idx = blockIdx.x * blockDim.x + threadIdx.x;
    if (idx >= SS * DKK) return;
    int s  = idx >> 6;
    int dk = idx & 63;
    int i  = dk >> 1;
    float freq = expf(-((float)(2 * i) / 64.0f) * 9.210340371976184f);
    float ang  = (float)s * freq;
    g_PE[idx]  = (dk & 1) ? cosf(ang) : sinf(ang);
}

// ---------------------------------------------------------------------------
// fp32 -> bf16 hi/lo split (X)
// ---------------------------------------------------------------------------
__device__ __forceinline__ void split4(float4 v, __nv_bfloat162* hp, __nv_bfloat162* lp, int i) {
    __nv_bfloat16 h0 = __float2bfloat16(v.x);
    __nv_bfloat16 h1 = __float2bfloat16(v.y);
    __nv_bfloat16 h2 = __float2bfloat16(v.z);
    __nv_bfloat16 h3 = __float2bfloat16(v.w);
    __nv_bfloat16 l0 = __float2bfloat16(v.x - __bfloat162float(h0));
    __nv_bfloat16 l1 = __float2bfloat16(v.y - __bfloat162float(h1));
    __nv_bfloat16 l2 = __float2bfloat16(v.z - __bfloat162float(h2));
    __nv_bfloat16 l3 = __float2bfloat16(v.w - __bfloat162float(h3));
    hp[2*i]   = __nv_bfloat162(h0, h1);
    hp[2*i+1] = __nv_bfloat162(h2, h3);
    lp[2*i]   = __nv_bfloat162(l0, l1);
    lp[2*i+1] = __nv_bfloat162(l2, l3);
}

__global__ void convx_kernel(const float* __restrict__ src) {
    int i = blockIdx.x * blockDim.x + threadIdx.x;   // n4 = MM*DD/4
    split4(((const float4*)src)[i], (__nv_bfloat162*)g_Xhi, (__nv_bfloat162*)g_Xlo, i);
}

// all 4 weight matrices in one launch: mat = 0..3 (Wq,Wk,Wv,Wo)
__global__ void convw_kernel(const float* __restrict__ Wq, const float* __restrict__ Wk,
                             const float* __restrict__ Wv, const float* __restrict__ Wo) {
    int gi  = blockIdx.x * blockDim.x + threadIdx.x;  // 4 * DD*DD/4
    int mat = gi >> 18;                               // DD*DD/4 = 262144 per matrix
    int i   = gi & 0x3FFFF;
    const float* src = (mat == 0) ? Wq : (mat == 1) ? Wk : (mat == 2) ? Wv : Wo;
    __nv_bfloat162* hp;
    __nv_bfloat162* lp;
    if (mat < 3) {
        hp = (__nv_bfloat162*)(g_Wh + (size_t)mat * DD * DD);
        lp = (__nv_bfloat162*)(g_Wl + (size_t)mat * DD * DD);
    } else {
        hp = (__nv_bfloat162*)g_Woh;
        lp = (__nv_bfloat162*)g_Wol;
    }
    split4(((const float4*)src)[i], hp, lp, i);
}

// ---------------------------------------------------------------------------
// bf16x3 HMMA GEMM mainloop
// ---------------------------------------------------------------------------
#define ROWB 80
#define MATB (128 * ROWB)
#define STG  (4 * MATB)
#define DYN_SMEM (2 * STG)

__device__ __forceinline__ void mma_gemm(
    const __nv_bfloat16* __restrict__ Ah, const __nv_bfloat16* __restrict__ Al,
    const __nv_bfloat16* __restrict__ Bh, const __nv_bfloat16* __restrict__ Bl,
    char* dyn, float acc[2][8][4])
{
    int t    = threadIdx.x;
    int lane = t & 31;
    int wid  = t >> 5;
    int wm   = wid >> 1;
    int wn   = wid & 1;
    uint32_t sbase = smem_u32(dyn);

    const char* mats[4] = {(const char*)Ah, (const char*)Al,
                           (const char*)Bh, (const char*)Bl};

#pragma unroll
    for (int tm = 0; tm < 2; tm++)
#pragma unroll
        for (int tn = 0; tn < 8; tn++)
#pragma unroll
            for (int u = 0; u < 4; u++) acc[tm][tn][u] = 0.0f;

    int idx0 = t * 8;
    auto load_stage = [&](int st, int kb) {
        uint32_t stb = sbase + st * STG;
#pragma unroll
        for (int q = 0; q < 8; q++) {
            int idx = idx0 + q;
            int mat = idx >> 9;
            int r   = (idx >> 2) & 127;
            int c16 = idx & 3;
            uint32_t dst = stb + mat * MATB + r * ROWB + c16 * 16;
            const char* src = mats[mat] + ((size_t)r * 1024 + kb + c16 * 8) * 2;
            CPA16(dst, src);
        }
        CPA_COMMIT();
    };

    int a_row = wm * 32 + (lane & 15);
    int b_row = wn * 64 + (lane & 7) + 8 * (lane >> 4);

    load_stage(0, 0);

    for (int it = 0; it < 32; it++) {
        int st = it & 1;
        if (it + 1 < 32) {
            load_stage(st ^ 1, (it + 1) * 32);
            CPA_WAIT1();
        } else {
            CPA_WAIT0();
        }
        __syncthreads();

        uint32_t stb = sbase + st * STG;
#pragma unroll
        for (int ks = 0; ks < 2; ks++) {
            int k0 = ks * 16;
            uint32_t aH[2][4], aL[2][4], bH[8][2], bL[8][2];
            int a_col = (k0 + 8 * (lane >> 4)) * 2;
            int b_col = (k0 + 8 * ((lane >> 3) & 1)) * 2;
#pragma unroll
            for (int tm = 0; tm < 2; tm++) {
                uint32_t off = (uint32_t)((a_row + 16 * tm) * ROWB + a_col);
                ldsm_x4(aH[tm], stb + 0 * MATB + off);
                ldsm_x4(aL[tm], stb + 1 * MATB + off);
            }
#pragma unroll
            for (int tp = 0; tp < 4; tp++) {
                uint32_t off = (uint32_t)((b_row + 16 * tp) * ROWB + b_col);
                ldsm_x4(&bH[2 * tp][0], stb + 2 * MATB + off);
                ldsm_x4(&bL[2 * tp][0], stb + 3 * MATB + off);
            }
#pragma unroll
            for (int tm = 0; tm < 2; tm++)
#pragma unroll
                for (int tn = 0; tn < 8; tn++) {
                    mma_bf16(acc[tm][tn], aH[tm], bH[tn]);
                    mma_bf16(acc[tm][tn], aH[tm], bL[tn]);
                    mma_bf16(acc[tm][tn], aL[tm], bH[tn]);
                }
        }
        __syncthreads();
    }
}

// ---------------------------------------------------------------------------
// QKV GEMM. z=0: Q -> (acc+PE)*SC2 split bf16; z=1: K fp32; z=2: V split bf16
// ---------------------------------------------------------------------------
__global__ __launch_bounds__(256, 2) void qkv_mma() {
    extern __shared__ char dyn[];
    float acc[2][8][4];

    int z  = blockIdx.z;
    int m0 = blockIdx.y * 128;
    int n0 = blockIdx.x * 128;

    mma_gemm(g_Xhi + (size_t)m0 * 1024, g_Xlo + (size_t)m0 * 1024,
             g_Wh + (size_t)z * DD * DD + (size_t)n0 * 1024,
             g_Wl + (size_t)z * DD * DD + (size_t)n0 * 1024,
             dyn, acc);

    int t = threadIdx.x, lane = t & 31, wid = t >> 5;
    int wm = wid >> 1, wn = wid & 1;

#pragma unroll
    for (int tm = 0; tm < 2; tm++)
#pragma unroll
        for (int tn = 0; tn < 8; tn++) {
            int c  = n0 + wn * 64 + tn * 8 + (lane & 3) * 2;
            int h  = c >> 6, dk = c & 63;
#pragma unroll
            for (int half = 0; half < 2; half++) {
                int m = m0 + wm * 32 + tm * 16 + (lane >> 2) + 8 * half;
                int b = m >> 11, s = m & 2047;
                float vx = acc[tm][tn][2 * half + 0];
                float vy = acc[tm][tn][2 * half + 1];
                size_t off = ((size_t)((b * 16 + h) * 2048 + s)) * 64 + dk;
                if (z == 1) {
                    float2 v; v.x = vx; v.y = vy;
                    *(float2*)&g_Kraw[off] = v;
                } else {
                    if (z == 0) {
                        float2 pe = *(const float2*)&g_PE[s * 64 + dk];
                        vx = (vx + pe.x) * SC2;
                        vy = (vy + pe.y) * SC2;
                    }
                    __nv_bfloat16 hx = __float2bfloat16(vx);
                    __nv_bfloat16 hy = __float2bfloat16(vy);
                    __nv_bfloat16 lx = __float2bfloat16(vx - __bfloat162float(hx));
                    __nv_bfloat16 ly = __float2bfloat16(vy - __bfloat162float(hy));
                    __nv_bfloat162* oh = (__nv_bfloat162*)((z == 0) ? g_Qhi : g_Vhi);
                    __nv_bfloat162* ol = (__nv_bfloat162*)((z == 0) ? g_Qlo : g_Vlo);
                    oh[off >> 1] = __nv_bfloat162(hx, hy);
                    ol[off >> 1] = __nv_bfloat162(lx, ly);
                }
            }
        }
}

// ---------------------------------------------------------------------------
// EMA smear on K + PE add, output split to bf16 hi/lo
// ---------------------------------------------------------------------------
__global__ void smear_kernel(const float* __restrict__ alpha) {
    int idx = blockIdx.x * blockDim.x + threadIdx.x;
    int dk = idx & 63;
    int s  = (idx >> 6) & 2047;
    int h  = (idx >> 17) & 15;
    float kc = g_Kraw[idx];
    float v;
    if (s == 0) {
        v = kc;
    } else {
        float a = 1.0f / (1.0f + expf(-alpha[h * 2047 + (s - 1)]));
        v = a * kc + (1.0f - a) * g_Kraw[idx - 64];
    }
    v += g_PE[s * 64 + dk];
    __nv_bfloat16 hv = __float2bfloat16(v);
    g_Khi[idx] = hv;
    g_Klo[idx] = __float2bfloat16(v - __bfloat162float(hv));
}

// ---------------------------------------------------------------------------
// Causal flash attention, bf16x3 HMMA, single-stage (proven R4 structure).
// BM=64, BN=64, 128 threads (4 warps, 16 q-rows each). smem 36864B static.
// ---------------------------------------------------------------------------
#define ASTR 144
#define AMAT (64 * ASTR)   // 9216

__global__ __launch_bounds__(128, 4) void attn_mma() {
    __shared__ __align__(16) char sm[4 * AMAT];
    uint32_t sb = smem_u32(sm);

    int t = threadIdx.x, lane = t & 31, w = t >> 5;
    int qt = 31 - (int)blockIdx.x;          // heavy tiles first
    int qb = qt * 64;
    int bh = blockIdx.y;
    size_t base = (size_t)bh * SS * DKK;

    // ---- stage Q tile (hi -> mat0, lo -> mat1), extract A-frags ----
    {
        const char* qsrc[2] = {(const char*)(g_Qhi + base), (const char*)(g_Qlo + base)};
#pragma unroll
        for (int q = 0; q < 8; q++) {
            int idx = t * 8 + q;
            int mat = idx >> 9;
            int r   = (idx >> 3) & 63;
            int c   = idx & 7;
            CPA16(sb + mat * AMAT + r * ASTR + c * 16,
                  qsrc[mat] + ((size_t)(qb + r) * 64 + c * 8) * 2);
        }
        CPA_COMMIT(); CPA_WAIT0();
        __syncthreads();
    }

    uint32_t qh[4][4], ql[4][4];
    {
        int ar = w * 16 + (lane & 15);
#pragma unroll
        for (int k = 0; k < 4; k++) {
            uint32_t acol = (uint32_t)(k * 32 + (lane >> 4) * 16);
            ldsm_x4(qh[k], sb + 0 * AMAT + ar * ASTR + acol);
            ldsm_x4(ql[k], sb + 1 * AMAT + ar * ASTR + acol);
        }
    }

    float o[8][4];
    float m2[2], lsum[2];
#pragma unroll
    for (int j = 0; j < 8; j++)
#pragma unroll
        for (int u = 0; u < 4; u++) o[j][u] = 0.0f;
    m2[0] = m2[1] = -1e30f;
    lsum[0] = lsum[1] = 0.0f;

    const char* kvsrc[4] = {(const char*)(g_Khi + base), (const char*)(g_Klo + base),
                            (const char*)(g_Vhi + base), (const char*)(g_Vlo + base)};

    int r0 = (lane >> 2);
    int ntiles = qt + 1;

    for (int tile = 0; tile < ntiles; tile++) {
        int kb = tile * 64;
        __syncthreads();
#pragma unroll
        for (int q = 0; q < 16; q++) {
            int idx = t * 16 + q;
            int mat = idx >> 9;
            int r   = (idx >> 3) & 63;
            int c   = idx & 7;
            CPA16(sb + mat * AMAT + r * ASTR + c * 16,
                  kvsrc[mat] + ((size_t)(kb + r) * 64 + c * 8) * 2);
        }
        CPA_COMMIT(); CPA_WAIT0();
        __syncthreads();

        // ---- S = Q K^T (bf16x3) ----
        float s[8][4];
#pragma unroll
        for (int j = 0; j < 8; j++)
#pragma unroll
            for (int u = 0; u < 4; u++) s[j][u] = 0.0f;

        {
            int b_row = (lane & 7) + 8 * (lane >> 4);
#pragma unroll
            for (int k = 0; k < 4; k++) {
                uint32_t bcol = (uint32_t)((k * 16 + 8 * ((lane >> 3) & 1)) * 2);
                uint32_t kH[8][2], kL[8][2];
#pragma unroll
                for (int tp = 0; tp < 4; tp++) {
                    uint32_t off = (uint32_t)((b_row + 16 * tp) * ASTR) + bcol;
                    ldsm_x4(&kH[2 * tp][0], sb + 0 * AMAT + off);
                    ldsm_x4(&kL[2 * tp][0], sb + 1 * AMAT + off);
                }
#pragma unroll
                for (int j = 0; j < 8; j++) {
                    mma_bf16(s[j], qh[k], kH[j]);
                    mma_bf16(s[j], qh[k], kL[j]);
                    mma_bf16(s[j], ql[k], kH[j]);
                }
            }
        }

        // ---- mask (diagonal tile) ----
        if (tile == ntiles - 1) {
#pragma unroll
            for (int j = 0; j < 8; j++)
#pragma unroll
                for (int u = 0; u < 4; u++) {
                    int row = (w * 16) + r0 + 8 * (u >> 1);
                    int col = j * 8 + 2 * (lane & 3) + (u & 1);
                    if (col > row) s[j][u] = -1e30f;
                }
        }

        // ---- online softmax (base 2), per row half ----
#pragma unroll
        for (int h = 0; h < 2; h++) {
            float mx = -1e30f;
#pragma unroll
            for (int j = 0; j < 8; j++) {
                mx = fmaxf(mx, s[j][2 * h + 0]);
                mx = fmaxf(mx, s[j][2 * h + 1]);
            }
            mx = fmaxf(mx, __shfl_xor_sync(0xffffffffu, mx, 1));
            mx = fmaxf(mx, __shfl_xor_sync(0xffffffffu, mx, 2));
            float mnew = fmaxf(m2[h], mx);
            float corr = ex2(m2[h] - mnew);
            m2[h] = mnew;
            float rs = 0.0f;
#pragma unroll
            for (int j = 0; j < 8; j++) {
                float p0 = ex2(s[j][2 * h + 0] - mnew);
                float p1 = ex2(s[j][2 * h + 1] - mnew);
                s[j][2 * h + 0] = p0;
                s[j][2 * h + 1] = p1;
                rs += p0 + p1;
            }
            lsum[h] = lsum[h] * corr + rs;
#pragma unroll
            for (int j = 0; j < 8; j++) {
                o[j][2 * h + 0] *= corr;
                o[j][2 * h + 1] *= corr;
            }
        }

        // ---- P fragments (C->A remap, hi/lo split in registers) ----
        uint32_t pH[4][4], pL[4][4];
#pragma unroll
        for (int kk = 0; kk < 4; kk++) {
            int j = 2 * kk;
#pragma unroll
            for (int q = 0; q < 4; q++) {
                int jj = j + (q >> 1);
                float a = s[jj][(q & 1) * 2 + 0];
                float b = s[jj][(q & 1) * 2 + 1];
                uint32_t hi2 = pk_bf2(a, b);
                pH[kk][q] = hi2;
                pL[kk][q] = pk_bf2(a - bf_lo(hi2), b - bf_hi(hi2));
            }
        }

        // ---- O += P V (bf16x3), V via ldmatrix.trans ----
        {
            int vrow = (lane & 7) + 8 * ((lane >> 3) & 1);
            uint32_t vcol = (uint32_t)(16 * (lane >> 4));
#pragma unroll
            for (int kk = 0; kk < 4; kk++) {
                uint32_t vH[8][2], vL[8][2];
#pragma unroll
                for (int jj = 0; jj < 4; jj++) {
                    uint32_t off = (uint32_t)((kk * 16 + vrow) * ASTR) + (uint32_t)(jj * 32) + vcol;
                    ldsm_x4_t(&vH[2 * jj][0], sb + 2 * AMAT + off);
                    ldsm_x4_t(&vL[2 * jj][0], sb + 3 * AMAT + off);
                }
#pragma unroll
                for (int j = 0; j < 8; j++) {
                    mma_bf16(o[j], pH[kk], vH[j]);
                    mma_bf16(o[j], pL[kk], vH[j]);
                    mma_bf16(o[j], pH[kk], vL[j]);
                }
            }
        }
    }

    // ---- epilogue: normalize, split to bf16 hi/lo, store ----
#pragma unroll
    for (int h = 0; h < 2; h++) {
        lsum[h] += __shfl_xor_sync(0xffffffffu, lsum[h], 1);
        lsum[h] += __shfl_xor_sync(0xffffffffu, lsum[h], 2);
        lsum[h] = 1.0f / lsum[h];
    }

    int b = bh >> 4, hh = bh & 15;
#pragma unroll
    for (int j = 0; j < 8; j++) {
        int dk = j * 8 + 2 * (lane & 3);
#pragma unroll
        for (int h = 0; h < 2; h++) {
            int srow = qb + w * 16 + r0 + 8 * h;
            float f0 = o[j][2 * h + 0] * lsum[h];
            float f1 = o[j][2 * h + 1] * lsum[h];
            __nv_bfloat16 h0 = __float2bfloat16(f0);
            __nv_bfloat16 h1 = __float2bfloat16(f1);
            __nv_bfloat16 l0 = __float2bfloat16(f0 - __bfloat162float(h0));
            __nv_bfloat16 l1 = __float2bfloat16(f1 - __bfloat162float(h1));
            size_t off = ((size_t)(b * SS + srow) * DD + hh * 64 + dk) >> 1;
            ((__nv_bfloat162*)g_Ahi)[off] = __nv_bfloat162(h0, h1);
            ((__nv_bfloat162*)g_Alo)[off] = __nv_bfloat162(l0, l1);
        }
    }
}

// ---------------------------------------------------------------------------
// Output projection GEMM: Y = attn @ Wo^T + X
// ---------------------------------------------------------------------------
__global__ __launch_bounds__(256, 2) void oproj_mma(const float* __restrict__ X) {
    extern __shared__ char dyn[];
    float acc[2][8][4];

    int m0 = blockIdx.y * 128;
    int n0 = blockIdx.x * 128;

    mma_gemm(g_Ahi + (size_t)m0 * 1024, g_Alo + (size_t)m0 * 1024,
             g_Woh + (size_t)n0 * 1024, g_Wol + (size_t)n0 * 1024,
             dyn, acc);

    int t = threadIdx.x, lane = t & 31, wid = t >> 5;
    int wm = wid >> 1, wn = wid & 1;
#pragma unroll
    for (int tm = 0; tm < 2; tm++)
#pragma unroll
        for (int tn = 0; tn < 8; tn++) {
            int c = n0 + wn * 64 + tn * 8 + (lane & 3) * 2;
#pragma unroll
            for (int half = 0; half < 2; half++) {
                int m = m0 + wm * 32 + tm * 16 + (lane >> 2) + 8 * half;
                float2 xr = *(const float2*)&X[(size_t)m * 1024 + c];
                float2 v;
                v.x = acc[tm][tn][2 * half + 0] + xr.x;
                v.y = acc[tm][tn][2 * half + 1] + xr.y;
                *(float2*)&g_Y[(size_t)m * 1024 + c] = v;
            }
        }
}

// ---------------------------------------------------------------------------
// LayerNorm over D=1024 per row
// ---------------------------------------------------------------------------
__global__ void ln_kernel(const float* __restrict__ gamma,
                          const float* __restrict__ beta,
                          float* __restrict__ out)
{
    int row = blockIdx.x;
    int t   = threadIdx.x;
    const float* y = g_Y + (size_t)row * 1024;

    float x[4];
    float s = 0.0f;
#pragma unroll
    for (int u = 0; u < 4; u++) { x[u] = y[t + 256 * u]; s += x[u]; }

    __shared__ float red[32];
#pragma unroll
    for (int off = 16; off; off >>= 1) s += __shfl_xor_sync(0xffffffffu, s, off);
    if ((t & 31) == 0) red[t >> 5] = s;
    __syncthreads();
    if (t == 0) {
        float tot = 0.0f;
        for (int w = 0; w < 8; w++) tot += red[w];
        red[8] = tot;
    }
    __syncthreads();
    float mean = red[8] * (1.0f / 1024.0f);

    float vs = 0.0f;
#pragma unroll
    for (int u = 0; u < 4; u++) { float d = x[u] - mean; vs += d * d; }
#pragma unroll
    for (int off = 16; off; off >>= 1) vs += __shfl_xor_sync(0xffffffffu, vs, off);
    if ((t & 31) == 0) red[16 + (t >> 5)] = vs;
    __syncthreads();
    if (t == 0) {
        float tot = 0.0f;
        for (int w = 0; w < 8; w++) tot += red[16 + w];
        red[24] = tot;
    }
    __syncthreads();
    float var  = red[24] * (1.0f / 1024.0f);
    float rstd = rsqrtf(var + 1e-5f);

#pragma unroll
    for (int u = 0; u < 4; u++) {
        int c = t + 256 * u;
        out[(size_t)row * 1024 + c] = (x[u] - mean) * rstd * gamma[c] + beta[c];
    }
}

// ---------------------------------------------------------------------------
extern "C" void kernel_launch(void* const* d_in, const int* in_sizes, int n_in,
                              void* d_out, int out_size)
{
    const float* X     = (const float*)d_in[0];
    const float* Wq    = (const float*)d_in[1];
    const float* Wk    = (const float*)d_in[2];
    const float* Wv    = (const float*)d_in[3];
    const float* Wo    = (const float*)d_in[4];
    const float* alpha = (const float*)d_in[5];
    const float* lns   = (const float*)d_in[6];
    const float* lnb   = (const float*)d_in[7];
    float* out = (float*)d_out;

    static int attr_set = 0;
    if (!attr_set) {
        cudaFuncSetAttribute(qkv_mma,   cudaFuncAttributeMaxDynamicSharedMemorySize, DYN_SMEM);
        cudaFuncSetAttribute(oproj_mma, cudaFuncAttributeMaxDynamicSharedMemorySize, DYN_SMEM);
        attr_set = 1;
    }

    // launch order chosen so ncu (-s 5 -c 1) captures attn_mma (launch #6)
    pe_kernel<<<(SS * DKK + 255) / 256, 256>>>();                 // 1
    convx_kernel<<<4096, 256>>>(X);                                // 2
    convw_kernel<<<4096, 256>>>(Wq, Wk, Wv, Wo);                   // 3
    qkv_mma<<<dim3(8, 32, 3), 256, DYN_SMEM>>>();                  // 4
    smear_kernel<<<(MM * DD) / 256, 256>>>(alpha);                 // 5
    attn_mma<<<dim3(32, 32), 128>>>();                             // 6  <- profiled
    oproj_mma<<<dim3(8, 32), 256, DYN_SMEM>>>(X);                  // 7
    ln_kernel<<<MM, 256>>>(lns, lnb, out);                         // 8
}

// round 7
// speedup vs baseline: 1.0772x; 1.0138x over previous
#include <cuda_runtime.h>
#include <cuda_bf16.h>
#include <math.h>
#include <stdint.h>

#define BB  2
#define SS  2048
#define DD  1024
#define HH  16
#define DKK 64
#define MM  (BB*SS)   // 4096 rows

// scale folded into Q: 1/sqrt(64) * log2(e)
#define SC2 0.18033688011112042f

// ---------------------------------------------------------------------------
// Scratch (allocation-free rule: __device__ globals)
// ---------------------------------------------------------------------------
__device__ __align__(16) float g_PE[SS*DKK];
__device__ __align__(16) float g_Kraw[MM*DD];
__device__ __align__(16) float g_Y[MM*DD];

__device__ __align__(16) __nv_bfloat16 g_Xhi[MM*DD];
__device__ __align__(16) __nv_bfloat16 g_Xlo[MM*DD];
__device__ __align__(16) __nv_bfloat16 g_Wh[3*DD*DD];
__device__ __align__(16) __nv_bfloat16 g_Wl[3*DD*DD];
__device__ __align__(16) __nv_bfloat16 g_Woh[DD*DD];
__device__ __align__(16) __nv_bfloat16 g_Wol[DD*DD];
__device__ __align__(16) __nv_bfloat16 g_Ahi[MM*DD];
__device__ __align__(16) __nv_bfloat16 g_Alo[MM*DD];

// attention operands, head-split [B*H][S][64], bf16 hi/lo
__device__ __align__(16) __nv_bfloat16 g_Qhi[MM*DD];
__device__ __align__(16) __nv_bfloat16 g_Qlo[MM*DD];
__device__ __align__(16) __nv_bfloat16 g_Khi[MM*DD];
__device__ __align__(16) __nv_bfloat16 g_Klo[MM*DD];
__device__ __align__(16) __nv_bfloat16 g_Vhi[MM*DD];
__device__ __align__(16) __nv_bfloat16 g_Vlo[MM*DD];

// ---------------------------------------------------------------------------
// PTX helpers (baseline sm_103-safe)
// ---------------------------------------------------------------------------
__device__ __forceinline__ uint32_t smem_u32(const void* p) {
    uint32_t a;
    asm("{ .reg .u64 t; cvta.to.shared.u64 t, %1; cvt.u32.u64 %0, t; }"
        : "=r"(a) : "l"(p));
    return a;
}

#define CPA16(dst, src) \
    asm volatile("cp.async.cg.shared.global [%0], [%1], 16;" :: "r"(dst), "l"(src) : "memory")
#define CPA_COMMIT() asm volatile("cp.async.commit_group;" ::: "memory")
#define CPA_WAIT1()  asm volatile("cp.async.wait_group 1;" ::: "memory")
#define CPA_WAIT0()  asm volatile("cp.async.wait_group 0;" ::: "memory")

__device__ __forceinline__ void ldsm_x4(uint32_t* r, uint32_t addr) {
    asm volatile("ldmatrix.sync.aligned.m8n8.x4.shared.b16 {%0,%1,%2,%3}, [%4];"
                 : "=r"(r[0]), "=r"(r[1]), "=r"(r[2]), "=r"(r[3]) : "r"(addr));
}
__device__ __forceinline__ void ldsm_x4_t(uint32_t* r, uint32_t addr) {
    asm volatile("ldmatrix.sync.aligned.m8n8.x4.trans.shared.b16 {%0,%1,%2,%3}, [%4];"
                 : "=r"(r[0]), "=r"(r[1]), "=r"(r[2]), "=r"(r[3]) : "r"(addr));
}

__device__ __forceinline__ void mma_bf16(float* c, const uint32_t* a, const uint32_t* b) {
    asm volatile(
        "mma.sync.aligned.m16n8k16.row.col.f32.bf16.bf16.f32 "
        "{%0,%1,%2,%3}, {%4,%5,%6,%7}, {%8,%9}, {%0,%1,%2,%3};"
        : "+f"(c[0]), "+f"(c[1]), "+f"(c[2]), "+f"(c[3])
        : "r"(a[0]), "r"(a[1]), "r"(a[2]), "r"(a[3]), "r"(b[0]), "r"(b[1]));
}

__device__ __forceinline__ float ex2(float x) {
    float r;
    asm("ex2.approx.ftz.f32 %0, %1;" : "=f"(r) : "f"(x));
    return r;
}
__device__ __forceinline__ uint32_t pk_bf2(float a, float b) {
    uint32_t r;
    asm("cvt.rn.bf16x2.f32 %0, %1, %2;" : "=r"(r) : "f"(b), "f"(a));
    return r;
}
__device__ __forceinline__ float bf_lo(uint32_t r) { return __uint_as_float(r << 16); }
__device__ __forceinline__ float bf_hi(uint32_t r) { return __uint_as_float(r & 0xFFFF0000u); }

// ---------------------------------------------------------------------------
__global__ void pe_kernel() {
    int idx = blockIdx.x * blockDim.x + threadIdx.x;
    if (idx >= SS * DKK) return;
    int s  = idx >> 6;
    int dk = idx & 63;
    int i  = dk >> 1;
    float freq = expf(-((float)(2 * i) / 64.0f) * 9.210340371976184f);
    float ang  = (float)s * freq;
    g_PE[idx]  = (dk & 1) ? cosf(ang) : sinf(ang);
}

// ---------------------------------------------------------------------------
// fp32 -> bf16 hi/lo split
// ---------------------------------------------------------------------------
__device__ __forceinline__ void split4(float4 v, __nv_bfloat162* hp, __nv_bfloat162* lp, int i) {
    __nv_bfloat16 h0 = __float2bfloat16(v.x);
    __nv_bfloat16 h1 = __float2bfloat16(v.y);
    __nv_bfloat16 h2 = __float2bfloat16(v.z);
    __nv_bfloat16 h3 = __float2bfloat16(v.w);
    __nv_bfloat16 l0 = __float2bfloat16(v.x - __bfloat162float(h0));
    __nv_bfloat16 l1 = __float2bfloat16(v.y - __bfloat162float(h1));
    __nv_bfloat16 l2 = __float2bfloat16(v.z - __bfloat162float(h2));
    __nv_bfloat16 l3 = __float2bfloat16(v.w - __bfloat162float(h3));
    hp[2*i]   = __nv_bfloat162(h0, h1);
    hp[2*i+1] = __nv_bfloat162(h2, h3);
    lp[2*i]   = __nv_bfloat162(l0, l1);
    lp[2*i+1] = __nv_bfloat162(l2, l3);
}

__global__ void convx_kernel(const float* __restrict__ src) {
    int i = blockIdx.x * blockDim.x + threadIdx.x;
    split4(((const float4*)src)[i], (__nv_bfloat162*)g_Xhi, (__nv_bfloat162*)g_Xlo, i);
}

__global__ void convw_kernel(const float* __restrict__ Wq, const float* __restrict__ Wk,
                             const float* __restrict__ Wv, const float* __restrict__ Wo) {
    int gi  = blockIdx.x * blockDim.x + threadIdx.x;
    int mat = gi >> 18;
    int i   = gi & 0x3FFFF;
    const float* src = (mat == 0) ? Wq : (mat == 1) ? Wk : (mat == 2) ? Wv : Wo;
    __nv_bfloat162* hp;
    __nv_bfloat162* lp;
    if (mat < 3) {
        hp = (__nv_bfloat162*)(g_Wh + (size_t)mat * DD * DD);
        lp = (__nv_bfloat162*)(g_Wl + (size_t)mat * DD * DD);
    } else {
        hp = (__nv_bfloat162*)g_Woh;
        lp = (__nv_bfloat162*)g_Wol;
    }
    split4(((const float4*)src)[i], hp, lp, i);
}

// ---------------------------------------------------------------------------
// bf16x3 HMMA GEMM mainloop: 3-stage cp.async pipeline, swizzled 64B rows,
// ONE __syncthreads per K-iteration.
// Stage: 4 mats x 128 rows x 64B = 32KB. Swizzle: chunk c -> c ^ ((row>>1)&3).
// ---------------------------------------------------------------------------
#define MATB 8192            // 128 * 64
#define STG  (4 * MATB)      // 32768
#define DYN_SMEM (3 * STG)   // 98304

__device__ __forceinline__ void mma_gemm(
    const __nv_bfloat16* __restrict__ Ah, const __nv_bfloat16* __restrict__ Al,
    const __nv_bfloat16* __restrict__ Bh, const __nv_bfloat16* __restrict__ Bl,
    char* dyn, float acc[2][8][4])
{
    int t    = threadIdx.x;
    int lane = t & 31;
    int wid  = t >> 5;
    int wm   = wid >> 1;
    int wn   = wid & 1;
    uint32_t sbase = smem_u32(dyn);

    const char* mats[4] = {(const char*)Ah, (const char*)Al,
                           (const char*)Bh, (const char*)Bl};

#pragma unroll
    for (int tm = 0; tm < 2; tm++)
#pragma unroll
        for (int tn = 0; tn < 8; tn++)
#pragma unroll
            for (int u = 0; u < 4; u++) acc[tm][tn][u] = 0.0f;

    // copy: 2048 16B-chunks per stage, 8 per thread
    int idx0 = t * 8;
    auto load_stage = [&](int st, int kb) {
        uint32_t stb = sbase + st * STG;
#pragma unroll
        for (int q = 0; q < 8; q++) {
            int idx = idx0 + q;
            int mat = idx >> 9;               // 512 chunks per mat
            int r   = (idx >> 2) & 127;
            int c   = idx & 3;
            uint32_t dst = stb + mat * MATB + r * 64 + ((c ^ ((r >> 1) & 3)) << 4);
            const char* src = mats[mat] + ((size_t)r * 1024 + kb + c * 8) * 2;
            CPA16(dst, src);
        }
        CPA_COMMIT();
    };

    // ldsm addressing (precompute row offsets + swizzle masks)
    int a_hi = lane >> 4;             // chunk add for A
    int b_hi = (lane >> 3) & 1;       // chunk add for B
    uint32_t aOff[2]; int aMsk[2];
#pragma unroll
    for (int tm = 0; tm < 2; tm++) {
        int r = wm * 32 + (lane & 15) + 16 * tm;
        aOff[tm] = (uint32_t)(r * 64);
        aMsk[tm] = (r >> 1) & 3;
    }
    uint32_t bOff[4]; int bMsk[4];
#pragma unroll
    for (int tp = 0; tp < 4; tp++) {
        int r = wn * 64 + (lane & 7) + 8 * (lane >> 4) + 16 * tp;
        bOff[tp] = (uint32_t)(r * 64);
        bMsk[tp] = (r >> 1) & 3;
    }

    load_stage(0, 0);
    load_stage(1, 32);

    int st = 0;
    for (int it = 0; it < 32; it++) {
        if (it < 31) { CPA_WAIT1(); } else { CPA_WAIT0(); }
        __syncthreads();
        if (it + 2 < 32) {
            int s2 = st + 2; if (s2 >= 3) s2 -= 3;
            load_stage(s2, (it + 2) * 32);
        }

        uint32_t stb = sbase + st * STG;
#pragma unroll
        for (int ks = 0; ks < 2; ks++) {
            int cA = 2 * ks + a_hi;
            int cB = 2 * ks + b_hi;
            uint32_t aH[2][4], aL[2][4], bH[8][2], bL[8][2];
#pragma unroll
            for (int tm = 0; tm < 2; tm++) {
                uint32_t off = aOff[tm] + (uint32_t)((cA ^ aMsk[tm]) << 4);
                ldsm_x4(aH[tm], stb + 0 * MATB + off);
                ldsm_x4(aL[tm], stb + 1 * MATB + off);
            }
#pragma unroll
            for (int tp = 0; tp < 4; tp++) {
                uint32_t off = bOff[tp] + (uint32_t)((cB ^ bMsk[tp]) << 4);
                ldsm_x4(&bH[2 * tp][0], stb + 2 * MATB + off);
                ldsm_x4(&bL[2 * tp][0], stb + 3 * MATB + off);
            }
#pragma unroll
            for (int tm = 0; tm < 2; tm++)
#pragma unroll
                for (int tn = 0; tn < 8; tn++) {
                    mma_bf16(acc[tm][tn], aH[tm], bH[tn]);
                    mma_bf16(acc[tm][tn], aH[tm], bL[tn]);
                    mma_bf16(acc[tm][tn], aL[tm], bH[tn]);
                }
        }
        st++; if (st == 3) st = 0;
    }
    __syncthreads();
}

// ---------------------------------------------------------------------------
// QKV GEMM. z=0: Q -> (acc+PE)*SC2 split bf16; z=1: K fp32; z=2: V split bf16
// ---------------------------------------------------------------------------
__global__ __launch_bounds__(256, 2) void qkv_mma() {
    extern __shared__ char dyn[];
    float acc[2][8][4];

    int z  = blockIdx.z;
    int m0 = blockIdx.y * 128;
    int n0 = blockIdx.x * 128;

    mma_gemm(g_Xhi + (size_t)m0 * 1024, g_Xlo + (size_t)m0 * 1024,
             g_Wh + (size_t)z * DD * DD + (size_t)n0 * 1024,
             g_Wl + (size_t)z * DD * DD + (size_t)n0 * 1024,
             dyn, acc);

    int t = threadIdx.x, lane = t & 31, wid = t >> 5;
    int wm = wid >> 1, wn = wid & 1;

#pragma unroll
    for (int tm = 0; tm < 2; tm++)
#pragma unroll
        for (int tn = 0; tn < 8; tn++) {
            int c  = n0 + wn * 64 + tn * 8 + (lane & 3) * 2;
            int h  = c >> 6, dk = c & 63;
#pragma unroll
            for (int half = 0; half < 2; half++) {
                int m = m0 + wm * 32 + tm * 16 + (lane >> 2) + 8 * half;
                int b = m >> 11, s = m & 2047;
                float vx = acc[tm][tn][2 * half + 0];
                float vy = acc[tm][tn][2 * half + 1];
                size_t off = ((size_t)((b * 16 + h) * 2048 + s)) * 64 + dk;
                if (z == 1) {
                    float2 v; v.x = vx; v.y = vy;
                    *(float2*)&g_Kraw[off] = v;
                } else {
                    if (z == 0) {
                        float2 pe = *(const float2*)&g_PE[s * 64 + dk];
                        vx = (vx + pe.x) * SC2;
                        vy = (vy + pe.y) * SC2;
                    }
                    __nv_bfloat16 hx = __float2bfloat16(vx);
                    __nv_bfloat16 hy = __float2bfloat16(vy);
                    __nv_bfloat16 lx = __float2bfloat16(vx - __bfloat162float(hx));
                    __nv_bfloat16 ly = __float2bfloat16(vy - __bfloat162float(hy));
                    __nv_bfloat162* oh = (__nv_bfloat162*)((z == 0) ? g_Qhi : g_Vhi);
                    __nv_bfloat162* ol = (__nv_bfloat162*)((z == 0) ? g_Qlo : g_Vlo);
                    oh[off >> 1] = __nv_bfloat162(hx, hy);
                    ol[off >> 1] = __nv_bfloat162(lx, ly);
                }
            }
        }
}

// ---------------------------------------------------------------------------
// EMA smear on K + PE add, output split to bf16 hi/lo
// ---------------------------------------------------------------------------
__global__ void smear_kernel(const float* __restrict__ alpha) {
    int idx = blockIdx.x * blockDim.x + threadIdx.x;
    int dk = idx & 63;
    int s  = (idx >> 6) & 2047;
    int h  = (idx >> 17) & 15;
    float kc = g_Kraw[idx];
    float v;
    if (s == 0) {
        v = kc;
    } else {
        float a = 1.0f / (1.0f + expf(-alpha[h * 2047 + (s - 1)]));
        v = a * kc + (1.0f - a) * g_Kraw[idx - 64];
    }
    v += g_PE[s * 64 + dk];
    __nv_bfloat16 hv = __float2bfloat16(v);
    g_Khi[idx] = hv;
    g_Klo[idx] = __float2bfloat16(v - __bfloat162float(hv));
}

// ---------------------------------------------------------------------------
// Causal flash attention, bf16x3 HMMA, single-stage (proven R6 structure).
// ---------------------------------------------------------------------------
#define ASTR 144
#define AMAT (64 * ASTR)   // 9216

__global__ __launch_bounds__(128, 4) void attn_mma() {
    __shared__ __align__(16) char sm[4 * AMAT];
    uint32_t sb = smem_u32(sm);

    int t = threadIdx.x, lane = t & 31, w = t >> 5;
    int qt = 31 - (int)blockIdx.x;          // heavy tiles first
    int qb = qt * 64;
    int bh = blockIdx.y;
    size_t base = (size_t)bh * SS * DKK;

    {
        const char* qsrc[2] = {(const char*)(g_Qhi + base), (const char*)(g_Qlo + base)};
#pragma unroll
        for (int q = 0; q < 8; q++) {
            int idx = t * 8 + q;
            int mat = idx >> 9;
            int r   = (idx >> 3) & 63;
            int c   = idx & 7;
            CPA16(sb + mat * AMAT + r * ASTR + c * 16,
                  qsrc[mat] + ((size_t)(qb + r) * 64 + c * 8) * 2);
        }
        CPA_COMMIT(); CPA_WAIT0();
        __syncthreads();
    }

    uint32_t qh[4][4], ql[4][4];
    {
        int ar = w * 16 + (lane & 15);
#pragma unroll
        for (int k = 0; k < 4; k++) {
            uint32_t acol = (uint32_t)(k * 32 + (lane >> 4) * 16);
            ldsm_x4(qh[k], sb + 0 * AMAT + ar * ASTR + acol);
            ldsm_x4(ql[k], sb + 1 * AMAT + ar * ASTR + acol);
        }
    }

    float o[8][4];
    float m2[2], lsum[2];
#pragma unroll
    for (int j = 0; j < 8; j++)
#pragma unroll
        for (int u = 0; u < 4; u++) o[j][u] = 0.0f;
    m2[0] = m2[1] = -1e30f;
    lsum[0] = lsum[1] = 0.0f;

    const char* kvsrc[4] = {(const char*)(g_Khi + base), (const char*)(g_Klo + base),
                            (const char*)(g_Vhi + base), (const char*)(g_Vlo + base)};

    int r0 = (lane >> 2);
    int ntiles = qt + 1;

    for (int tile = 0; tile < ntiles; tile++) {
        int kb = tile * 64;
        __syncthreads();
#pragma unroll
        for (int q = 0; q < 16; q++) {
            int idx = t * 16 + q;
            int mat = idx >> 9;
            int r   = (idx >> 3) & 63;
            int c   = idx & 7;
            CPA16(sb + mat * AMAT + r * ASTR + c * 16,
                  kvsrc[mat] + ((size_t)(kb + r) * 64 + c * 8) * 2);
        }
        CPA_COMMIT(); CPA_WAIT0();
        __syncthreads();

        float s[8][4];
#pragma unroll
        for (int j = 0; j < 8; j++)
#pragma unroll
            for (int u = 0; u < 4; u++) s[j][u] = 0.0f;

        {
            int b_row = (lane & 7) + 8 * (lane >> 4);
#pragma unroll
            for (int k = 0; k < 4; k++) {
                uint32_t bcol = (uint32_t)((k * 16 + 8 * ((lane >> 3) & 1)) * 2);
                uint32_t kH[8][2], kL[8][2];
#pragma unroll
                for (int tp = 0; tp < 4; tp++) {
                    uint32_t off = (uint32_t)((b_row + 16 * tp) * ASTR) + bcol;
                    ldsm_x4(&kH[2 * tp][0], sb + 0 * AMAT + off);
                    ldsm_x4(&kL[2 * tp][0], sb + 1 * AMAT + off);
                }
#pragma unroll
                for (int j = 0; j < 8; j++) {
                    mma_bf16(s[j], qh[k], kH[j]);
                    mma_bf16(s[j], qh[k], kL[j]);
                    mma_bf16(s[j], ql[k], kH[j]);
                }
            }
        }

        if (tile == ntiles - 1) {
#pragma unroll
            for (int j = 0; j < 8; j++)
#pragma unroll
                for (int u = 0; u < 4; u++) {
                    int row = (w * 16) + r0 + 8 * (u >> 1);
                    int col = j * 8 + 2 * (lane & 3) + (u & 1);
                    if (col > row) s[j][u] = -1e30f;
                }
        }

#pragma unroll
        for (int h = 0; h < 2; h++) {
            float mx = -1e30f;
#pragma unroll
            for (int j = 0; j < 8; j++) {
                mx = fmaxf(mx, s[j][2 * h + 0]);
                mx = fmaxf(mx, s[j][2 * h + 1]);
            }
            mx = fmaxf(mx, __shfl_xor_sync(0xffffffffu, mx, 1));
            mx = fmaxf(mx, __shfl_xor_sync(0xffffffffu, mx, 2));
            float mnew = fmaxf(m2[h], mx);
            float corr = ex2(m2[h] - mnew);
            m2[h] = mnew;
            float rs = 0.0f;
#pragma unroll
            for (int j = 0; j < 8; j++) {
                float p0 = ex2(s[j][2 * h + 0] - mnew);
                float p1 = ex2(s[j][2 * h + 1] - mnew);
                s[j][2 * h + 0] = p0;
                s[j][2 * h + 1] = p1;
                rs += p0 + p1;
            }
            lsum[h] = lsum[h] * corr + rs;
#pragma unroll
            for (int j = 0; j < 8; j++) {
                o[j][2 * h + 0] *= corr;
                o[j][2 * h + 1] *= corr;
            }
        }

        uint32_t pH[4][4], pL[4][4];
#pragma unroll
        for (int kk = 0; kk < 4; kk++) {
            int j = 2 * kk;
#pragma unroll
            for (int q = 0; q < 4; q++) {
                int jj = j + (q >> 1);
                float a = s[jj][(q & 1) * 2 + 0];
                float b = s[jj][(q & 1) * 2 + 1];
                uint32_t hi2 = pk_bf2(a, b);
                pH[kk][q] = hi2;
                pL[kk][q] = pk_bf2(a - bf_lo(hi2), b - bf_hi(hi2));
            }
        }

        {
            int vrow = (lane & 7) + 8 * ((lane >> 3) & 1);
            uint32_t vcol = (uint32_t)(16 * (lane >> 4));
#pragma unroll
            for (int kk = 0; kk < 4; kk++) {
                uint32_t vH[8][2], vL[8][2];
#pragma unroll
                for (int jj = 0; jj < 4; jj++) {
                    uint32_t off = (uint32_t)((kk * 16 + vrow) * ASTR) + (uint32_t)(jj * 32) + vcol;
                    ldsm_x4_t(&vH[2 * jj][0], sb + 2 * AMAT + off);
                    ldsm_x4_t(&vL[2 * jj][0], sb + 3 * AMAT + off);
                }
#pragma unroll
                for (int j = 0; j < 8; j++) {
                    mma_bf16(o[j], pH[kk], vH[j]);
                    mma_bf16(o[j], pL[kk], vH[j]);
                    mma_bf16(o[j], pH[kk], vL[j]);
                }
            }
        }
    }

#pragma unroll
    for (int h = 0; h < 2; h++) {
        lsum[h] += __shfl_xor_sync(0xffffffffu, lsum[h], 1);
        lsum[h] += __shfl_xor_sync(0xffffffffu, lsum[h], 2);
        lsum[h] = 1.0f / lsum[h];
    }

    int b = bh >> 4, hh = bh & 15;
#pragma unroll
    for (int j = 0; j < 8; j++) {
        int dk = j * 8 + 2 * (lane & 3);
#pragma unroll
        for (int h = 0; h < 2; h++) {
            int srow = qb + w * 16 + r0 + 8 * h;
            float f0 = o[j][2 * h + 0] * lsum[h];
            float f1 = o[j][2 * h + 1] * lsum[h];
            __nv_bfloat16 h0 = __float2bfloat16(f0);
            __nv_bfloat16 h1 = __float2bfloat16(f1);
            __nv_bfloat16 l0 = __float2bfloat16(f0 - __bfloat162float(h0));
            __nv_bfloat16 l1 = __float2bfloat16(f1 - __bfloat162float(h1));
            size_t off = ((size_t)(b * SS + srow) * DD + hh * 64 + dk) >> 1;
            ((__nv_bfloat162*)g_Ahi)[off] = __nv_bfloat162(h0, h1);
            ((__nv_bfloat162*)g_Alo)[off] = __nv_bfloat162(l0, l1);
        }
    }
}

// ---------------------------------------------------------------------------
// Output projection GEMM: Y = attn @ Wo^T + X
// ---------------------------------------------------------------------------
__global__ __launch_bounds__(256, 2) void oproj_mma(const float* __restrict__ X) {
    extern __shared__ char dyn[];
    float acc[2][8][4];

    int m0 = blockIdx.y * 128;
    int n0 = blockIdx.x * 128;

    mma_gemm(g_Ahi + (size_t)m0 * 1024, g_Alo + (size_t)m0 * 1024,
             g_Woh + (size_t)n0 * 1024, g_Wol + (size_t)n0 * 1024,
             dyn, acc);

    int t = threadIdx.x, lane = t & 31, wid = t >> 5;
    int wm = wid >> 1, wn = wid & 1;
#pragma unroll
    for (int tm = 0; tm < 2; tm++)
#pragma unroll
        for (int tn = 0; tn < 8; tn++) {
            int c = n0 + wn * 64 + tn * 8 + (lane & 3) * 2;
#pragma unroll
            for (int half = 0; half < 2; half++) {
                int m = m0 + wm * 32 + tm * 16 + (lane >> 2) + 8 * half;
                float2 xr = *(const float2*)&X[(size_t)m * 1024 + c];
                float2 v;
                v.x = acc[tm][tn][2 * half + 0] + xr.x;
                v.y = acc[tm][tn][2 * half + 1] + xr.y;
                *(float2*)&g_Y[(size_t)m * 1024 + c] = v;
            }
        }
}

// ---------------------------------------------------------------------------
// LayerNorm over D=1024 per row
// ---------------------------------------------------------------------------
__global__ void ln_kernel(const float* __restrict__ gamma,
                          const float* __restrict__ beta,
                          float* __restrict__ out)
{
    int row = blockIdx.x;
    int t   = threadIdx.x;
    const float* y = g_Y + (size_t)row * 1024;

    float x[4];
    float s = 0.0f;
#pragma unroll
    for (int u = 0; u < 4; u++) { x[u] = y[t + 256 * u]; s += x[u]; }

    __shared__ float red[32];
#pragma unroll
    for (int off = 16; off; off >>= 1) s += __shfl_xor_sync(0xffffffffu, s, off);
    if ((t & 31) == 0) red[t >> 5] = s;
    __syncthreads();
    if (t == 0) {
        float tot = 0.0f;
        for (int w = 0; w < 8; w++) tot += red[w];
        red[8] = tot;
    }
    __syncthreads();
    float mean = red[8] * (1.0f / 1024.0f);

    float vs = 0.0f;
#pragma unroll
    for (int u = 0; u < 4; u++) { float d = x[u] - mean; vs += d * d; }
#pragma unroll
    for (int off = 16; off; off >>= 1) vs += __shfl_xor_sync(0xffffffffu, vs, off);
    if ((t & 31) == 0) red[16 + (t >> 5)] = vs;
    __syncthreads();
    if (t == 0) {
        float tot = 0.0f;
        for (int w = 0; w < 8; w++) tot += red[16 + w];
        red[24] = tot;
    }
    __syncthreads();
    float var  = red[24] * (1.0f / 1024.0f);
    float rstd = rsqrtf(var + 1e-5f);

#pragma unroll
    for (int u = 0; u < 4; u++) {
        int c = t + 256 * u;
        out[(size_t)row * 1024 + c] = (x[u] - mean) * rstd * gamma[c] + beta[c];
    }
}

// ---------------------------------------------------------------------------
extern "C" void kernel_launch(void* const* d_in, const int* in_sizes, int n_in,
                              void* d_out, int out_size)
{
    const float* X     = (const float*)d_in[0];
    const float* Wq    = (const float*)d_in[1];
    const float* Wk    = (const float*)d_in[2];
    const float* Wv    = (const float*)d_in[3];
    const float* Wo    = (const float*)d_in[4];
    const float* alpha = (const float*)d_in[5];
    const float* lns   = (const float*)d_in[6];
    const float* lnb   = (const float*)d_in[7];
    float* out = (float*)d_out;

    static int attr_set = 0;
    if (!attr_set) {
        cudaFuncSetAttribute(qkv_mma,   cudaFuncAttributeMaxDynamicSharedMemorySize, DYN_SMEM);
        cudaFuncSetAttribute(oproj_mma, cudaFuncAttributeMaxDynamicSharedMemorySize, DYN_SMEM);
        attr_set = 1;
    }

    pe_kernel<<<(SS * DKK + 255) / 256, 256>>>();                 // 1
    convx_kernel<<<4096, 256>>>(X);                                // 2
    convw_kernel<<<4096, 256>>>(Wq, Wk, Wv, Wo);                   // 3
    qkv_mma<<<dim3(8, 32, 3), 256, DYN_SMEM>>>();                  // 4
    smear_kernel<<<(MM * DD) / 256, 256>>>(alpha);                 // 5
    attn_mma<<<dim3(32, 32), 128>>>();                             // 6
    oproj_mma<<<dim3(8, 32), 256, DYN_SMEM>>>(X);                  // 7
    ln_kernel<<<MM, 256>>>(lns, lnb, out);                         // 8
}

// round 8
// speedup vs baseline: 1.0820x; 1.0044x over previous
#include <cuda_runtime.h>
#include <cuda_bf16.h>
#include <math.h>
#include <stdint.h>

#define BB  2
#define SS  2048
#define DD  1024
#define HH  16
#define DKK 64
#define MM  (BB*SS)   // 4096 rows

// scale folded into Q: 1/sqrt(64) * log2(e)
#define SC2 0.18033688011112042f

// ---------------------------------------------------------------------------
// Scratch (allocation-free rule: __device__ globals)
// ---------------------------------------------------------------------------
__device__ __align__(16) float g_PE[SS*DKK];
__device__ __align__(16) float g_Kraw[MM*DD];
__device__ __align__(16) float g_Y[MM*DD];

__device__ __align__(16) __nv_bfloat16 g_Xhi[MM*DD];
__device__ __align__(16) __nv_bfloat16 g_Xlo[MM*DD];
__device__ __align__(16) __nv_bfloat16 g_Wh[3*DD*DD];
__device__ __align__(16) __nv_bfloat16 g_Wl[3*DD*DD];
__device__ __align__(16) __nv_bfloat16 g_Woh[DD*DD];
__device__ __align__(16) __nv_bfloat16 g_Wol[DD*DD];
__device__ __align__(16) __nv_bfloat16 g_Ahi[MM*DD];
__device__ __align__(16) __nv_bfloat16 g_Alo[MM*DD];

// attention operands, head-split [B*H][S][64], bf16 hi/lo
__device__ __align__(16) __nv_bfloat16 g_Qhi[MM*DD];
__device__ __align__(16) __nv_bfloat16 g_Qlo[MM*DD];
__device__ __align__(16) __nv_bfloat16 g_Khi[MM*DD];
__device__ __align__(16) __nv_bfloat16 g_Klo[MM*DD];
__device__ __align__(16) __nv_bfloat16 g_Vhi[MM*DD];
__device__ __align__(16) __nv_bfloat16 g_Vlo[MM*DD];

// ---------------------------------------------------------------------------
// PTX helpers (baseline sm_103-safe)
// ---------------------------------------------------------------------------
__device__ __forceinline__ uint32_t smem_u32(const void* p) {
    uint32_t a;
    asm("{ .reg .u64 t; cvta.to.shared.u64 t, %1; cvt.u32.u64 %0, t; }"
        : "=r"(a) : "l"(p));
    return a;
}

#define CPA16(dst, src) \
    asm volatile("cp.async.cg.shared.global [%0], [%1], 16;" :: "r"(dst), "l"(src) : "memory")
#define CPA_COMMIT() asm volatile("cp.async.commit_group;" ::: "memory")
#define CPA_WAIT1()  asm volatile("cp.async.wait_group 1;" ::: "memory")
#define CPA_WAIT0()  asm volatile("cp.async.wait_group 0;" ::: "memory")

__device__ __forceinline__ void ldsm_x4(uint32_t* r, uint32_t addr) {
    asm volatile("ldmatrix.sync.aligned.m8n8.x4.shared.b16 {%0,%1,%2,%3}, [%4];"
                 : "=r"(r[0]), "=r"(r[1]), "=r"(r[2]), "=r"(r[3]) : "r"(addr));
}
__device__ __forceinline__ void ldsm_x4_t(uint32_t* r, uint32_t addr) {
    asm volatile("ldmatrix.sync.aligned.m8n8.x4.trans.shared.b16 {%0,%1,%2,%3}, [%4];"
                 : "=r"(r[0]), "=r"(r[1]), "=r"(r[2]), "=r"(r[3]) : "r"(addr));
}

__device__ __forceinline__ void mma_bf16(float* c, const uint32_t* a, const uint32_t* b) {
    asm volatile(
        "mma.sync.aligned.m16n8k16.row.col.f32.bf16.bf16.f32 "
        "{%0,%1,%2,%3}, {%4,%5,%6,%7}, {%8,%9}, {%0,%1,%2,%3};"
        : "+f"(c[0]), "+f"(c[1]), "+f"(c[2]), "+f"(c[3])
        : "r"(a[0]), "r"(a[1]), "r"(a[2]), "r"(a[3]), "r"(b[0]), "r"(b[1]));
}

__device__ __forceinline__ float ex2(float x) {
    float r;
    asm("ex2.approx.ftz.f32 %0, %1;" : "=f"(r) : "f"(x));
    return r;
}
__device__ __forceinline__ uint32_t pk_bf2(float a, float b) {
    uint32_t r;
    asm("cvt.rn.bf16x2.f32 %0, %1, %2;" : "=r"(r) : "f"(b), "f"(a));
    return r;
}
__device__ __forceinline__ float bf_lo(uint32_t r) { return __uint_as_float(r << 16); }
__device__ __forceinline__ float bf_hi(uint32_t r) { return __uint_as_float(r & 0xFFFF0000u); }

// ---------------------------------------------------------------------------
__global__ void pe_kernel() {
    int idx = blockIdx.x * blockDim.x + threadIdx.x;
    if (idx >= SS * DKK) return;
    int s  = idx >> 6;
    int dk = idx & 63;
    int i  = dk >> 1;
    float freq = expf(-((float)(2 * i) / 64.0f) * 9.210340371976184f);
    float ang  = (float)s * freq;
    g_PE[idx]  = (dk & 1) ? cosf(ang) : sinf(ang);
}

// ---------------------------------------------------------------------------
// fp32 -> bf16 hi/lo split
// ---------------------------------------------------------------------------
__device__ __forceinline__ void split4(float4 v, __nv_bfloat162* hp, __nv_bfloat162* lp, int i) {
    __nv_bfloat16 h0 = __float2bfloat16(v.x);
    __nv_bfloat16 h1 = __float2bfloat16(v.y);
    __nv_bfloat16 h2 = __float2bfloat16(v.z);
    __nv_bfloat16 h3 = __float2bfloat16(v.w);
    __nv_bfloat16 l0 = __float2bfloat16(v.x - __bfloat162float(h0));
    __nv_bfloat16 l1 = __float2bfloat16(v.y - __bfloat162float(h1));
    __nv_bfloat16 l2 = __float2bfloat16(v.z - __bfloat162float(h2));
    __nv_bfloat16 l3 = __float2bfloat16(v.w - __bfloat162float(h3));
    hp[2*i]   = __nv_bfloat162(h0, h1);
    hp[2*i+1] = __nv_bfloat162(h2, h3);
    lp[2*i]   = __nv_bfloat162(l0, l1);
    lp[2*i+1] = __nv_bfloat162(l2, l3);
}

__global__ void convx_kernel(const float* __restrict__ src) {
    int i = blockIdx.x * blockDim.x + threadIdx.x;
    split4(((const float4*)src)[i], (__nv_bfloat162*)g_Xhi, (__nv_bfloat162*)g_Xlo, i);
}

__global__ void convw_kernel(const float* __restrict__ Wq, const float* __restrict__ Wk,
                             const float* __restrict__ Wv, const float* __restrict__ Wo) {
    int gi  = blockIdx.x * blockDim.x + threadIdx.x;
    int mat = gi >> 18;
    int i   = gi & 0x3FFFF;
    const float* src = (mat == 0) ? Wq : (mat == 1) ? Wk : (mat == 2) ? Wv : Wo;
    __nv_bfloat162* hp;
    __nv_bfloat162* lp;
    if (mat < 3) {
        hp = (__nv_bfloat162*)(g_Wh + (size_t)mat * DD * DD);
        lp = (__nv_bfloat162*)(g_Wl + (size_t)mat * DD * DD);
    } else {
        hp = (__nv_bfloat162*)g_Woh;
        lp = (__nv_bfloat162*)g_Wol;
    }
    split4(((const float4*)src)[i], hp, lp, i);
}

// ---------------------------------------------------------------------------
// bf16x3 HMMA GEMM mainloop: 3-stage cp.async pipeline, swizzled 64B rows.
// Pass-reordered MMA issue: HH sweep, HL sweep, LH sweep (no RAW chains).
// ---------------------------------------------------------------------------
#define MATB 8192            // 128 * 64
#define STG  (4 * MATB)      // 32768
#define DYN_SMEM (3 * STG)   // 98304

__device__ __forceinline__ void mma_gemm(
    const __nv_bfloat16* __restrict__ Ah, const __nv_bfloat16* __restrict__ Al,
    const __nv_bfloat16* __restrict__ Bh, const __nv_bfloat16* __restrict__ Bl,
    char* dyn, float acc[2][8][4])
{
    int t    = threadIdx.x;
    int lane = t & 31;
    int wid  = t >> 5;
    int wm   = wid >> 1;
    int wn   = wid & 1;
    uint32_t sbase = smem_u32(dyn);

    const char* mats[4] = {(const char*)Ah, (const char*)Al,
                           (const char*)Bh, (const char*)Bl};

#pragma unroll
    for (int tm = 0; tm < 2; tm++)
#pragma unroll
        for (int tn = 0; tn < 8; tn++)
#pragma unroll
            for (int u = 0; u < 4; u++) acc[tm][tn][u] = 0.0f;

    int idx0 = t * 8;
    auto load_stage = [&](int st, int kb) {
        uint32_t stb = sbase + st * STG;
#pragma unroll
        for (int q = 0; q < 8; q++) {
            int idx = idx0 + q;
            int mat = idx >> 9;
            int r   = (idx >> 2) & 127;
            int c   = idx & 3;
            uint32_t dst = stb + mat * MATB + r * 64 + ((c ^ ((r >> 1) & 3)) << 4);
            const char* src = mats[mat] + ((size_t)r * 1024 + kb + c * 8) * 2;
            CPA16(dst, src);
        }
        CPA_COMMIT();
    };

    int a_hi = lane >> 4;
    int b_hi = (lane >> 3) & 1;
    uint32_t aOff[2]; int aMsk[2];
#pragma unroll
    for (int tm = 0; tm < 2; tm++) {
        int r = wm * 32 + (lane & 15) + 16 * tm;
        aOff[tm] = (uint32_t)(r * 64);
        aMsk[tm] = (r >> 1) & 3;
    }
    uint32_t bOff[4]; int bMsk[4];
#pragma unroll
    for (int tp = 0; tp < 4; tp++) {
        int r = wn * 64 + (lane & 7) + 8 * (lane >> 4) + 16 * tp;
        bOff[tp] = (uint32_t)(r * 64);
        bMsk[tp] = (r >> 1) & 3;
    }

    load_stage(0, 0);
    load_stage(1, 32);

    int st = 0;
    for (int it = 0; it < 32; it++) {
        if (it < 31) { CPA_WAIT1(); } else { CPA_WAIT0(); }
        __syncthreads();
        if (it + 2 < 32) {
            int s2 = st + 2; if (s2 >= 3) s2 -= 3;
            load_stage(s2, (it + 2) * 32);
        }

        uint32_t stb = sbase + st * STG;
#pragma unroll
        for (int ks = 0; ks < 2; ks++) {
            int cA = 2 * ks + a_hi;
            int cB = 2 * ks + b_hi;
            uint32_t aH[2][4], aL[2][4], bH[8][2], bL[8][2];
#pragma unroll
            for (int tm = 0; tm < 2; tm++) {
                uint32_t off = aOff[tm] + (uint32_t)((cA ^ aMsk[tm]) << 4);
                ldsm_x4(aH[tm], stb + 0 * MATB + off);
                ldsm_x4(aL[tm], stb + 1 * MATB + off);
            }
#pragma unroll
            for (int tp = 0; tp < 4; tp++) {
                uint32_t off = bOff[tp] + (uint32_t)((cB ^ bMsk[tp]) << 4);
                ldsm_x4(&bH[2 * tp][0], stb + 2 * MATB + off);
                ldsm_x4(&bL[2 * tp][0], stb + 3 * MATB + off);
            }
            // pass 1: Ah*Bh — 16 independent accumulators
#pragma unroll
            for (int tm = 0; tm < 2; tm++)
#pragma unroll
                for (int tn = 0; tn < 8; tn++)
                    mma_bf16(acc[tm][tn], aH[tm], bH[tn]);
            // pass 2: Ah*Bl
#pragma unroll
            for (int tm = 0; tm < 2; tm++)
#pragma unroll
                for (int tn = 0; tn < 8; tn++)
                    mma_bf16(acc[tm][tn], aH[tm], bL[tn]);
            // pass 3: Al*Bh
#pragma unroll
            for (int tm = 0; tm < 2; tm++)
#pragma unroll
                for (int tn = 0; tn < 8; tn++)
                    mma_bf16(acc[tm][tn], aL[tm], bH[tn]);
        }
        st++; if (st == 3) st = 0;
    }
    __syncthreads();
}

// ---------------------------------------------------------------------------
// QKV GEMM. z=0: Q -> (acc+PE)*SC2 split bf16; z=1: K fp32; z=2: V split bf16
// ---------------------------------------------------------------------------
__global__ __launch_bounds__(256, 2) void qkv_mma() {
    extern __shared__ char dyn[];
    float acc[2][8][4];

    int z  = blockIdx.z;
    int m0 = blockIdx.y * 128;
    int n0 = blockIdx.x * 128;

    mma_gemm(g_Xhi + (size_t)m0 * 1024, g_Xlo + (size_t)m0 * 1024,
             g_Wh + (size_t)z * DD * DD + (size_t)n0 * 1024,
             g_Wl + (size_t)z * DD * DD + (size_t)n0 * 1024,
             dyn, acc);

    int t = threadIdx.x, lane = t & 31, wid = t >> 5;
    int wm = wid >> 1, wn = wid & 1;

#pragma unroll
    for (int tm = 0; tm < 2; tm++)
#pragma unroll
        for (int tn = 0; tn < 8; tn++) {
            int c  = n0 + wn * 64 + tn * 8 + (lane & 3) * 2;
            int h  = c >> 6, dk = c & 63;
#pragma unroll
            for (int half = 0; half < 2; half++) {
                int m = m0 + wm * 32 + tm * 16 + (lane >> 2) + 8 * half;
                int b = m >> 11, s = m & 2047;
                float vx = acc[tm][tn][2 * half + 0];
                float vy = acc[tm][tn][2 * half + 1];
                size_t off = ((size_t)((b * 16 + h) * 2048 + s)) * 64 + dk;
                if (z == 1) {
                    float2 v; v.x = vx; v.y = vy;
                    *(float2*)&g_Kraw[off] = v;
                } else {
                    if (z == 0) {
                        float2 pe = *(const float2*)&g_PE[s * 64 + dk];
                        vx = (vx + pe.x) * SC2;
                        vy = (vy + pe.y) * SC2;
                    }
                    __nv_bfloat16 hx = __float2bfloat16(vx);
                    __nv_bfloat16 hy = __float2bfloat16(vy);
                    __nv_bfloat16 lx = __float2bfloat16(vx - __bfloat162float(hx));
                    __nv_bfloat16 ly = __float2bfloat16(vy - __bfloat162float(hy));
                    __nv_bfloat162* oh = (__nv_bfloat162*)((z == 0) ? g_Qhi : g_Vhi);
                    __nv_bfloat162* ol = (__nv_bfloat162*)((z == 0) ? g_Qlo : g_Vlo);
                    oh[off >> 1] = __nv_bfloat162(hx, hy);
                    ol[off >> 1] = __nv_bfloat162(lx, ly);
                }
            }
        }
}

// ---------------------------------------------------------------------------
// EMA smear on K + PE add, output split to bf16 hi/lo
// ---------------------------------------------------------------------------
__global__ void smear_kernel(const float* __restrict__ alpha) {
    int idx = blockIdx.x * blockDim.x + threadIdx.x;
    int dk = idx & 63;
    int s  = (idx >> 6) & 2047;
    int h  = (idx >> 17) & 15;
    float kc = g_Kraw[idx];
    float v;
    if (s == 0) {
        v = kc;
    } else {
        float a = 1.0f / (1.0f + expf(-alpha[h * 2047 + (s - 1)]));
        v = a * kc + (1.0f - a) * g_Kraw[idx - 64];
    }
    v += g_PE[s * 64 + dk];
    __nv_bfloat16 hv = __float2bfloat16(v);
    g_Khi[idx] = hv;
    g_Klo[idx] = __float2bfloat16(v - __bfloat162float(hv));
}

// ---------------------------------------------------------------------------
// Causal flash attention, bf16x3 HMMA, single-stage, pass-reordered MMAs.
// ---------------------------------------------------------------------------
#define ASTR 144
#define AMAT (64 * ASTR)   // 9216

__global__ __launch_bounds__(128, 4) void attn_mma() {
    __shared__ __align__(16) char sm[4 * AMAT];
    uint32_t sb = smem_u32(sm);

    int t = threadIdx.x, lane = t & 31, w = t >> 5;
    int qt = 31 - (int)blockIdx.x;          // heavy tiles first
    int qb = qt * 64;
    int bh = blockIdx.y;
    size_t base = (size_t)bh * SS * DKK;

    {
        const char* qsrc[2] = {(const char*)(g_Qhi + base), (const char*)(g_Qlo + base)};
#pragma unroll
        for (int q = 0; q < 8; q++) {
            int idx = t * 8 + q;
            int mat = idx >> 9;
            int r   = (idx >> 3) & 63;
            int c   = idx & 7;
            CPA16(sb + mat * AMAT + r * ASTR + c * 16,
                  qsrc[mat] + ((size_t)(qb + r) * 64 + c * 8) * 2);
        }
        CPA_COMMIT(); CPA_WAIT0();
        __syncthreads();
    }

    uint32_t qh[4][4], ql[4][4];
    {
        int ar = w * 16 + (lane & 15);
#pragma unroll
        for (int k = 0; k < 4; k++) {
            uint32_t acol = (uint32_t)(k * 32 + (lane >> 4) * 16);
            ldsm_x4(qh[k], sb + 0 * AMAT + ar * ASTR + acol);
            ldsm_x4(ql[k], sb + 1 * AMAT + ar * ASTR + acol);
        }
    }

    float o[8][4];
    float m2[2], lsum[2];
#pragma unroll
    for (int j = 0; j < 8; j++)
#pragma unroll
        for (int u = 0; u < 4; u++) o[j][u] = 0.0f;
    m2[0] = m2[1] = -1e30f;
    lsum[0] = lsum[1] = 0.0f;

    const char* kvsrc[4] = {(const char*)(g_Khi + base), (const char*)(g_Klo + base),
                            (const char*)(g_Vhi + base), (const char*)(g_Vlo + base)};

    int r0 = (lane >> 2);
    int ntiles = qt + 1;

    for (int tile = 0; tile < ntiles; tile++) {
        int kb = tile * 64;
        __syncthreads();
#pragma unroll
        for (int q = 0; q < 16; q++) {
            int idx = t * 16 + q;
            int mat = idx >> 9;
            int r   = (idx >> 3) & 63;
            int c   = idx & 7;
            CPA16(sb + mat * AMAT + r * ASTR + c * 16,
                  kvsrc[mat] + ((size_t)(kb + r) * 64 + c * 8) * 2);
        }
        CPA_COMMIT(); CPA_WAIT0();
        __syncthreads();

        // ---- S = Q K^T (bf16x3), pass-reordered ----
        float s[8][4];
#pragma unroll
        for (int j = 0; j < 8; j++)
#pragma unroll
            for (int u = 0; u < 4; u++) s[j][u] = 0.0f;

        {
            int b_row = (lane & 7) + 8 * (lane >> 4);
#pragma unroll
            for (int k = 0; k < 4; k++) {
                uint32_t bcol = (uint32_t)((k * 16 + 8 * ((lane >> 3) & 1)) * 2);
                uint32_t kH[8][2], kL[8][2];
#pragma unroll
                for (int tp = 0; tp < 4; tp++) {
                    uint32_t off = (uint32_t)((b_row + 16 * tp) * ASTR) + bcol;
                    ldsm_x4(&kH[2 * tp][0], sb + 0 * AMAT + off);
                    ldsm_x4(&kL[2 * tp][0], sb + 1 * AMAT + off);
                }
#pragma unroll
                for (int j = 0; j < 8; j++) mma_bf16(s[j], qh[k], kH[j]);
#pragma unroll
                for (int j = 0; j < 8; j++) mma_bf16(s[j], qh[k], kL[j]);
#pragma unroll
                for (int j = 0; j < 8; j++) mma_bf16(s[j], ql[k], kH[j]);
            }
        }

        if (tile == ntiles - 1) {
#pragma unroll
            for (int j = 0; j < 8; j++)
#pragma unroll
                for (int u = 0; u < 4; u++) {
                    int row = (w * 16) + r0 + 8 * (u >> 1);
                    int col = j * 8 + 2 * (lane & 3) + (u & 1);
                    if (col > row) s[j][u] = -1e30f;
                }
        }

#pragma unroll
        for (int h = 0; h < 2; h++) {
            float mx = -1e30f;
#pragma unroll
            for (int j = 0; j < 8; j++) {
                mx = fmaxf(mx, s[j][2 * h + 0]);
                mx = fmaxf(mx, s[j][2 * h + 1]);
            }
            mx = fmaxf(mx, __shfl_xor_sync(0xffffffffu, mx, 1));
            mx = fmaxf(mx, __shfl_xor_sync(0xffffffffu, mx, 2));
            float mnew = fmaxf(m2[h], mx);
            float corr = ex2(m2[h] - mnew);
            m2[h] = mnew;
            float rs = 0.0f;
#pragma unroll
            for (int j = 0; j < 8; j++) {
                float p0 = ex2(s[j][2 * h + 0] - mnew);
                float p1 = ex2(s[j][2 * h + 1] - mnew);
                s[j][2 * h + 0] = p0;
                s[j][2 * h + 1] = p1;
                rs += p0 + p1;
            }
            lsum[h] = lsum[h] * corr + rs;
#pragma unroll
            for (int j = 0; j < 8; j++) {
                o[j][2 * h + 0] *= corr;
                o[j][2 * h + 1] *= corr;
            }
        }

        uint32_t pH[4][4], pL[4][4];
#pragma unroll
        for (int kk = 0; kk < 4; kk++) {
            int j = 2 * kk;
#pragma unroll
            for (int q = 0; q < 4; q++) {
                int jj = j + (q >> 1);
                float a = s[jj][(q & 1) * 2 + 0];
                float b = s[jj][(q & 1) * 2 + 1];
                uint32_t hi2 = pk_bf2(a, b);
                pH[kk][q] = hi2;
                pL[kk][q] = pk_bf2(a - bf_lo(hi2), b - bf_hi(hi2));
            }
        }

        // ---- O += P V (bf16x3), pass-reordered ----
        {
            int vrow = (lane & 7) + 8 * ((lane >> 3) & 1);
            uint32_t vcol = (uint32_t)(16 * (lane >> 4));
#pragma unroll
            for (int kk = 0; kk < 4; kk++) {
                uint32_t vH[8][2], vL[8][2];
#pragma unroll
                for (int jj = 0; jj < 4; jj++) {
                    uint32_t off = (uint32_t)((kk * 16 + vrow) * ASTR) + (uint32_t)(jj * 32) + vcol;
                    ldsm_x4_t(&vH[2 * jj][0], sb + 2 * AMAT + off);
                    ldsm_x4_t(&vL[2 * jj][0], sb + 3 * AMAT + off);
                }
#pragma unroll
                for (int j = 0; j < 8; j++) mma_bf16(o[j], pH[kk], vH[j]);
#pragma unroll
                for (int j = 0; j < 8; j++) mma_bf16(o[j], pL[kk], vH[j]);
#pragma unroll
                for (int j = 0; j < 8; j++) mma_bf16(o[j], pH[kk], vL[j]);
            }
        }
    }

#pragma unroll
    for (int h = 0; h < 2; h++) {
        lsum[h] += __shfl_xor_sync(0xffffffffu, lsum[h], 1);
        lsum[h] += __shfl_xor_sync(0xffffffffu, lsum[h], 2);
        lsum[h] = 1.0f / lsum[h];
    }

    int b = bh >> 4, hh = bh & 15;
#pragma unroll
    for (int j = 0; j < 8; j++) {
        int dk = j * 8 + 2 * (lane & 3);
#pragma unroll
        for (int h = 0; h < 2; h++) {
            int srow = qb + w * 16 + r0 + 8 * h;
            float f0 = o[j][2 * h + 0] * lsum[h];
            float f1 = o[j][2 * h + 1] * lsum[h];
            __nv_bfloat16 h0 = __float2bfloat16(f0);
            __nv_bfloat16 h1 = __float2bfloat16(f1);
            __nv_bfloat16 l0 = __float2bfloat16(f0 - __bfloat162float(h0));
            __nv_bfloat16 l1 = __float2bfloat16(f1 - __bfloat162float(h1));
            size_t off = ((size_t)(b * SS + srow) * DD + hh * 64 + dk) >> 1;
            ((__nv_bfloat162*)g_Ahi)[off] = __nv_bfloat162(h0, h1);
            ((__nv_bfloat162*)g_Alo)[off] = __nv_bfloat162(l0, l1);
        }
    }
}

// ---------------------------------------------------------------------------
// Output projection GEMM: Y = attn @ Wo^T + X
// ---------------------------------------------------------------------------
__global__ __launch_bounds__(256, 2) void oproj_mma(const float* __restrict__ X) {
    extern __shared__ char dyn[];
    float acc[2][8][4];

    int m0 = blockIdx.y * 128;
    int n0 = blockIdx.x * 128;

    mma_gemm(g_Ahi + (size_t)m0 * 1024, g_Alo + (size_t)m0 * 1024,
             g_Woh + (size_t)n0 * 1024, g_Wol + (size_t)n0 * 1024,
             dyn, acc);

    int t = threadIdx.x, lane = t & 31, wid = t >> 5;
    int wm = wid >> 1, wn = wid & 1;
#pragma unroll
    for (int tm = 0; tm < 2; tm++)
#pragma unroll
        for (int tn = 0; tn < 8; tn++) {
            int c = n0 + wn * 64 + tn * 8 + (lane & 3) * 2;
#pragma unroll
            for (int half = 0; half < 2; half++) {
                int m = m0 + wm * 32 + tm * 16 + (lane >> 2) + 8 * half;
                float2 xr = *(const float2*)&X[(size_t)m * 1024 + c];
                float2 v;
                v.x = acc[tm][tn][2 * half + 0] + xr.x;
                v.y = acc[tm][tn][2 * half + 1] + xr.y;
                *(float2*)&g_Y[(size_t)m * 1024 + c] = v;
            }
        }
}

// ---------------------------------------------------------------------------
// LayerNorm over D=1024 per row
// ---------------------------------------------------------------------------
__global__ void ln_kernel(const float* __restrict__ gamma,
                          const float* __restrict__ beta,
                          float* __restrict__ out)
{
    int row = blockIdx.x;
    int t   = threadIdx.x;
    const float* y = g_Y + (size_t)row * 1024;

    float x[4];
    float s = 0.0f;
#pragma unroll
    for (int u = 0; u < 4; u++) { x[u] = y[t + 256 * u]; s += x[u]; }

    __shared__ float red[32];
#pragma unroll
    for (int off = 16; off; off >>= 1) s += __shfl_xor_sync(0xffffffffu, s, off);
    if ((t & 31) == 0) red[t >> 5] = s;
    __syncthreads();
    if (t == 0) {
        float tot = 0.0f;
        for (int w = 0; w < 8; w++) tot += red[w];
        red[8] = tot;
    }
    __syncthreads();
    float mean = red[8] * (1.0f / 1024.0f);

    float vs = 0.0f;
#pragma unroll
    for (int u = 0; u < 4; u++) { float d = x[u] - mean; vs += d * d; }
#pragma unroll
    for (int off = 16; off; off >>= 1) vs += __shfl_xor_sync(0xffffffffu, vs, off);
    if ((t & 31) == 0) red[16 + (t >> 5)] = vs;
    __syncthreads();
    if (t == 0) {
        float tot = 0.0f;
        for (int w = 0; w < 8; w++) tot += red[16 + w];
        red[24] = tot;
    }
    __syncthreads();
    float var  = red[24] * (1.0f / 1024.0f);
    float rstd = rsqrtf(var + 1e-5f);

#pragma unroll
    for (int u = 0; u < 4; u++) {
        int c = t + 256 * u;
        out[(size_t)row * 1024 + c] = (x[u] - mean) * rstd * gamma[c] + beta[c];
    }
}

// ---------------------------------------------------------------------------
extern "C" void kernel_launch(void* const* d_in, const int* in_sizes, int n_in,
                              void* d_out, int out_size)
{
    const float* X     = (const float*)d_in[0];
    const float* Wq    = (const float*)d_in[1];
    const float* Wk    = (const float*)d_in[2];
    const float* Wv    = (const float*)d_in[3];
    const float* Wo    = (const float*)d_in[4];
    const float* alpha = (const float*)d_in[5];
    const float* lns   = (const float*)d_in[6];
    const float* lnb   = (const float*)d_in[7];
    float* out = (float*)d_out;

    static int attr_set = 0;
    if (!attr_set) {
        cudaFuncSetAttribute(qkv_mma,   cudaFuncAttributeMaxDynamicSharedMemorySize, DYN_SMEM);
        cudaFuncSetAttribute(oproj_mma, cudaFuncAttributeMaxDynamicSharedMemorySize, DYN_SMEM);
        attr_set = 1;
    }

    pe_kernel<<<(SS * DKK + 255) / 256, 256>>>();                 // 1
    convx_kernel<<<4096, 256>>>(X);                                // 2
    convw_kernel<<<4096, 256>>>(Wq, Wk, Wv, Wo);                   // 3
    qkv_mma<<<dim3(8, 32, 3), 256, DYN_SMEM>>>();                  // 4
    smear_kernel<<<(MM * DD) / 256, 256>>>(alpha);                 // 5
    attn_mma<<<dim3(32, 32), 128>>>();                             // 6
    oproj_mma<<<dim3(8, 32), 256, DYN_SMEM>>>(X);                  // 7
    ln_kernel<<<MM, 256>>>(lns, lnb, out);                         // 8
}

// round 9
// speedup vs baseline: 1.0912x; 1.0086x over previous
#include <cuda_runtime.h>
#include <cuda_bf16.h>
#include <math.h>
#include <stdint.h>

#define BB  2
#define SS  2048
#define DD  1024
#define HH  16
#define DKK 64
#define MM  (BB*SS)   // 4096 rows

// scale folded into Q: 1/sqrt(64) * log2(e)
#define SC2 0.18033688011112042f

// ---------------------------------------------------------------------------
// Scratch (allocation-free rule: __device__ globals)
// ---------------------------------------------------------------------------
__device__ __align__(16) float g_PE[SS*DKK];
__device__ __align__(16) float g_Kraw[MM*DD];
__device__ __align__(16) float g_Y[MM*DD];

__device__ __align__(16) __nv_bfloat16 g_Xhi[MM*DD];
__device__ __align__(16) __nv_bfloat16 g_Xlo[MM*DD];
__device__ __align__(16) __nv_bfloat16 g_Wh[3*DD*DD];
__device__ __align__(16) __nv_bfloat16 g_Wl[3*DD*DD];
__device__ __align__(16) __nv_bfloat16 g_Woh[DD*DD];
__device__ __align__(16) __nv_bfloat16 g_Wol[DD*DD];
__device__ __align__(16) __nv_bfloat16 g_Ahi[MM*DD];
__device__ __align__(16) __nv_bfloat16 g_Alo[MM*DD];

// attention operands, head-split [B*H][S][64], bf16 hi/lo
__device__ __align__(16) __nv_bfloat16 g_Qhi[MM*DD];
__device__ __align__(16) __nv_bfloat16 g_Qlo[MM*DD];
__device__ __align__(16) __nv_bfloat16 g_Khi[MM*DD];
__device__ __align__(16) __nv_bfloat16 g_Klo[MM*DD];
__device__ __align__(16) __nv_bfloat16 g_Vhi[MM*DD];
__device__ __align__(16) __nv_bfloat16 g_Vlo[MM*DD];

// ---------------------------------------------------------------------------
// PTX helpers (baseline sm_103-safe)
// ---------------------------------------------------------------------------
__device__ __forceinline__ uint32_t smem_u32(const void* p) {
    uint32_t a;
    asm("{ .reg .u64 t; cvta.to.shared.u64 t, %1; cvt.u32.u64 %0, t; }"
        : "=r"(a) : "l"(p));
    return a;
}

#define CPA16(dst, src) \
    asm volatile("cp.async.cg.shared.global [%0], [%1], 16;" :: "r"(dst), "l"(src) : "memory")
#define CPA_COMMIT() asm volatile("cp.async.commit_group;" ::: "memory")
#define CPA_WAIT1()  asm volatile("cp.async.wait_group 1;" ::: "memory")
#define CPA_WAIT0()  asm volatile("cp.async.wait_group 0;" ::: "memory")

__device__ __forceinline__ void ldsm_x4(uint32_t* r, uint32_t addr) {
    asm volatile("ldmatrix.sync.aligned.m8n8.x4.shared.b16 {%0,%1,%2,%3}, [%4];"
                 : "=r"(r[0]), "=r"(r[1]), "=r"(r[2]), "=r"(r[3]) : "r"(addr));
}
__device__ __forceinline__ void ldsm_x4_t(uint32_t* r, uint32_t addr) {
    asm volatile("ldmatrix.sync.aligned.m8n8.x4.trans.shared.b16 {%0,%1,%2,%3}, [%4];"
                 : "=r"(r[0]), "=r"(r[1]), "=r"(r[2]), "=r"(r[3]) : "r"(addr));
}

__device__ __forceinline__ void mma_bf16(float* c, const uint32_t* a, const uint32_t* b) {
    asm volatile(
        "mma.sync.aligned.m16n8k16.row.col.f32.bf16.bf16.f32 "
        "{%0,%1,%2,%3}, {%4,%5,%6,%7}, {%8,%9}, {%0,%1,%2,%3};"
        : "+f"(c[0]), "+f"(c[1]), "+f"(c[2]), "+f"(c[3])
        : "r"(a[0]), "r"(a[1]), "r"(a[2]), "r"(a[3]), "r"(b[0]), "r"(b[1]));
}

__device__ __forceinline__ float ex2(float x) {
    float r;
    asm("ex2.approx.ftz.f32 %0, %1;" : "=f"(r) : "f"(x));
    return r;
}
__device__ __forceinline__ uint32_t pk_bf2(float a, float b) {
    uint32_t r;
    asm("cvt.rn.bf16x2.f32 %0, %1, %2;" : "=r"(r) : "f"(b), "f"(a));
    return r;
}
__device__ __forceinline__ float bf_lo(uint32_t r) { return __uint_as_float(r << 16); }
__device__ __forceinline__ float bf_hi(uint32_t r) { return __uint_as_float(r & 0xFFFF0000u); }

// ---------------------------------------------------------------------------
__global__ void pe_kernel() {
    int idx = blockIdx.x * blockDim.x + threadIdx.x;
    if (idx >= SS * DKK) return;
    int s  = idx >> 6;
    int dk = idx & 63;
    int i  = dk >> 1;
    float freq = expf(-((float)(2 * i) / 64.0f) * 9.210340371976184f);
    float ang  = (float)s * freq;
    g_PE[idx]  = (dk & 1) ? cosf(ang) : sinf(ang);
}

// ---------------------------------------------------------------------------
// fp32 -> bf16 hi/lo split
// ---------------------------------------------------------------------------
__device__ __forceinline__ void split4(float4 v, __nv_bfloat162* hp, __nv_bfloat162* lp, int i) {
    __nv_bfloat16 h0 = __float2bfloat16(v.x);
    __nv_bfloat16 h1 = __float2bfloat16(v.y);
    __nv_bfloat16 h2 = __float2bfloat16(v.z);
    __nv_bfloat16 h3 = __float2bfloat16(v.w);
    __nv_bfloat16 l0 = __float2bfloat16(v.x - __bfloat162float(h0));
    __nv_bfloat16 l1 = __float2bfloat16(v.y - __bfloat162float(h1));
    __nv_bfloat16 l2 = __float2bfloat16(v.z - __bfloat162float(h2));
    __nv_bfloat16 l3 = __float2bfloat16(v.w - __bfloat162float(h3));
    hp[2*i]   = __nv_bfloat162(h0, h1);
    hp[2*i+1] = __nv_bfloat162(h2, h3);
    lp[2*i]   = __nv_bfloat162(l0, l1);
    lp[2*i+1] = __nv_bfloat162(l2, l3);
}

__global__ void convx_kernel(const float* __restrict__ src) {
    int i = blockIdx.x * blockDim.x + threadIdx.x;
    split4(((const float4*)src)[i], (__nv_bfloat162*)g_Xhi, (__nv_bfloat162*)g_Xlo, i);
}

__global__ void convw_kernel(const float* __restrict__ Wq, const float* __restrict__ Wk,
                             const float* __restrict__ Wv, const float* __restrict__ Wo) {
    int gi  = blockIdx.x * blockDim.x + threadIdx.x;
    int mat = gi >> 18;
    int i   = gi & 0x3FFFF;
    const float* src = (mat == 0) ? Wq : (mat == 1) ? Wk : (mat == 2) ? Wv : Wo;
    __nv_bfloat162* hp;
    __nv_bfloat162* lp;
    if (mat < 3) {
        hp = (__nv_bfloat162*)(g_Wh + (size_t)mat * DD * DD);
        lp = (__nv_bfloat162*)(g_Wl + (size_t)mat * DD * DD);
    } else {
        hp = (__nv_bfloat162*)g_Woh;
        lp = (__nv_bfloat162*)g_Wol;
    }
    split4(((const float4*)src)[i], hp, lp, i);
}

// ---------------------------------------------------------------------------
// bf16x3 HMMA GEMM mainloop: 128 threads, 64x64 warp tiles (2x2 warp grid),
// 3-stage cp.async pipeline, swizzled 64B rows.
// ---------------------------------------------------------------------------
#define MATB 8192            // 128 * 64
#define STG  (4 * MATB)      // 32768
#define DYN_SMEM (3 * STG)   // 98304

__device__ __forceinline__ void mma_gemm(
    const __nv_bfloat16* __restrict__ Ah, const __nv_bfloat16* __restrict__ Al,
    const __nv_bfloat16* __restrict__ Bh, const __nv_bfloat16* __restrict__ Bl,
    char* dyn, float acc[4][8][4])
{
    int t    = threadIdx.x;
    int lane = t & 31;
    int wid  = t >> 5;
    int wm   = wid & 1;       // warp row (64 rows)
    int wn   = wid >> 1;      // warp col (64 cols)
    uint32_t sbase = smem_u32(dyn);

    const char* mats[4] = {(const char*)Ah, (const char*)Al,
                           (const char*)Bh, (const char*)Bl};

#pragma unroll
    for (int tm = 0; tm < 4; tm++)
#pragma unroll
        for (int tn = 0; tn < 8; tn++)
#pragma unroll
            for (int u = 0; u < 4; u++) acc[tm][tn][u] = 0.0f;

    // copy: 2048 16B-chunks per stage, 16 per thread
    int idx0 = t * 16;
    auto load_stage = [&](int st, int kb) {
        uint32_t stb = sbase + st * STG;
#pragma unroll
        for (int q = 0; q < 16; q++) {
            int idx = idx0 + q;
            int mat = idx >> 9;
            int r   = (idx >> 2) & 127;
            int c   = idx & 3;
            uint32_t dst = stb + mat * MATB + r * 64 + ((c ^ ((r >> 1) & 3)) << 4);
            const char* src = mats[mat] + ((size_t)r * 1024 + kb + c * 8) * 2;
            CPA16(dst, src);
        }
        CPA_COMMIT();
    };

    int a_hi = lane >> 4;
    int b_hi = (lane >> 3) & 1;
    uint32_t aOff[4]; int aMsk[4];
#pragma unroll
    for (int tm = 0; tm < 4; tm++) {
        int r = wm * 64 + (lane & 15) + 16 * tm;
        aOff[tm] = (uint32_t)(r * 64);
        aMsk[tm] = (r >> 1) & 3;
    }
    uint32_t bOff[4]; int bMsk[4];
#pragma unroll
    for (int tp = 0; tp < 4; tp++) {
        int r = wn * 64 + (lane & 7) + 8 * (lane >> 4) + 16 * tp;
        bOff[tp] = (uint32_t)(r * 64);
        bMsk[tp] = (r >> 1) & 3;
    }

    load_stage(0, 0);
    load_stage(1, 32);

    int st = 0;
    for (int it = 0; it < 32; it++) {
        if (it < 31) { CPA_WAIT1(); } else { CPA_WAIT0(); }
        __syncthreads();
        if (it + 2 < 32) {
            int s2 = st + 2; if (s2 >= 3) s2 -= 3;
            load_stage(s2, (it + 2) * 32);
        }

        uint32_t stb = sbase + st * STG;
#pragma unroll
        for (int ks = 0; ks < 2; ks++) {
            int cA = 2 * ks + a_hi;
            int cB = 2 * ks + b_hi;
            uint32_t aH[4][4], aL[4][4], bH[8][2], bL[8][2];
#pragma unroll
            for (int tm = 0; tm < 4; tm++) {
                uint32_t off = aOff[tm] + (uint32_t)((cA ^ aMsk[tm]) << 4);
                ldsm_x4(aH[tm], stb + 0 * MATB + off);
                ldsm_x4(aL[tm], stb + 1 * MATB + off);
            }
#pragma unroll
            for (int tp = 0; tp < 4; tp++) {
                uint32_t off = bOff[tp] + (uint32_t)((cB ^ bMsk[tp]) << 4);
                ldsm_x4(&bH[2 * tp][0], stb + 2 * MATB + off);
                ldsm_x4(&bL[2 * tp][0], stb + 3 * MATB + off);
            }
            // pass 1: Ah*Bh — 32 independent accumulators
#pragma unroll
            for (int tm = 0; tm < 4; tm++)
#pragma unroll
                for (int tn = 0; tn < 8; tn++)
                    mma_bf16(acc[tm][tn], aH[tm], bH[tn]);
            // pass 2: Ah*Bl
#pragma unroll
            for (int tm = 0; tm < 4; tm++)
#pragma unroll
                for (int tn = 0; tn < 8; tn++)
                    mma_bf16(acc[tm][tn], aH[tm], bL[tn]);
            // pass 3: Al*Bh
#pragma unroll
            for (int tm = 0; tm < 4; tm++)
#pragma unroll
                for (int tn = 0; tn < 8; tn++)
                    mma_bf16(acc[tm][tn], aL[tm], bH[tn]);
        }
        st++; if (st == 3) st = 0;
    }
    __syncthreads();
}

// ---------------------------------------------------------------------------
// QKV GEMM. z=0: Q -> (acc+PE)*SC2 split bf16; z=1: K fp32; z=2: V split bf16
// ---------------------------------------------------------------------------
__global__ __launch_bounds__(128, 2) void qkv_mma() {
    extern __shared__ char dyn[];
    float acc[4][8][4];

    int z  = blockIdx.z;
    int m0 = blockIdx.y * 128;
    int n0 = blockIdx.x * 128;

    mma_gemm(g_Xhi + (size_t)m0 * 1024, g_Xlo + (size_t)m0 * 1024,
             g_Wh + (size_t)z * DD * DD + (size_t)n0 * 1024,
             g_Wl + (size_t)z * DD * DD + (size_t)n0 * 1024,
             dyn, acc);

    int t = threadIdx.x, lane = t & 31, wid = t >> 5;
    int wm = wid & 1, wn = wid >> 1;

#pragma unroll
    for (int tm = 0; tm < 4; tm++)
#pragma unroll
        for (int tn = 0; tn < 8; tn++) {
            int c  = n0 + wn * 64 + tn * 8 + (lane & 3) * 2;
            int h  = c >> 6, dk = c & 63;
#pragma unroll
            for (int half = 0; half < 2; half++) {
                int m = m0 + wm * 64 + tm * 16 + (lane >> 2) + 8 * half;
                int b = m >> 11, s = m & 2047;
                float vx = acc[tm][tn][2 * half + 0];
                float vy = acc[tm][tn][2 * half + 1];
                size_t off = ((size_t)((b * 16 + h) * 2048 + s)) * 64 + dk;
                if (z == 1) {
                    float2 v; v.x = vx; v.y = vy;
                    *(float2*)&g_Kraw[off] = v;
                } else {
                    if (z == 0) {
                        float2 pe = *(const float2*)&g_PE[s * 64 + dk];
                        vx = (vx + pe.x) * SC2;
                        vy = (vy + pe.y) * SC2;
                    }
                    __nv_bfloat16 hx = __float2bfloat16(vx);
                    __nv_bfloat16 hy = __float2bfloat16(vy);
                    __nv_bfloat16 lx = __float2bfloat16(vx - __bfloat162float(hx));
                    __nv_bfloat16 ly = __float2bfloat16(vy - __bfloat162float(hy));
                    __nv_bfloat162* oh = (__nv_bfloat162*)((z == 0) ? g_Qhi : g_Vhi);
                    __nv_bfloat162* ol = (__nv_bfloat162*)((z == 0) ? g_Qlo : g_Vlo);
                    oh[off >> 1] = __nv_bfloat162(hx, hy);
                    ol[off >> 1] = __nv_bfloat162(lx, ly);
                }
            }
        }
}

// ---------------------------------------------------------------------------
// EMA smear on K + PE add, output split to bf16 hi/lo
// ---------------------------------------------------------------------------
__global__ void smear_kernel(const float* __restrict__ alpha) {
    int idx = blockIdx.x * blockDim.x + threadIdx.x;
    int dk = idx & 63;
    int s  = (idx >> 6) & 2047;
    int h  = (idx >> 17) & 15;
    float kc = g_Kraw[idx];
    float v;
    if (s == 0) {
        v = kc;
    } else {
        float a = 1.0f / (1.0f + expf(-alpha[h * 2047 + (s - 1)]));
        v = a * kc + (1.0f - a) * g_Kraw[idx - 64];
    }
    v += g_PE[s * 64 + dk];
    __nv_bfloat16 hv = __float2bfloat16(v);
    g_Khi[idx] = hv;
    g_Klo[idx] = __float2bfloat16(v - __bfloat162float(hv));
}

// ---------------------------------------------------------------------------
// Causal flash attention, bf16x3 HMMA (unchanged from R8)
// ---------------------------------------------------------------------------
#define ASTR 144
#define AMAT (64 * ASTR)   // 9216

__global__ __launch_bounds__(128, 4) void attn_mma() {
    __shared__ __align__(16) char sm[4 * AMAT];
    uint32_t sb = smem_u32(sm);

    int t = threadIdx.x, lane = t & 31, w = t >> 5;
    int qt = 31 - (int)blockIdx.x;          // heavy tiles first
    int qb = qt * 64;
    int bh = blockIdx.y;
    size_t base = (size_t)bh * SS * DKK;

    {
        const char* qsrc[2] = {(const char*)(g_Qhi + base), (const char*)(g_Qlo + base)};
#pragma unroll
        for (int q = 0; q < 8; q++) {
            int idx = t * 8 + q;
            int mat = idx >> 9;
            int r   = (idx >> 3) & 63;
            int c   = idx & 7;
            CPA16(sb + mat * AMAT + r * ASTR + c * 16,
                  qsrc[mat] + ((size_t)(qb + r) * 64 + c * 8) * 2);
        }
        CPA_COMMIT(); CPA_WAIT0();
        __syncthreads();
    }

    uint32_t qh[4][4], ql[4][4];
    {
        int ar = w * 16 + (lane & 15);
#pragma unroll
        for (int k = 0; k < 4; k++) {
            uint32_t acol = (uint32_t)(k * 32 + (lane >> 4) * 16);
            ldsm_x4(qh[k], sb + 0 * AMAT + ar * ASTR + acol);
            ldsm_x4(ql[k], sb + 1 * AMAT + ar * ASTR + acol);
        }
    }

    float o[8][4];
    float m2[2], lsum[2];
#pragma unroll
    for (int j = 0; j < 8; j++)
#pragma unroll
        for (int u = 0; u < 4; u++) o[j][u] = 0.0f;
    m2[0] = m2[1] = -1e30f;
    lsum[0] = lsum[1] = 0.0f;

    const char* kvsrc[4] = {(const char*)(g_Khi + base), (const char*)(g_Klo + base),
                            (const char*)(g_Vhi + base), (const char*)(g_Vlo + base)};

    int r0 = (lane >> 2);
    int ntiles = qt + 1;

    for (int tile = 0; tile < ntiles; tile++) {
        int kb = tile * 64;
        __syncthreads();
#pragma unroll
        for (int q = 0; q < 16; q++) {
            int idx = t * 16 + q;
            int mat = idx >> 9;
            int r   = (idx >> 3) & 63;
            int c   = idx & 7;
            CPA16(sb + mat * AMAT + r * ASTR + c * 16,
                  kvsrc[mat] + ((size_t)(kb + r) * 64 + c * 8) * 2);
        }
        CPA_COMMIT(); CPA_WAIT0();
        __syncthreads();

        float s[8][4];
#pragma unroll
        for (int j = 0; j < 8; j++)
#pragma unroll
            for (int u = 0; u < 4; u++) s[j][u] = 0.0f;

        {
            int b_row = (lane & 7) + 8 * (lane >> 4);
#pragma unroll
            for (int k = 0; k < 4; k++) {
                uint32_t bcol = (uint32_t)((k * 16 + 8 * ((lane >> 3) & 1)) * 2);
                uint32_t kH[8][2], kL[8][2];
#pragma unroll
                for (int tp = 0; tp < 4; tp++) {
                    uint32_t off = (uint32_t)((b_row + 16 * tp) * ASTR) + bcol;
                    ldsm_x4(&kH[2 * tp][0], sb + 0 * AMAT + off);
                    ldsm_x4(&kL[2 * tp][0], sb + 1 * AMAT + off);
                }
#pragma unroll
                for (int j = 0; j < 8; j++) mma_bf16(s[j], qh[k], kH[j]);
#pragma unroll
                for (int j = 0; j < 8; j++) mma_bf16(s[j], qh[k], kL[j]);
#pragma unroll
                for (int j = 0; j < 8; j++) mma_bf16(s[j], ql[k], kH[j]);
            }
        }

        if (tile == ntiles - 1) {
#pragma unroll
            for (int j = 0; j < 8; j++)
#pragma unroll
                for (int u = 0; u < 4; u++) {
                    int row = (w * 16) + r0 + 8 * (u >> 1);
                    int col = j * 8 + 2 * (lane & 3) + (u & 1);
                    if (col > row) s[j][u] = -1e30f;
                }
        }

#pragma unroll
        for (int h = 0; h < 2; h++) {
            float mx = -1e30f;
#pragma unroll
            for (int j = 0; j < 8; j++) {
                mx = fmaxf(mx, s[j][2 * h + 0]);
                mx = fmaxf(mx, s[j][2 * h + 1]);
            }
            mx = fmaxf(mx, __shfl_xor_sync(0xffffffffu, mx, 1));
            mx = fmaxf(mx, __shfl_xor_sync(0xffffffffu, mx, 2));
            float mnew = fmaxf(m2[h], mx);
            float corr = ex2(m2[h] - mnew);
            m2[h] = mnew;
            float rs = 0.0f;
#pragma unroll
            for (int j = 0; j < 8; j++) {
                float p0 = ex2(s[j][2 * h + 0] - mnew);
                float p1 = ex2(s[j][2 * h + 1] - mnew);
                s[j][2 * h + 0] = p0;
                s[j][2 * h + 1] = p1;
                rs += p0 + p1;
            }
            lsum[h] = lsum[h] * corr + rs;
#pragma unroll
            for (int j = 0; j < 8; j++) {
                o[j][2 * h + 0] *= corr;
                o[j][2 * h + 1] *= corr;
            }
        }

        uint32_t pH[4][4], pL[4][4];
#pragma unroll
        for (int kk = 0; kk < 4; kk++) {
            int j = 2 * kk;
#pragma unroll
            for (int q = 0; q < 4; q++) {
                int jj = j + (q >> 1);
                float a = s[jj][(q & 1) * 2 + 0];
                float b = s[jj][(q & 1) * 2 + 1];
                uint32_t hi2 = pk_bf2(a, b);
                pH[kk][q] = hi2;
                pL[kk][q] = pk_bf2(a - bf_lo(hi2), b - bf_hi(hi2));
            }
        }

        {
            int vrow = (lane & 7) + 8 * ((lane >> 3) & 1);
            uint32_t vcol = (uint32_t)(16 * (lane >> 4));
#pragma unroll
            for (int kk = 0; kk < 4; kk++) {
                uint32_t vH[8][2], vL[8][2];
#pragma unroll
                for (int jj = 0; jj < 4; jj++) {
                    uint32_t off = (uint32_t)((kk * 16 + vrow) * ASTR) + (uint32_t)(jj * 32) + vcol;
                    ldsm_x4_t(&vH[2 * jj][0], sb + 2 * AMAT + off);
                    ldsm_x4_t(&vL[2 * jj][0], sb + 3 * AMAT + off);
                }
#pragma unroll
                for (int j = 0; j < 8; j++) mma_bf16(o[j], pH[kk], vH[j]);
#pragma unroll
                for (int j = 0; j < 8; j++) mma_bf16(o[j], pL[kk], vH[j]);
#pragma unroll
                for (int j = 0; j < 8; j++) mma_bf16(o[j], pH[kk], vL[j]);
            }
        }
    }

#pragma unroll
    for (int h = 0; h < 2; h++) {
        lsum[h] += __shfl_xor_sync(0xffffffffu, lsum[h], 1);
        lsum[h] += __shfl_xor_sync(0xffffffffu, lsum[h], 2);
        lsum[h] = 1.0f / lsum[h];
    }

    int b = bh >> 4, hh = bh & 15;
#pragma unroll
    for (int j = 0; j < 8; j++) {
        int dk = j * 8 + 2 * (lane & 3);
#pragma unroll
        for (int h = 0; h < 2; h++) {
            int srow = qb + w * 16 + r0 + 8 * h;
            float f0 = o[j][2 * h + 0] * lsum[h];
            float f1 = o[j][2 * h + 1] * lsum[h];
            __nv_bfloat16 h0 = __float2bfloat16(f0);
            __nv_bfloat16 h1 = __float2bfloat16(f1);
            __nv_bfloat16 l0 = __float2bfloat16(f0 - __bfloat162float(h0));
            __nv_bfloat16 l1 = __float2bfloat16(f1 - __bfloat162float(h1));
            size_t off = ((size_t)(b * SS + srow) * DD + hh * 64 + dk) >> 1;
            ((__nv_bfloat162*)g_Ahi)[off] = __nv_bfloat162(h0, h1);
            ((__nv_bfloat162*)g_Alo)[off] = __nv_bfloat162(l0, l1);
        }
    }
}

// ---------------------------------------------------------------------------
// Output projection GEMM: Y = attn @ Wo^T + X
// ---------------------------------------------------------------------------
__global__ __launch_bounds__(128, 2) void oproj_mma(const float* __restrict__ X) {
    extern __shared__ char dyn[];
    float acc[4][8][4];

    int m0 = blockIdx.y * 128;
    int n0 = blockIdx.x * 128;

    mma_gemm(g_Ahi + (size_t)m0 * 1024, g_Alo + (size_t)m0 * 1024,
             g_Woh + (size_t)n0 * 1024, g_Wol + (size_t)n0 * 1024,
             dyn, acc);

    int t = threadIdx.x, lane = t & 31, wid = t >> 5;
    int wm = wid & 1, wn = wid >> 1;
#pragma unroll
    for (int tm = 0; tm < 4; tm++)
#pragma unroll
        for (int tn = 0; tn < 8; tn++) {
            int c = n0 + wn * 64 + tn * 8 + (lane & 3) * 2;
#pragma unroll
            for (int half = 0; half < 2; half++) {
                int m = m0 + wm * 64 + tm * 16 + (lane >> 2) + 8 * half;
                float2 xr = *(const float2*)&X[(size_t)m * 1024 + c];
                float2 v;
                v.x = acc[tm][tn][2 * half + 0] + xr.x;
                v.y = acc[tm][tn][2 * half + 1] + xr.y;
                *(float2*)&g_Y[(size_t)m * 1024 + c] = v;
            }
        }
}

// ---------------------------------------------------------------------------
// LayerNorm over D=1024 per row
// ---------------------------------------------------------------------------
__global__ void ln_kernel(const float* __restrict__ gamma,
                          const float* __restrict__ beta,
                          float* __restrict__ out)
{
    int row = blockIdx.x;
    int t   = threadIdx.x;
    const float* y = g_Y + (size_t)row * 1024;

    float x[4];
    float s = 0.0f;
#pragma unroll
    for (int u = 0; u < 4; u++) { x[u] = y[t + 256 * u]; s += x[u]; }

    __shared__ float red[32];
#pragma unroll
    for (int off = 16; off; off >>= 1) s += __shfl_xor_sync(0xffffffffu, s, off);
    if ((t & 31) == 0) red[t >> 5] = s;
    __syncthreads();
    if (t == 0) {
        float tot = 0.0f;
        for (int w = 0; w < 8; w++) tot += red[w];
        red[8] = tot;
    }
    __syncthreads();
    float mean = red[8] * (1.0f / 1024.0f);

    float vs = 0.0f;
#pragma unroll
    for (int u = 0; u < 4; u++) { float d = x[u] - mean; vs += d * d; }
#pragma unroll
    for (int off = 16; off; off >>= 1) vs += __shfl_xor_sync(0xffffffffu, vs, off);
    if ((t & 31) == 0) red[16 + (t >> 5)] = vs;
    __syncthreads();
    if (t == 0) {
        float tot = 0.0f;
        for (int w = 0; w < 8; w++) tot += red[16 + w];
        red[24] = tot;
    }
    __syncthreads();
    float var  = red[24] * (1.0f / 1024.0f);
    float rstd = rsqrtf(var + 1e-5f);

#pragma unroll
    for (int u = 0; u < 4; u++) {
        int c = t + 256 * u;
        out[(size_t)row * 1024 + c] = (x[u] - mean) * rstd * gamma[c] + beta[c];
    }
}

// ---------------------------------------------------------------------------
extern "C" void kernel_launch(void* const* d_in, const int* in_sizes, int n_in,
                              void* d_out, int out_size)
{
    const float* X     = (const float*)d_in[0];
    const float* Wq    = (const float*)d_in[1];
    const float* Wk    = (const float*)d_in[2];
    const float* Wv    = (const float*)d_in[3];
    const float* Wo    = (const float*)d_in[4];
    const float* alpha = (const float*)d_in[5];
    const float* lns   = (const float*)d_in[6];
    const float* lnb   = (const float*)d_in[7];
    float* out = (float*)d_out;

    static int attr_set = 0;
    if (!attr_set) {
        cudaFuncSetAttribute(qkv_mma,   cudaFuncAttributeMaxDynamicSharedMemorySize, DYN_SMEM);
        cudaFuncSetAttribute(oproj_mma, cudaFuncAttributeMaxDynamicSharedMemorySize, DYN_SMEM);
        attr_set = 1;
    }

    pe_kernel<<<(SS * DKK + 255) / 256, 256>>>();                 // 1
    convx_kernel<<<4096, 256>>>(X);                                // 2
    convw_kernel<<<4096, 256>>>(Wq, Wk, Wv, Wo);                   // 3
    qkv_mma<<<dim3(8, 32, 3), 128, DYN_SMEM>>>();                  // 4
    smear_kernel<<<(MM * DD) / 256, 256>>>(alpha);                 // 5
    attn_mma<<<dim3(32, 32), 128>>>();                             // 6
    oproj_mma<<<dim3(8, 32), 128, DYN_SMEM>>>(X);                  // 7
    ln_kernel<<<MM, 256>>>(lns, lnb, out);                         // 8
}

// round 10
// speedup vs baseline: 1.5405x; 1.4117x over previous
#include <cuda_runtime.h>
#include <cuda_fp16.h>
#include <math.h>
#include <stdint.h>

#define BB  2
#define SS  2048
#define DD  1024
#define HH  16
#define DKK 64
#define MM  (BB*SS)   // 4096 rows

// scale folded into Q: 1/sqrt(64) * log2(e)
#define SC2 0.18033688011112042f

// ---------------------------------------------------------------------------
// Scratch (allocation-free rule: __device__ globals)
// ---------------------------------------------------------------------------
__device__ __align__(16) float g_PE[SS*DKK];
__device__ __align__(16) float g_Kraw[MM*DD];
__device__ __align__(16) float g_Y[MM*DD];

__device__ __align__(16) __half g_Xhi[MM*DD];
__device__ __align__(16) __half g_Xlo[MM*DD];
__device__ __align__(16) __half g_Wh[3*DD*DD];     // hi only (B-side)
__device__ __align__(16) __half g_Woh[DD*DD];      // hi only
__device__ __align__(16) __half g_Ahi[MM*DD];
__device__ __align__(16) __half g_Alo[MM*DD];

// attention operands, head-split [B*H][S][64]
__device__ __align__(16) __half g_Qhi[MM*DD];
__device__ __align__(16) __half g_Qlo[MM*DD];
__device__ __align__(16) __half g_Khi[MM*DD];      // hi only
__device__ __align__(16) __half g_Vhi[MM*DD];      // hi only

// ---------------------------------------------------------------------------
// PTX helpers (baseline sm_103-safe)
// ---------------------------------------------------------------------------
__device__ __forceinline__ uint32_t smem_u32(const void* p) {
    uint32_t a;
    asm("{ .reg .u64 t; cvta.to.shared.u64 t, %1; cvt.u32.u64 %0, t; }"
        : "=r"(a) : "l"(p));
    return a;
}

#define CPA16(dst, src) \
    asm volatile("cp.async.cg.shared.global [%0], [%1], 16;" :: "r"(dst), "l"(src) : "memory")
#define CPA_COMMIT() asm volatile("cp.async.commit_group;" ::: "memory")
#define CPA_WAIT1()  asm volatile("cp.async.wait_group 1;" ::: "memory")
#define CPA_WAIT0()  asm volatile("cp.async.wait_group 0;" ::: "memory")

__device__ __forceinline__ void ldsm_x4(uint32_t* r, uint32_t addr) {
    asm volatile("ldmatrix.sync.aligned.m8n8.x4.shared.b16 {%0,%1,%2,%3}, [%4];"
                 : "=r"(r[0]), "=r"(r[1]), "=r"(r[2]), "=r"(r[3]) : "r"(addr));
}
__device__ __forceinline__ void ldsm_x4_t(uint32_t* r, uint32_t addr) {
    asm volatile("ldmatrix.sync.aligned.m8n8.x4.trans.shared.b16 {%0,%1,%2,%3}, [%4];"
                 : "=r"(r[0]), "=r"(r[1]), "=r"(r[2]), "=r"(r[3]) : "r"(addr));
}

__device__ __forceinline__ void mma_f16(float* c, const uint32_t* a, const uint32_t* b) {
    asm volatile(
        "mma.sync.aligned.m16n8k16.row.col.f32.f16.f16.f32 "
        "{%0,%1,%2,%3}, {%4,%5,%6,%7}, {%8,%9}, {%0,%1,%2,%3};"
        : "+f"(c[0]), "+f"(c[1]), "+f"(c[2]), "+f"(c[3])
        : "r"(a[0]), "r"(a[1]), "r"(a[2]), "r"(a[3]), "r"(b[0]), "r"(b[1]));
}

__device__ __forceinline__ float ex2(float x) {
    float r;
    asm("ex2.approx.ftz.f32 %0, %1;" : "=f"(r) : "f"(x));
    return r;
}

// ---------------------------------------------------------------------------
__global__ void pe_kernel() {
    int idx = blockIdx.x * blockDim.x + threadIdx.x;
    if (idx >= SS * DKK) return;
    int s  = idx >> 6;
    int dk = idx & 63;
    int i  = dk >> 1;
    float freq = expf(-((float)(2 * i) / 64.0f) * 9.210340371976184f);
    float ang  = (float)s * freq;
    g_PE[idx]  = (dk & 1) ? cosf(ang) : sinf(ang);
}

// ---------------------------------------------------------------------------
// fp32 -> fp16 hi(/lo) conversions
// ---------------------------------------------------------------------------
__global__ void convx_kernel(const float* __restrict__ src) {
    int i = blockIdx.x * blockDim.x + threadIdx.x;   // MM*DD/4
    float4 v = ((const float4*)src)[i];
    __half h0 = __float2half_rn(v.x);
    __half h1 = __float2half_rn(v.y);
    __half h2 = __float2half_rn(v.z);
    __half h3 = __float2half_rn(v.w);
    __half l0 = __float2half_rn(v.x - __half2float(h0));
    __half l1 = __float2half_rn(v.y - __half2float(h1));
    __half l2 = __float2half_rn(v.z - __half2float(h2));
    __half l3 = __float2half_rn(v.w - __half2float(h3));
    __half2* hp = (__half2*)g_Xhi;
    __half2* lp = (__half2*)g_Xlo;
    hp[2*i]   = __halves2half2(h0, h1);
    hp[2*i+1] = __halves2half2(h2, h3);
    lp[2*i]   = __halves2half2(l0, l1);
    lp[2*i+1] = __halves2half2(l2, l3);
}

// hi-only conversion for all 4 weight matrices
__global__ void convw_kernel(const float* __restrict__ Wq, const float* __restrict__ Wk,
                             const float* __restrict__ Wv, const float* __restrict__ Wo) {
    int gi  = blockIdx.x * blockDim.x + threadIdx.x;  // 4 * DD*DD/4
    int mat = gi >> 18;
    int i   = gi & 0x3FFFF;
    const float* src = (mat == 0) ? Wq : (mat == 1) ? Wk : (mat == 2) ? Wv : Wo;
    __half2* hp = (mat < 3) ? (__half2*)(g_Wh + (size_t)mat * DD * DD)
                            : (__half2*)g_Woh;
    float4 v = ((const float4*)src)[i];
    hp[2*i]   = __floats2half2_rn(v.x, v.y);
    hp[2*i+1] = __floats2half2_rn(v.z, v.w);
}

// ---------------------------------------------------------------------------
// fp16x2 HMMA GEMM mainloop: 128 threads, 64x64 warp tiles (2x2 warp grid),
// 3-stage cp.async pipeline, swizzled 64B rows. 3 smem mats: Ah, Al, Bh.
// C = Ah*Bh + Al*Bh (= A*Bh; B truncation error ~2^-12 rel)
// ---------------------------------------------------------------------------
#define MATB 8192            // 128 * 64
#define STG  (3 * MATB)      // 24576
#define DYN_SMEM (3 * STG)   // 73728

__device__ __forceinline__ void mma_gemm(
    const __half* __restrict__ Ah, const __half* __restrict__ Al,
    const __half* __restrict__ Bh,
    char* dyn, float acc[4][8][4])
{
    int t    = threadIdx.x;
    int lane = t & 31;
    int wid  = t >> 5;
    int wm   = wid & 1;       // warp row (64 rows)
    int wn   = wid >> 1;      // warp col (64 cols)
    uint32_t sbase = smem_u32(dyn);

    const char* mats[3] = {(const char*)Ah, (const char*)Al, (const char*)Bh};

#pragma unroll
    for (int tm = 0; tm < 4; tm++)
#pragma unroll
        for (int tn = 0; tn < 8; tn++)
#pragma unroll
            for (int u = 0; u < 4; u++) acc[tm][tn][u] = 0.0f;

    // copy: 1536 16B-chunks per stage, 12 per thread
    int idx0 = t * 12;
    auto load_stage = [&](int st, int kb) {
        uint32_t stb = sbase + st * STG;
#pragma unroll
        for (int q = 0; q < 12; q++) {
            int idx = idx0 + q;
            int mat = idx >> 9;
            int r   = (idx >> 2) & 127;
            int c   = idx & 3;
            uint32_t dst = stb + mat * MATB + r * 64 + ((c ^ ((r >> 1) & 3)) << 4);
            const char* src = mats[mat] + ((size_t)r * 1024 + kb + c * 8) * 2;
            CPA16(dst, src);
        }
        CPA_COMMIT();
    };

    int a_hi = lane >> 4;
    int b_hi = (lane >> 3) & 1;
    uint32_t aOff[4]; int aMsk[4];
#pragma unroll
    for (int tm = 0; tm < 4; tm++) {
        int r = wm * 64 + (lane & 15) + 16 * tm;
        aOff[tm] = (uint32_t)(r * 64);
        aMsk[tm] = (r >> 1) & 3;
    }
    uint32_t bOff[4]; int bMsk[4];
#pragma unroll
    for (int tp = 0; tp < 4; tp++) {
        int r = wn * 64 + (lane & 7) + 8 * (lane >> 4) + 16 * tp;
        bOff[tp] = (uint32_t)(r * 64);
        bMsk[tp] = (r >> 1) & 3;
    }

    load_stage(0, 0);
    load_stage(1, 32);

    int st = 0;
    for (int it = 0; it < 32; it++) {
        if (it < 31) { CPA_WAIT1(); } else { CPA_WAIT0(); }
        __syncthreads();
        if (it + 2 < 32) {
            int s2 = st + 2; if (s2 >= 3) s2 -= 3;
            load_stage(s2, (it + 2) * 32);
        }

        uint32_t stb = sbase + st * STG;
#pragma unroll
        for (int ks = 0; ks < 2; ks++) {
            int cA = 2 * ks + a_hi;
            int cB = 2 * ks + b_hi;
            uint32_t aH[4][4], aL[4][4], bH[8][2];
#pragma unroll
            for (int tm = 0; tm < 4; tm++) {
                uint32_t off = aOff[tm] + (uint32_t)((cA ^ aMsk[tm]) << 4);
                ldsm_x4(aH[tm], stb + 0 * MATB + off);
                ldsm_x4(aL[tm], stb + 1 * MATB + off);
            }
#pragma unroll
            for (int tp = 0; tp < 4; tp++) {
                uint32_t off = bOff[tp] + (uint32_t)((cB ^ bMsk[tp]) << 4);
                ldsm_x4(&bH[2 * tp][0], stb + 2 * MATB + off);
            }
            // pass 1: Ah*Bh — 32 independent accumulators
#pragma unroll
            for (int tm = 0; tm < 4; tm++)
#pragma unroll
                for (int tn = 0; tn < 8; tn++)
                    mma_f16(acc[tm][tn], aH[tm], bH[tn]);
            // pass 2: Al*Bh
#pragma unroll
            for (int tm = 0; tm < 4; tm++)
#pragma unroll
                for (int tn = 0; tn < 8; tn++)
                    mma_f16(acc[tm][tn], aL[tm], bH[tn]);
        }
        st++; if (st == 3) st = 0;
    }
    __syncthreads();
}

// ---------------------------------------------------------------------------
// QKV GEMM. z=0: Q -> (acc+PE)*SC2 split fp16; z=1: K fp32; z=2: V fp16 hi
// ---------------------------------------------------------------------------
__global__ __launch_bounds__(128, 2) void qkv_mma() {
    extern __shared__ char dyn[];
    float acc[4][8][4];

    int z  = blockIdx.z;
    int m0 = blockIdx.y * 128;
    int n0 = blockIdx.x * 128;

    mma_gemm(g_Xhi + (size_t)m0 * 1024, g_Xlo + (size_t)m0 * 1024,
             g_Wh + (size_t)z * DD * DD + (size_t)n0 * 1024,
             dyn, acc);

    int t = threadIdx.x, lane = t & 31, wid = t >> 5;
    int wm = wid & 1, wn = wid >> 1;

#pragma unroll
    for (int tm = 0; tm < 4; tm++)
#pragma unroll
        for (int tn = 0; tn < 8; tn++) {
            int c  = n0 + wn * 64 + tn * 8 + (lane & 3) * 2;
            int h  = c >> 6, dk = c & 63;
#pragma unroll
            for (int half = 0; half < 2; half++) {
                int m = m0 + wm * 64 + tm * 16 + (lane >> 2) + 8 * half;
                int b = m >> 11, s = m & 2047;
                float vx = acc[tm][tn][2 * half + 0];
                float vy = acc[tm][tn][2 * half + 1];
                size_t off = ((size_t)((b * 16 + h) * 2048 + s)) * 64 + dk;
                if (z == 1) {
                    float2 v; v.x = vx; v.y = vy;
                    *(float2*)&g_Kraw[off] = v;
                } else if (z == 2) {
                    ((__half2*)g_Vhi)[off >> 1] = __floats2half2_rn(vx, vy);
                } else {
                    float2 pe = *(const float2*)&g_PE[s * 64 + dk];
                    vx = (vx + pe.x) * SC2;
                    vy = (vy + pe.y) * SC2;
                    __half hx = __float2half_rn(vx);
                    __half hy = __float2half_rn(vy);
                    __half lx = __float2half_rn(vx - __half2float(hx));
                    __half ly = __float2half_rn(vy - __half2float(hy));
                    ((__half2*)g_Qhi)[off >> 1] = __halves2half2(hx, hy);
                    ((__half2*)g_Qlo)[off >> 1] = __halves2half2(lx, ly);
                }
            }
        }
}

// ---------------------------------------------------------------------------
// EMA smear on K + PE add, output fp16 hi only
// ---------------------------------------------------------------------------
__global__ void smear_kernel(const float* __restrict__ alpha) {
    int idx = blockIdx.x * blockDim.x + threadIdx.x;
    int dk = idx & 63;
    int s  = (idx >> 6) & 2047;
    int h  = (idx >> 17) & 15;
    float kc = g_Kraw[idx];
    float v;
    if (s == 0) {
        v = kc;
    } else {
        float a = 1.0f / (1.0f + expf(-alpha[h * 2047 + (s - 1)]));
        v = a * kc + (1.0f - a) * g_Kraw[idx - 64];
    }
    v += g_PE[s * 64 + dk];
    g_Khi[idx] = __float2half_rn(v);
}

// ---------------------------------------------------------------------------
// Causal flash attention, fp16x2 HMMA.
// QK^T = Qh*Kh + Ql*Kh ; O += Ph*Vh + Pl*Vh.  Smem: 2 mats (K, V).
// ---------------------------------------------------------------------------
#define ASTR 144
#define AMAT (64 * ASTR)   // 9216

__global__ __launch_bounds__(128, 4) void attn_mma() {
    __shared__ __align__(16) char sm[2 * AMAT];
    uint32_t sb = smem_u32(sm);

    int t = threadIdx.x, lane = t & 31, w = t >> 5;
    int qt = 31 - (int)blockIdx.x;          // heavy tiles first
    int qb = qt * 64;
    int bh = blockIdx.y;
    size_t base = (size_t)bh * SS * DKK;

    // ---- stage Q tile (hi -> mat0, lo -> mat1), extract A-frags ----
    {
        const char* qsrc[2] = {(const char*)(g_Qhi + base), (const char*)(g_Qlo + base)};
#pragma unroll
        for (int q = 0; q < 8; q++) {
            int idx = t * 8 + q;
            int mat = idx >> 9;
            int r   = (idx >> 3) & 63;
            int c   = idx & 7;
            CPA16(sb + mat * AMAT + r * ASTR + c * 16,
                  qsrc[mat] + ((size_t)(qb + r) * 64 + c * 8) * 2);
        }
        CPA_COMMIT(); CPA_WAIT0();
        __syncthreads();
    }

    uint32_t qh[4][4], ql[4][4];
    {
        int ar = w * 16 + (lane & 15);
#pragma unroll
        for (int k = 0; k < 4; k++) {
            uint32_t acol = (uint32_t)(k * 32 + (lane >> 4) * 16);
            ldsm_x4(qh[k], sb + 0 * AMAT + ar * ASTR + acol);
            ldsm_x4(ql[k], sb + 1 * AMAT + ar * ASTR + acol);
        }
    }

    float o[8][4];
    float m2[2], lsum[2];
#pragma unroll
    for (int j = 0; j < 8; j++)
#pragma unroll
        for (int u = 0; u < 4; u++) o[j][u] = 0.0f;
    m2[0] = m2[1] = -1e30f;
    lsum[0] = lsum[1] = 0.0f;

    const char* kvsrc[2] = {(const char*)(g_Khi + base), (const char*)(g_Vhi + base)};

    int r0 = (lane >> 2);
    int ntiles = qt + 1;

    for (int tile = 0; tile < ntiles; tile++) {
        int kb = tile * 64;
        __syncthreads();
#pragma unroll
        for (int q = 0; q < 8; q++) {
            int idx = t * 8 + q;
            int mat = idx >> 9;          // 0 = K, 1 = V
            int r   = (idx >> 3) & 63;
            int c   = idx & 7;
            CPA16(sb + mat * AMAT + r * ASTR + c * 16,
                  kvsrc[mat] + ((size_t)(kb + r) * 64 + c * 8) * 2);
        }
        CPA_COMMIT(); CPA_WAIT0();
        __syncthreads();

        // ---- S = Q K^T (fp16x2) ----
        float s[8][4];
#pragma unroll
        for (int j = 0; j < 8; j++)
#pragma unroll
            for (int u = 0; u < 4; u++) s[j][u] = 0.0f;

        {
            int b_row = (lane & 7) + 8 * (lane >> 4);
#pragma unroll
            for (int k = 0; k < 4; k++) {
                uint32_t bcol = (uint32_t)((k * 16 + 8 * ((lane >> 3) & 1)) * 2);
                uint32_t kH[8][2];
#pragma unroll
                for (int tp = 0; tp < 4; tp++) {
                    uint32_t off = (uint32_t)((b_row + 16 * tp) * ASTR) + bcol;
                    ldsm_x4(&kH[2 * tp][0], sb + 0 * AMAT + off);
                }
#pragma unroll
                for (int j = 0; j < 8; j++) mma_f16(s[j], qh[k], kH[j]);
#pragma unroll
                for (int j = 0; j < 8; j++) mma_f16(s[j], ql[k], kH[j]);
            }
        }

        // ---- mask (diagonal tile) ----
        if (tile == ntiles - 1) {
#pragma unroll
            for (int j = 0; j < 8; j++)
#pragma unroll
                for (int u = 0; u < 4; u++) {
                    int row = (w * 16) + r0 + 8 * (u >> 1);
                    int col = j * 8 + 2 * (lane & 3) + (u & 1);
                    if (col > row) s[j][u] = -1e30f;
                }
        }

        // ---- online softmax (base 2), per row half ----
#pragma unroll
        for (int h = 0; h < 2; h++) {
            float mx = -1e30f;
#pragma unroll
            for (int j = 0; j < 8; j++) {
                mx = fmaxf(mx, s[j][2 * h + 0]);
                mx = fmaxf(mx, s[j][2 * h + 1]);
            }
            mx = fmaxf(mx, __shfl_xor_sync(0xffffffffu, mx, 1));
            mx = fmaxf(mx, __shfl_xor_sync(0xffffffffu, mx, 2));
            float mnew = fmaxf(m2[h], mx);
            float corr = ex2(m2[h] - mnew);
            m2[h] = mnew;
            float rs = 0.0f;
#pragma unroll
            for (int j = 0; j < 8; j++) {
                float p0 = ex2(s[j][2 * h + 0] - mnew);
                float p1 = ex2(s[j][2 * h + 1] - mnew);
                s[j][2 * h + 0] = p0;
                s[j][2 * h + 1] = p1;
                rs += p0 + p1;
            }
            lsum[h] = lsum[h] * corr + rs;
#pragma unroll
            for (int j = 0; j < 8; j++) {
                o[j][2 * h + 0] *= corr;
                o[j][2 * h + 1] *= corr;
            }
        }

        // ---- P fragments (C->A remap, fp16 hi/lo split in registers) ----
        uint32_t pH[4][4], pL[4][4];
#pragma unroll
        for (int kk = 0; kk < 4; kk++) {
            int j = 2 * kk;
#pragma unroll
            for (int q = 0; q < 4; q++) {
                int jj = j + (q >> 1);
                float a = s[jj][(q & 1) * 2 + 0];
                float b = s[jj][(q & 1) * 2 + 1];
                __half2 hp = __floats2half2_rn(a, b);
                float la = a - __half2float(__low2half(hp));
                float lb = b - __half2float(__high2half(hp));
                __half2 lp = __floats2half2_rn(la, lb);
                pH[kk][q] = *(uint32_t*)&hp;
                pL[kk][q] = *(uint32_t*)&lp;
            }
        }

        // ---- O += P V (fp16x2), V via ldmatrix.trans (mat 1) ----
        {
            int vrow = (lane & 7) + 8 * ((lane >> 3) & 1);
            uint32_t vcol = (uint32_t)(16 * (lane >> 4));
#pragma unroll
            for (int kk = 0; kk < 4; kk++) {
                uint32_t vH[8][2];
#pragma unroll
                for (int jj = 0; jj < 4; jj++) {
                    uint32_t off = (uint32_t)((kk * 16 + vrow) * ASTR) + (uint32_t)(jj * 32) + vcol;
                    ldsm_x4_t(&vH[2 * jj][0], sb + 1 * AMAT + off);
                }
#pragma unroll
                for (int j = 0; j < 8; j++) mma_f16(o[j], pH[kk], vH[j]);
#pragma unroll
                for (int j = 0; j < 8; j++) mma_f16(o[j], pL[kk], vH[j]);
            }
        }
    }

    // ---- epilogue: normalize, split fp16 hi/lo, store ----
#pragma unroll
    for (int h = 0; h < 2; h++) {
        lsum[h] += __shfl_xor_sync(0xffffffffu, lsum[h], 1);
        lsum[h] += __shfl_xor_sync(0xffffffffu, lsum[h], 2);
        lsum[h] = 1.0f / lsum[h];
    }

    int b = bh >> 4, hh = bh & 15;
#pragma unroll
    for (int j = 0; j < 8; j++) {
        int dk = j * 8 + 2 * (lane & 3);
#pragma unroll
        for (int h = 0; h < 2; h++) {
            int srow = qb + w * 16 + r0 + 8 * h;
            float f0 = o[j][2 * h + 0] * lsum[h];
            float f1 = o[j][2 * h + 1] * lsum[h];
            __half h0 = __float2half_rn(f0);
            __half h1 = __float2half_rn(f1);
            __half l0 = __float2half_rn(f0 - __half2float(h0));
            __half l1 = __float2half_rn(f1 - __half2float(h1));
            size_t off = ((size_t)(b * SS + srow) * DD + hh * 64 + dk) >> 1;
            ((__half2*)g_Ahi)[off] = __halves2half2(h0, h1);
            ((__half2*)g_Alo)[off] = __halves2half2(l0, l1);
        }
    }
}

// ---------------------------------------------------------------------------
// Output projection GEMM: Y = attn @ Wo^T + X
// ---------------------------------------------------------------------------
__global__ __launch_bounds__(128, 2) void oproj_mma(const float* __restrict__ X) {
    extern __shared__ char dyn[];
    float acc[4][8][4];

    int m0 = blockIdx.y * 128;
    int n0 = blockIdx.x * 128;

    mma_gemm(g_Ahi + (size_t)m0 * 1024, g_Alo + (size_t)m0 * 1024,
             g_Woh + (size_t)n0 * 1024, dyn, acc);

    int t = threadIdx.x, lane = t & 31, wid = t >> 5;
    int wm = wid & 1, wn = wid >> 1;
#pragma unroll
    for (int tm = 0; tm < 4; tm++)
#pragma unroll
        for (int tn = 0; tn < 8; tn++) {
            int c = n0 + wn * 64 + tn * 8 + (lane & 3) * 2;
#pragma unroll
            for (int half = 0; half < 2; half++) {
                int m = m0 + wm * 64 + tm * 16 + (lane >> 2) + 8 * half;
                float2 xr = *(const float2*)&X[(size_t)m * 1024 + c];
                float2 v;
                v.x = acc[tm][tn][2 * half + 0] + xr.x;
                v.y = acc[tm][tn][2 * half + 1] + xr.y;
                *(float2*)&g_Y[(size_t)m * 1024 + c] = v;
            }
        }
}

// ---------------------------------------------------------------------------
// LayerNorm over D=1024 per row
// ---------------------------------------------------------------------------
__global__ void ln_kernel(const float* __restrict__ gamma,
                          const float* __restrict__ beta,
                          float* __restrict__ out)
{
    int row = blockIdx.x;
    int t   = threadIdx.x;
    const float* y = g_Y + (size_t)row * 1024;

    float x[4];
    float s = 0.0f;
#pragma unroll
    for (int u = 0; u < 4; u++) { x[u] = y[t + 256 * u]; s += x[u]; }

    __shared__ float red[32];
#pragma unroll
    for (int off = 16; off; off >>= 1) s += __shfl_xor_sync(0xffffffffu, s, off);
    if ((t & 31) == 0) red[t >> 5] = s;
    __syncthreads();
    if (t == 0) {
        float tot = 0.0f;
        for (int w = 0; w < 8; w++) tot += red[w];
        red[8] = tot;
    }
    __syncthreads();
    float mean = red[8] * (1.0f / 1024.0f);

    float vs = 0.0f;
#pragma unroll
    for (int u = 0; u < 4; u++) { float d = x[u] - mean; vs += d * d; }
#pragma unroll
    for (int off = 16; off; off >>= 1) vs += __shfl_xor_sync(0xffffffffu, vs, off);
    if ((t & 31) == 0) red[16 + (t >> 5)] = vs;
    __syncthreads();
    if (t == 0) {
        float tot = 0.0f;
        for (int w = 0; w < 8; w++) tot += red[16 + w];
        red[24] = tot;
    }
    __syncthreads();
    float var  = red[24] * (1.0f / 1024.0f);
    float rstd = rsqrtf(var + 1e-5f);

#pragma unroll
    for (int u = 0; u < 4; u++) {
        int c = t + 256 * u;
        out[(size_t)row * 1024 + c] = (x[u] - mean) * rstd * gamma[c] + beta[c];
    }
}

// ---------------------------------------------------------------------------
extern "C" void kernel_launch(void* const* d_in, const int* in_sizes, int n_in,
                              void* d_out, int out_size)
{
    const float* X     = (const float*)d_in[0];
    const float* Wq    = (const float*)d_in[1];
    const float* Wk    = (const float*)d_in[2];
    const float* Wv    = (const float*)d_in[3];
    const float* Wo    = (const float*)d_in[4];
    const float* alpha = (const float*)d_in[5];
    const float* lns   = (const float*)d_in[6];
    const float* lnb   = (const float*)d_in[7];
    float* out = (float*)d_out;

    static int attr_set = 0;
    if (!attr_set) {
        cudaFuncSetAttribute(qkv_mma,   cudaFuncAttributeMaxDynamicSharedMemorySize, DYN_SMEM);
        cudaFuncSetAttribute(oproj_mma, cudaFuncAttributeMaxDynamicSharedMemorySize, DYN_SMEM);
        attr_set = 1;
    }

    pe_kernel<<<(SS * DKK + 255) / 256, 256>>>();                 // 1
    convx_kernel<<<4096, 256>>>(X);                                // 2
    convw_kernel<<<4096, 256>>>(Wq, Wk, Wv, Wo);                   // 3
    qkv_mma<<<dim3(8, 32, 3), 128, DYN_SMEM>>>();                  // 4
    smear_kernel<<<(MM * DD) / 256, 256>>>(alpha);                 // 5
    attn_mma<<<dim3(32, 32), 128>>>();                             // 6
    oproj_mma<<<dim3(8, 32), 128, DYN_SMEM>>>(X);                  // 7
    ln_kernel<<<MM, 256>>>(lns, lnb, out);                         // 8
}

// round 11
// speedup vs baseline: 2.3900x; 1.5514x over previous
#include <cuda_runtime.h>
#include <cuda_fp16.h>
#include <math.h>
#include <stdint.h>

#define BB  2
#define SS  2048
#define DD  1024
#define HH  16
#define DKK 64
#define MM  (BB*SS)   // 4096 rows

// scale folded into Q: 1/sqrt(64) * log2(e)
#define SC2 0.18033688011112042f

// ---------------------------------------------------------------------------
// Scratch (allocation-free rule: __device__ globals)
// ---------------------------------------------------------------------------
__device__ __align__(16) float g_PE[SS*DKK];
__device__ __align__(16) float g_Kraw[MM*DD];
__device__ __align__(16) float g_Y[MM*DD];

__device__ __align__(16) __half g_Xh[MM*DD];
__device__ __align__(16) __half g_Wh[3*DD*DD];
__device__ __align__(16) __half g_Woh[DD*DD];
__device__ __align__(16) __half g_Ah[MM*DD];

// attention operands, head-split [B*H][S][64]
__device__ __align__(16) __half g_Qh[MM*DD];
__device__ __align__(16) __half g_Kh[MM*DD];
__device__ __align__(16) __half g_Vh[MM*DD];

// ---------------------------------------------------------------------------
// PTX helpers (baseline sm_103-safe)
// ---------------------------------------------------------------------------
__device__ __forceinline__ uint32_t smem_u32(const void* p) {
    uint32_t a;
    asm("{ .reg .u64 t; cvta.to.shared.u64 t, %1; cvt.u32.u64 %0, t; }"
        : "=r"(a) : "l"(p));
    return a;
}

#define CPA16(dst, src) \
    asm volatile("cp.async.cg.shared.global [%0], [%1], 16;" :: "r"(dst), "l"(src) : "memory")
#define CPA_COMMIT() asm volatile("cp.async.commit_group;" ::: "memory")
#define CPA_WAIT1()  asm volatile("cp.async.wait_group 1;" ::: "memory")
#define CPA_WAIT0()  asm volatile("cp.async.wait_group 0;" ::: "memory")

__device__ __forceinline__ void ldsm_x4(uint32_t* r, uint32_t addr) {
    asm volatile("ldmatrix.sync.aligned.m8n8.x4.shared.b16 {%0,%1,%2,%3}, [%4];"
                 : "=r"(r[0]), "=r"(r[1]), "=r"(r[2]), "=r"(r[3]) : "r"(addr));
}
__device__ __forceinline__ void ldsm_x4_t(uint32_t* r, uint32_t addr) {
    asm volatile("ldmatrix.sync.aligned.m8n8.x4.trans.shared.b16 {%0,%1,%2,%3}, [%4];"
                 : "=r"(r[0]), "=r"(r[1]), "=r"(r[2]), "=r"(r[3]) : "r"(addr));
}

__device__ __forceinline__ void mma_f16(float* c, const uint32_t* a, const uint32_t* b) {
    asm volatile(
        "mma.sync.aligned.m16n8k16.row.col.f32.f16.f16.f32 "
        "{%0,%1,%2,%3}, {%4,%5,%6,%7}, {%8,%9}, {%0,%1,%2,%3};"
        : "+f"(c[0]), "+f"(c[1]), "+f"(c[2]), "+f"(c[3])
        : "r"(a[0]), "r"(a[1]), "r"(a[2]), "r"(a[3]), "r"(b[0]), "r"(b[1]));
}

__device__ __forceinline__ float ex2(float x) {
    float r;
    asm("ex2.approx.ftz.f32 %0, %1;" : "=f"(r) : "f"(x));
    return r;
}

// ---------------------------------------------------------------------------
__global__ void pe_kernel() {
    int idx = blockIdx.x * blockDim.x + threadIdx.x;
    if (idx >= SS * DKK) return;
    int s  = idx >> 6;
    int dk = idx & 63;
    int i  = dk >> 1;
    float freq = expf(-((float)(2 * i) / 64.0f) * 9.210340371976184f);
    float ang  = (float)s * freq;
    g_PE[idx]  = (dk & 1) ? cosf(ang) : sinf(ang);
}

// ---------------------------------------------------------------------------
// fp32 -> fp16 conversions
// ---------------------------------------------------------------------------
__global__ void convx_kernel(const float* __restrict__ src) {
    int i = blockIdx.x * blockDim.x + threadIdx.x;   // MM*DD/4
    float4 v = ((const float4*)src)[i];
    __half2* hp = (__half2*)g_Xh;
    hp[2*i]   = __floats2half2_rn(v.x, v.y);
    hp[2*i+1] = __floats2half2_rn(v.z, v.w);
}

__global__ void convw_kernel(const float* __restrict__ Wq, const float* __restrict__ Wk,
                             const float* __restrict__ Wv, const float* __restrict__ Wo) {
    int gi  = blockIdx.x * blockDim.x + threadIdx.x;  // 4 * DD*DD/4
    int mat = gi >> 18;
    int i   = gi & 0x3FFFF;
    const float* src = (mat == 0) ? Wq : (mat == 1) ? Wk : (mat == 2) ? Wv : Wo;
    __half2* hp = (mat < 3) ? (__half2*)(g_Wh + (size_t)mat * DD * DD)
                            : (__half2*)g_Woh;
    float4 v = ((const float4*)src)[i];
    hp[2*i]   = __floats2half2_rn(v.x, v.y);
    hp[2*i+1] = __floats2half2_rn(v.z, v.w);
}

// ---------------------------------------------------------------------------
// fp16 single-pass HMMA GEMM: 128 threads, 64x64 warp tiles (2x2 warp grid),
// 3-stage cp.async pipeline, swizzled 64B rows. 2 smem mats: A, B.
// ---------------------------------------------------------------------------
#define MATB 8192            // 128 * 64
#define STG  (2 * MATB)      // 16384
#define DYN_SMEM (3 * STG)   // 49152

__device__ __forceinline__ void mma_gemm(
    const __half* __restrict__ A, const __half* __restrict__ B,
    char* dyn, float acc[4][8][4])
{
    int t    = threadIdx.x;
    int lane = t & 31;
    int wid  = t >> 5;
    int wm   = wid & 1;       // warp row (64 rows)
    int wn   = wid >> 1;      // warp col (64 cols)
    uint32_t sbase = smem_u32(dyn);

    const char* mats[2] = {(const char*)A, (const char*)B};

#pragma unroll
    for (int tm = 0; tm < 4; tm++)
#pragma unroll
        for (int tn = 0; tn < 8; tn++)
#pragma unroll
            for (int u = 0; u < 4; u++) acc[tm][tn][u] = 0.0f;

    // copy: 1024 16B-chunks per stage, 8 per thread
    int idx0 = t * 8;
    auto load_stage = [&](int st, int kb) {
        uint32_t stb = sbase + st * STG;
#pragma unroll
        for (int q = 0; q < 8; q++) {
            int idx = idx0 + q;
            int mat = idx >> 9;
            int r   = (idx >> 2) & 127;
            int c   = idx & 3;
            uint32_t dst = stb + mat * MATB + r * 64 + ((c ^ ((r >> 1) & 3)) << 4);
            const char* src = mats[mat] + ((size_t)r * 1024 + kb + c * 8) * 2;
            CPA16(dst, src);
        }
        CPA_COMMIT();
    };

    int a_hi = lane >> 4;
    int b_hi = (lane >> 3) & 1;
    uint32_t aOff[4]; int aMsk[4];
#pragma unroll
    for (int tm = 0; tm < 4; tm++) {
        int r = wm * 64 + (lane & 15) + 16 * tm;
        aOff[tm] = (uint32_t)(r * 64);
        aMsk[tm] = (r >> 1) & 3;
    }
    uint32_t bOff[4]; int bMsk[4];
#pragma unroll
    for (int tp = 0; tp < 4; tp++) {
        int r = wn * 64 + (lane & 7) + 8 * (lane >> 4) + 16 * tp;
        bOff[tp] = (uint32_t)(r * 64);
        bMsk[tp] = (r >> 1) & 3;
    }

    load_stage(0, 0);
    load_stage(1, 32);

    int st = 0;
    for (int it = 0; it < 32; it++) {
        if (it < 31) { CPA_WAIT1(); } else { CPA_WAIT0(); }
        __syncthreads();
        if (it + 2 < 32) {
            int s2 = st + 2; if (s2 >= 3) s2 -= 3;
            load_stage(s2, (it + 2) * 32);
        }

        uint32_t stb = sbase + st * STG;
#pragma unroll
        for (int ks = 0; ks < 2; ks++) {
            int cA = 2 * ks + a_hi;
            int cB = 2 * ks + b_hi;
            uint32_t aF[4][4], bF[8][2];
#pragma unroll
            for (int tm = 0; tm < 4; tm++) {
                uint32_t off = aOff[tm] + (uint32_t)((cA ^ aMsk[tm]) << 4);
                ldsm_x4(aF[tm], stb + 0 * MATB + off);
            }
#pragma unroll
            for (int tp = 0; tp < 4; tp++) {
                uint32_t off = bOff[tp] + (uint32_t)((cB ^ bMsk[tp]) << 4);
                ldsm_x4(&bF[2 * tp][0], stb + 1 * MATB + off);
            }
#pragma unroll
            for (int tm = 0; tm < 4; tm++)
#pragma unroll
                for (int tn = 0; tn < 8; tn++)
                    mma_f16(acc[tm][tn], aF[tm], bF[tn]);
        }
        st++; if (st == 3) st = 0;
    }
    __syncthreads();
}

// ---------------------------------------------------------------------------
// QKV GEMM. z=0: Q -> (acc+PE)*SC2 fp16; z=1: K fp32; z=2: V fp16
// ---------------------------------------------------------------------------
__global__ __launch_bounds__(128, 2) void qkv_mma() {
    extern __shared__ char dyn[];
    float acc[4][8][4];

    int z  = blockIdx.z;
    int m0 = blockIdx.y * 128;
    int n0 = blockIdx.x * 128;

    mma_gemm(g_Xh + (size_t)m0 * 1024,
             g_Wh + (size_t)z * DD * DD + (size_t)n0 * 1024,
             dyn, acc);

    int t = threadIdx.x, lane = t & 31, wid = t >> 5;
    int wm = wid & 1, wn = wid >> 1;

#pragma unroll
    for (int tm = 0; tm < 4; tm++)
#pragma unroll
        for (int tn = 0; tn < 8; tn++) {
            int c  = n0 + wn * 64 + tn * 8 + (lane & 3) * 2;
            int h  = c >> 6, dk = c & 63;
#pragma unroll
            for (int half = 0; half < 2; half++) {
                int m = m0 + wm * 64 + tm * 16 + (lane >> 2) + 8 * half;
                int b = m >> 11, s = m & 2047;
                float vx = acc[tm][tn][2 * half + 0];
                float vy = acc[tm][tn][2 * half + 1];
                size_t off = ((size_t)((b * 16 + h) * 2048 + s)) * 64 + dk;
                if (z == 1) {
                    float2 v; v.x = vx; v.y = vy;
                    *(float2*)&g_Kraw[off] = v;
                } else if (z == 2) {
                    ((__half2*)g_Vh)[off >> 1] = __floats2half2_rn(vx, vy);
                } else {
                    float2 pe = *(const float2*)&g_PE[s * 64 + dk];
                    vx = (vx + pe.x) * SC2;
                    vy = (vy + pe.y) * SC2;
                    ((__half2*)g_Qh)[off >> 1] = __floats2half2_rn(vx, vy);
                }
            }
        }
}

// ---------------------------------------------------------------------------
// EMA smear on K + PE add, output fp16
// ---------------------------------------------------------------------------
__global__ void smear_kernel(const float* __restrict__ alpha) {
    int idx = blockIdx.x * blockDim.x + threadIdx.x;
    int dk = idx & 63;
    int s  = (idx >> 6) & 2047;
    int h  = (idx >> 17) & 15;
    float kc = g_Kraw[idx];
    float v;
    if (s == 0) {
        v = kc;
    } else {
        float a = 1.0f / (1.0f + expf(-alpha[h * 2047 + (s - 1)]));
        v = a * kc + (1.0f - a) * g_Kraw[idx - 64];
    }
    v += g_PE[s * 64 + dk];
    g_Kh[idx] = __float2half_rn(v);
}

// ---------------------------------------------------------------------------
// Causal flash attention, fp16 single-pass HMMA. Smem: 2 mats (K, V).
// ---------------------------------------------------------------------------
#define ASTR 144
#define AMAT (64 * ASTR)   // 9216

__global__ __launch_bounds__(128, 4) void attn_mma() {
    __shared__ __align__(16) char sm[2 * AMAT];
    uint32_t sb = smem_u32(sm);

    int t = threadIdx.x, lane = t & 31, w = t >> 5;
    int qt = 31 - (int)blockIdx.x;          // heavy tiles first
    int qb = qt * 64;
    int bh = blockIdx.y;
    size_t base = (size_t)bh * SS * DKK;

    // ---- stage Q tile into mat0, extract A-frags ----
    {
        const char* qsrc = (const char*)(g_Qh + base);
#pragma unroll
        for (int q = 0; q < 4; q++) {
            int idx = t * 4 + q;
            int r   = idx >> 3;
            int c   = idx & 7;
            CPA16(sb + r * ASTR + c * 16,
                  qsrc + ((size_t)(qb + r) * 64 + c * 8) * 2);
        }
        CPA_COMMIT(); CPA_WAIT0();
        __syncthreads();
    }

    uint32_t qF[4][4];
    {
        int ar = w * 16 + (lane & 15);
#pragma unroll
        for (int k = 0; k < 4; k++) {
            uint32_t acol = (uint32_t)(k * 32 + (lane >> 4) * 16);
            ldsm_x4(qF[k], sb + ar * ASTR + acol);
        }
    }

    float o[8][4];
    float m2[2], lsum[2];
#pragma unroll
    for (int j = 0; j < 8; j++)
#pragma unroll
        for (int u = 0; u < 4; u++) o[j][u] = 0.0f;
    m2[0] = m2[1] = -1e30f;
    lsum[0] = lsum[1] = 0.0f;

    const char* kvsrc[2] = {(const char*)(g_Kh + base), (const char*)(g_Vh + base)};

    int r0 = (lane >> 2);
    int ntiles = qt + 1;

    for (int tile = 0; tile < ntiles; tile++) {
        int kb = tile * 64;
        __syncthreads();
#pragma unroll
        for (int q = 0; q < 8; q++) {
            int idx = t * 8 + q;
            int mat = idx >> 9;          // 0 = K, 1 = V
            int r   = (idx >> 3) & 63;
            int c   = idx & 7;
            CPA16(sb + mat * AMAT + r * ASTR + c * 16,
                  kvsrc[mat] + ((size_t)(kb + r) * 64 + c * 8) * 2);
        }
        CPA_COMMIT(); CPA_WAIT0();
        __syncthreads();

        // ---- S = Q K^T ----
        float s[8][4];
#pragma unroll
        for (int j = 0; j < 8; j++)
#pragma unroll
            for (int u = 0; u < 4; u++) s[j][u] = 0.0f;

        {
            int b_row = (lane & 7) + 8 * (lane >> 4);
#pragma unroll
            for (int k = 0; k < 4; k++) {
                uint32_t bcol = (uint32_t)((k * 16 + 8 * ((lane >> 3) & 1)) * 2);
                uint32_t kF[8][2];
#pragma unroll
                for (int tp = 0; tp < 4; tp++) {
                    uint32_t off = (uint32_t)((b_row + 16 * tp) * ASTR) + bcol;
                    ldsm_x4(&kF[2 * tp][0], sb + 0 * AMAT + off);
                }
#pragma unroll
                for (int j = 0; j < 8; j++) mma_f16(s[j], qF[k], kF[j]);
            }
        }

        // ---- mask (diagonal tile) ----
        if (tile == ntiles - 1) {
#pragma unroll
            for (int j = 0; j < 8; j++)
#pragma unroll
                for (int u = 0; u < 4; u++) {
                    int row = (w * 16) + r0 + 8 * (u >> 1);
                    int col = j * 8 + 2 * (lane & 3) + (u & 1);
                    if (col > row) s[j][u] = -1e30f;
                }
        }

        // ---- online softmax (base 2), per row half ----
#pragma unroll
        for (int h = 0; h < 2; h++) {
            float mx = -1e30f;
#pragma unroll
            for (int j = 0; j < 8; j++) {
                mx = fmaxf(mx, s[j][2 * h + 0]);
                mx = fmaxf(mx, s[j][2 * h + 1]);
            }
            mx = fmaxf(mx, __shfl_xor_sync(0xffffffffu, mx, 1));
            mx = fmaxf(mx, __shfl_xor_sync(0xffffffffu, mx, 2));
            float mnew = fmaxf(m2[h], mx);
            float corr = ex2(m2[h] - mnew);
            m2[h] = mnew;
            float rs = 0.0f;
#pragma unroll
            for (int j = 0; j < 8; j++) {
                float p0 = ex2(s[j][2 * h + 0] - mnew);
                float p1 = ex2(s[j][2 * h + 1] - mnew);
                s[j][2 * h + 0] = p0;
                s[j][2 * h + 1] = p1;
                rs += p0 + p1;
            }
            lsum[h] = lsum[h] * corr + rs;
#pragma unroll
            for (int j = 0; j < 8; j++) {
                o[j][2 * h + 0] *= corr;
                o[j][2 * h + 1] *= corr;
            }
        }

        // ---- P fragments (C->A remap, fp16) ----
        uint32_t pF[4][4];
#pragma unroll
        for (int kk = 0; kk < 4; kk++) {
            int j = 2 * kk;
#pragma unroll
            for (int q = 0; q < 4; q++) {
                int jj = j + (q >> 1);
                __half2 hp = __floats2half2_rn(s[jj][(q & 1) * 2 + 0],
                                               s[jj][(q & 1) * 2 + 1]);
                pF[kk][q] = *(uint32_t*)&hp;
            }
        }

        // ---- O += P V, V via ldmatrix.trans (mat 1) ----
        {
            int vrow = (lane & 7) + 8 * ((lane >> 3) & 1);
            uint32_t vcol = (uint32_t)(16 * (lane >> 4));
#pragma unroll
            for (int kk = 0; kk < 4; kk++) {
                uint32_t vF[8][2];
#pragma unroll
                for (int jj = 0; jj < 4; jj++) {
                    uint32_t off = (uint32_t)((kk * 16 + vrow) * ASTR) + (uint32_t)(jj * 32) + vcol;
                    ldsm_x4_t(&vF[2 * jj][0], sb + 1 * AMAT + off);
                }
#pragma unroll
                for (int j = 0; j < 8; j++) mma_f16(o[j], pF[kk], vF[j]);
            }
        }
    }

    // ---- epilogue: normalize, fp16, store ----
#pragma unroll
    for (int h = 0; h < 2; h++) {
        lsum[h] += __shfl_xor_sync(0xffffffffu, lsum[h], 1);
        lsum[h] += __shfl_xor_sync(0xffffffffu, lsum[h], 2);
        lsum[h] = 1.0f / lsum[h];
    }

    int b = bh >> 4, hh = bh & 15;
#pragma unroll
    for (int j = 0; j < 8; j++) {
        int dk = j * 8 + 2 * (lane & 3);
#pragma unroll
        for (int h = 0; h < 2; h++) {
            int srow = qb + w * 16 + r0 + 8 * h;
            float f0 = o[j][2 * h + 0] * lsum[h];
            float f1 = o[j][2 * h + 1] * lsum[h];
            size_t off = ((size_t)(b * SS + srow) * DD + hh * 64 + dk) >> 1;
            ((__half2*)g_Ah)[off] = __floats2half2_rn(f0, f1);
        }
    }
}

// ---------------------------------------------------------------------------
// Output projection GEMM: Y = attn @ Wo^T + X
// ---------------------------------------------------------------------------
__global__ __launch_bounds__(128, 2) void oproj_mma(const float* __restrict__ X) {
    extern __shared__ char dyn[];
    float acc[4][8][4];

    int m0 = blockIdx.y * 128;
    int n0 = blockIdx.x * 128;

    mma_gemm(g_Ah + (size_t)m0 * 1024, g_Woh + (size_t)n0 * 1024, dyn, acc);

    int t = threadIdx.x, lane = t & 31, wid = t >> 5;
    int wm = wid & 1, wn = wid >> 1;
#pragma unroll
    for (int tm = 0; tm < 4; tm++)
#pragma unroll
        for (int tn = 0; tn < 8; tn++) {
            int c = n0 + wn * 64 + tn * 8 + (lane & 3) * 2;
#pragma unroll
            for (int half = 0; half < 2; half++) {
                int m = m0 + wm * 64 + tm * 16 + (lane >> 2) + 8 * half;
                float2 xr = *(const float2*)&X[(size_t)m * 1024 + c];
                float2 v;
                v.x = acc[tm][tn][2 * half + 0] + xr.x;
                v.y = acc[tm][tn][2 * half + 1] + xr.y;
                *(float2*)&g_Y[(size_t)m * 1024 + c] = v;
            }
        }
}

// ---------------------------------------------------------------------------
// LayerNorm over D=1024 per row
// ---------------------------------------------------------------------------
__global__ void ln_kernel(const float* __restrict__ gamma,
                          const float* __restrict__ beta,
                          float* __restrict__ out)
{
    int row = blockIdx.x;
    int t   = threadIdx.x;
    const float* y = g_Y + (size_t)row * 1024;

    float x[4];
    float s = 0.0f;
#pragma unroll
    for (int u = 0; u < 4; u++) { x[u] = y[t + 256 * u]; s += x[u]; }

    __shared__ float red[32];
#pragma unroll
    for (int off = 16; off; off >>= 1) s += __shfl_xor_sync(0xffffffffu, s, off);
    if ((t & 31) == 0) red[t >> 5] = s;
    __syncthreads();
    if (t == 0) {
        float tot = 0.0f;
        for (int w = 0; w < 8; w++) tot += red[w];
        red[8] = tot;
    }
    __syncthreads();
    float mean = red[8] * (1.0f / 1024.0f);

    float vs = 0.0f;
#pragma unroll
    for (int u = 0; u < 4; u++) { float d = x[u] - mean; vs += d * d; }
#pragma unroll
    for (int off = 16; off; off >>= 1) vs += __shfl_xor_sync(0xffffffffu, vs, off);
    if ((t & 31) == 0) red[16 + (t >> 5)] = vs;
    __syncthreads();
    if (t == 0) {
        float tot = 0.0f;
        for (int w = 0; w < 8; w++) tot += red[16 + w];
        red[24] = tot;
    }
    __syncthreads();
    float var  = red[24] * (1.0f / 1024.0f);
    float rstd = rsqrtf(var + 1e-5f);

#pragma unroll
    for (int u = 0; u < 4; u++) {
        int c = t + 256 * u;
        out[(size_t)row * 1024 + c] = (x[u] - mean) * rstd * gamma[c] + beta[c];
    }
}

// ---------------------------------------------------------------------------
extern "C" void kernel_launch(void* const* d_in, const int* in_sizes, int n_in,
                              void* d_out, int out_size)
{
    const float* X     = (const float*)d_in[0];
    const float* Wq    = (const float*)d_in[1];
    const float* Wk    = (const float*)d_in[2];
    const float* Wv    = (const float*)d_in[3];
    const float* Wo    = (const float*)d_in[4];
    const float* alpha = (const float*)d_in[5];
    const float* lns   = (const float*)d_in[6];
    const float* lnb   = (const float*)d_in[7];
    float* out = (float*)d_out;

    static int attr_set = 0;
    if (!attr_set) {
        cudaFuncSetAttribute(qkv_mma,   cudaFuncAttributeMaxDynamicSharedMemorySize, DYN_SMEM);
        cudaFuncSetAttribute(oproj_mma, cudaFuncAttributeMaxDynamicSharedMemorySize, DYN_SMEM);
        attr_set = 1;
    }

    pe_kernel<<<(SS * DKK + 255) / 256, 256>>>();                 // 1
    convx_kernel<<<4096, 256>>>(X);                                // 2
    convw_kernel<<<4096, 256>>>(Wq, Wk, Wv, Wo);                   // 3
    qkv_mma<<<dim3(8, 32, 3), 128, DYN_SMEM>>>();                  // 4
    smear_kernel<<<(MM * DD) / 256, 256>>>(alpha);                 // 5
    attn_mma<<<dim3(32, 32), 128>>>();                             // 6
    oproj_mma<<<dim3(8, 32), 128, DYN_SMEM>>>(X);                  // 7
    ln_kernel<<<MM, 256>>>(lns, lnb, out);                         // 8
}

// round 12
// speedup vs baseline: 2.5767x; 1.0781x over previous
#include <cuda_runtime.h>
#include <cuda_fp16.h>
#include <math.h>
#include <stdint.h>

#define BB  2
#define SS  2048
#define DD  1024
#define HH  16
#define DKK 64
#define MM  (BB*SS)   // 4096 rows

// scale folded into Q: 1/sqrt(64) * log2(e)
#define SC2 0.18033688011112042f

// ---------------------------------------------------------------------------
// Scratch (allocation-free rule: __device__ globals)
// ---------------------------------------------------------------------------
__device__ __align__(16) float g_PE[SS*DKK];
__device__ __align__(16) float g_Kraw[MM*DD];
__device__ __align__(16) float g_Y[MM*DD];

__device__ __align__(16) __half g_Xh[MM*DD];
__device__ __align__(16) __half g_Wh[3*DD*DD];
__device__ __align__(16) __half g_Woh[DD*DD];
__device__ __align__(16) __half g_Ah[MM*DD];

// attention operands, head-split [B*H][S][64]
__device__ __align__(16) __half g_Qh[MM*DD];
__device__ __align__(16) __half g_Kh[MM*DD];
__device__ __align__(16) __half g_Vh[MM*DD];

// ---------------------------------------------------------------------------
// PTX helpers (baseline sm_103-safe)
// ---------------------------------------------------------------------------
__device__ __forceinline__ uint32_t smem_u32(const void* p) {
    uint32_t a;
    asm("{ .reg .u64 t; cvta.to.shared.u64 t, %1; cvt.u32.u64 %0, t; }"
        : "=r"(a) : "l"(p));
    return a;
}

#define CPA16(dst, src) \
    asm volatile("cp.async.cg.shared.global [%0], [%1], 16;" :: "r"(dst), "l"(src) : "memory")
#define CPA_COMMIT() asm volatile("cp.async.commit_group;" ::: "memory")
#define CPA_WAIT1()  asm volatile("cp.async.wait_group 1;" ::: "memory")
#define CPA_WAIT0()  asm volatile("cp.async.wait_group 0;" ::: "memory")

__device__ __forceinline__ void ldsm_x4(uint32_t* r, uint32_t addr) {
    asm volatile("ldmatrix.sync.aligned.m8n8.x4.shared.b16 {%0,%1,%2,%3}, [%4];"
                 : "=r"(r[0]), "=r"(r[1]), "=r"(r[2]), "=r"(r[3]) : "r"(addr));
}
__device__ __forceinline__ void ldsm_x4_t(uint32_t* r, uint32_t addr) {
    asm volatile("ldmatrix.sync.aligned.m8n8.x4.trans.shared.b16 {%0,%1,%2,%3}, [%4];"
                 : "=r"(r[0]), "=r"(r[1]), "=r"(r[2]), "=r"(r[3]) : "r"(addr));
}

__device__ __forceinline__ void mma_f16(float* c, const uint32_t* a, const uint32_t* b) {
    asm volatile(
        "mma.sync.aligned.m16n8k16.row.col.f32.f16.f16.f32 "
        "{%0,%1,%2,%3}, {%4,%5,%6,%7}, {%8,%9}, {%0,%1,%2,%3};"
        : "+f"(c[0]), "+f"(c[1]), "+f"(c[2]), "+f"(c[3])
        : "r"(a[0]), "r"(a[1]), "r"(a[2]), "r"(a[3]), "r"(b[0]), "r"(b[1]));
}

__device__ __forceinline__ float ex2(float x) {
    float r;
    asm("ex2.approx.ftz.f32 %0, %1;" : "=f"(r) : "f"(x));
    return r;
}

// ---------------------------------------------------------------------------
__global__ void pe_kernel() {
    int idx = blockIdx.x * blockDim.x + threadIdx.x;
    if (idx >= SS * DKK) return;
    int s  = idx >> 6;
    int dk = idx & 63;
    int i  = dk >> 1;
    float freq = expf(-((float)(2 * i) / 64.0f) * 9.210340371976184f);
    float ang  = (float)s * freq;
    g_PE[idx]  = (dk & 1) ? cosf(ang) : sinf(ang);
}

// ---------------------------------------------------------------------------
// fp32 -> fp16 conversions
// ---------------------------------------------------------------------------
__global__ void convx_kernel(const float* __restrict__ src) {
    int i = blockIdx.x * blockDim.x + threadIdx.x;   // MM*DD/4
    float4 v = ((const float4*)src)[i];
    __half2* hp = (__half2*)g_Xh;
    hp[2*i]   = __floats2half2_rn(v.x, v.y);
    hp[2*i+1] = __floats2half2_rn(v.z, v.w);
}

__global__ void convw_kernel(const float* __restrict__ Wq, const float* __restrict__ Wk,
                             const float* __restrict__ Wv, const float* __restrict__ Wo) {
    int gi  = blockIdx.x * blockDim.x + threadIdx.x;  // 4 * DD*DD/4
    int mat = gi >> 18;
    int i   = gi & 0x3FFFF;
    const float* src = (mat == 0) ? Wq : (mat == 1) ? Wk : (mat == 2) ? Wv : Wo;
    __half2* hp = (mat < 3) ? (__half2*)(g_Wh + (size_t)mat * DD * DD)
                            : (__half2*)g_Woh;
    float4 v = ((const float4*)src)[i];
    hp[2*i]   = __floats2half2_rn(v.x, v.y);
    hp[2*i+1] = __floats2half2_rn(v.z, v.w);
}

// ---------------------------------------------------------------------------
// fp16 single-pass HMMA GEMM (proven R11, unchanged)
// ---------------------------------------------------------------------------
#define MATB 8192            // 128 * 64
#define STG  (2 * MATB)      // 16384
#define DYN_SMEM (3 * STG)   // 49152

__device__ __forceinline__ void mma_gemm(
    const __half* __restrict__ A, const __half* __restrict__ B,
    char* dyn, float acc[4][8][4])
{
    int t    = threadIdx.x;
    int lane = t & 31;
    int wid  = t >> 5;
    int wm   = wid & 1;
    int wn   = wid >> 1;
    uint32_t sbase = smem_u32(dyn);

    const char* mats[2] = {(const char*)A, (const char*)B};

#pragma unroll
    for (int tm = 0; tm < 4; tm++)
#pragma unroll
        for (int tn = 0; tn < 8; tn++)
#pragma unroll
            for (int u = 0; u < 4; u++) acc[tm][tn][u] = 0.0f;

    int idx0 = t * 8;
    auto load_stage = [&](int st, int kb) {
        uint32_t stb = sbase + st * STG;
#pragma unroll
        for (int q = 0; q < 8; q++) {
            int idx = idx0 + q;
            int mat = idx >> 9;
            int r   = (idx >> 2) & 127;
            int c   = idx & 3;
            uint32_t dst = stb + mat * MATB + r * 64 + ((c ^ ((r >> 1) & 3)) << 4);
            const char* src = mats[mat] + ((size_t)r * 1024 + kb + c * 8) * 2;
            CPA16(dst, src);
        }
        CPA_COMMIT();
    };

    int a_hi = lane >> 4;
    int b_hi = (lane >> 3) & 1;
    uint32_t aOff[4]; int aMsk[4];
#pragma unroll
    for (int tm = 0; tm < 4; tm++) {
        int r = wm * 64 + (lane & 15) + 16 * tm;
        aOff[tm] = (uint32_t)(r * 64);
        aMsk[tm] = (r >> 1) & 3;
    }
    uint32_t bOff[4]; int bMsk[4];
#pragma unroll
    for (int tp = 0; tp < 4; tp++) {
        int r = wn * 64 + (lane & 7) + 8 * (lane >> 4) + 16 * tp;
        bOff[tp] = (uint32_t)(r * 64);
        bMsk[tp] = (r >> 1) & 3;
    }

    load_stage(0, 0);
    load_stage(1, 32);

    int st = 0;
    for (int it = 0; it < 32; it++) {
        if (it < 31) { CPA_WAIT1(); } else { CPA_WAIT0(); }
        __syncthreads();
        if (it + 2 < 32) {
            int s2 = st + 2; if (s2 >= 3) s2 -= 3;
            load_stage(s2, (it + 2) * 32);
        }

        uint32_t stb = sbase + st * STG;
#pragma unroll
        for (int ks = 0; ks < 2; ks++) {
            int cA = 2 * ks + a_hi;
            int cB = 2 * ks + b_hi;
            uint32_t aF[4][4], bF[8][2];
#pragma unroll
            for (int tm = 0; tm < 4; tm++) {
                uint32_t off = aOff[tm] + (uint32_t)((cA ^ aMsk[tm]) << 4);
                ldsm_x4(aF[tm], stb + 0 * MATB + off);
            }
#pragma unroll
            for (int tp = 0; tp < 4; tp++) {
                uint32_t off = bOff[tp] + (uint32_t)((cB ^ bMsk[tp]) << 4);
                ldsm_x4(&bF[2 * tp][0], stb + 1 * MATB + off);
            }
#pragma unroll
            for (int tm = 0; tm < 4; tm++)
#pragma unroll
                for (int tn = 0; tn < 8; tn++)
                    mma_f16(acc[tm][tn], aF[tm], bF[tn]);
        }
        st++; if (st == 3) st = 0;
    }
    __syncthreads();
}

// ---------------------------------------------------------------------------
// QKV GEMM. z=0: Q -> (acc+PE)*SC2 fp16; z=1: K fp32; z=2: V fp16
// ---------------------------------------------------------------------------
__global__ __launch_bounds__(128, 2) void qkv_mma() {
    extern __shared__ char dyn[];
    float acc[4][8][4];

    int z  = blockIdx.z;
    int m0 = blockIdx.y * 128;
    int n0 = blockIdx.x * 128;

    mma_gemm(g_Xh + (size_t)m0 * 1024,
             g_Wh + (size_t)z * DD * DD + (size_t)n0 * 1024,
             dyn, acc);

    int t = threadIdx.x, lane = t & 31, wid = t >> 5;
    int wm = wid & 1, wn = wid >> 1;

#pragma unroll
    for (int tm = 0; tm < 4; tm++)
#pragma unroll
        for (int tn = 0; tn < 8; tn++) {
            int c  = n0 + wn * 64 + tn * 8 + (lane & 3) * 2;
            int h  = c >> 6, dk = c & 63;
#pragma unroll
            for (int half = 0; half < 2; half++) {
                int m = m0 + wm * 64 + tm * 16 + (lane >> 2) + 8 * half;
                int b = m >> 11, s = m & 2047;
                float vx = acc[tm][tn][2 * half + 0];
                float vy = acc[tm][tn][2 * half + 1];
                size_t off = ((size_t)((b * 16 + h) * 2048 + s)) * 64 + dk;
                if (z == 1) {
                    float2 v; v.x = vx; v.y = vy;
                    *(float2*)&g_Kraw[off] = v;
                } else if (z == 2) {
                    ((__half2*)g_Vh)[off >> 1] = __floats2half2_rn(vx, vy);
                } else {
                    float2 pe = *(const float2*)&g_PE[s * 64 + dk];
                    vx = (vx + pe.x) * SC2;
                    vy = (vy + pe.y) * SC2;
                    ((__half2*)g_Qh)[off >> 1] = __floats2half2_rn(vx, vy);
                }
            }
        }
}

// ---------------------------------------------------------------------------
// EMA smear on K + PE add, output fp16
// ---------------------------------------------------------------------------
__global__ void smear_kernel(const float* __restrict__ alpha) {
    int idx = blockIdx.x * blockDim.x + threadIdx.x;
    int dk = idx & 63;
    int s  = (idx >> 6) & 2047;
    int h  = (idx >> 17) & 15;
    float kc = g_Kraw[idx];
    float v;
    if (s == 0) {
        v = kc;
    } else {
        float a = 1.0f / (1.0f + expf(-alpha[h * 2047 + (s - 1)]));
        v = a * kc + (1.0f - a) * g_Kraw[idx - 64];
    }
    v += g_PE[s * 64 + dk];
    g_Kh[idx] = __float2half_rn(v);
}

// ---------------------------------------------------------------------------
// Causal flash attention, fp16 HMMA. BM=128 (8 warps, 256 thr), BN=64.
// 2-stage double-buffered KV pipeline. Smem: 2 stages x (K,V) = 36864B;
// the Q tile (128 x 144B) is staged in the same region before the mainloop.
// ---------------------------------------------------------------------------
#define ASTR 144
#define AMAT (64 * ASTR)    // 9216
#define KVSTG (2 * AMAT)    // 18432 per stage

__global__ __launch_bounds__(256, 2) void attn_mma() {
    __shared__ __align__(16) char sm[2 * KVSTG];
    uint32_t sb = smem_u32(sm);

    int t = threadIdx.x, lane = t & 31, w = t >> 5;   // w = 0..7
    int qt = 15 - (int)blockIdx.x;          // heavy tiles first
    int qb = qt * 128;
    int bh = blockIdx.y;
    size_t base = (size_t)bh * SS * DKK;

    // ---- stage Q tile (128 rows x 64 fp16) into sm[0..18432), extract frags ----
    {
        const char* qsrc = (const char*)(g_Qh + base);
#pragma unroll
        for (int q = 0; q < 4; q++) {
            int idx = t * 4 + q;        // 1024 chunks
            int r   = idx >> 3;
            int c   = idx & 7;
            CPA16(sb + r * ASTR + c * 16,
                  qsrc + ((size_t)(qb + r) * 64 + c * 8) * 2);
        }
        CPA_COMMIT(); CPA_WAIT0();
        __syncthreads();
    }

    uint32_t qF[4][4];
    {
        int ar = w * 16 + (lane & 15);   // 0..127
#pragma unroll
        for (int k = 0; k < 4; k++) {
            uint32_t acol = (uint32_t)(k * 32 + (lane >> 4) * 16);
            ldsm_x4(qF[k], sb + ar * ASTR + acol);
        }
    }
    __syncthreads();   // Q frags extracted before the region is reused for KV

    float o[8][4];
    float m2[2], lsum[2];
#pragma unroll
    for (int j = 0; j < 8; j++)
#pragma unroll
        for (int u = 0; u < 4; u++) o[j][u] = 0.0f;
    m2[0] = m2[1] = -1e30f;
    lsum[0] = lsum[1] = 0.0f;

    const char* kvsrc[2] = {(const char*)(g_Kh + base), (const char*)(g_Vh + base)};

    auto load_kv = [&](int tile, int st) {
        uint32_t stb = sb + st * KVSTG;
        int kb = tile * 64;
#pragma unroll
        for (int q = 0; q < 4; q++) {
            int idx = t * 4 + q;          // 1024 chunks: K then V
            int mat = idx >> 9;
            int r   = (idx >> 3) & 63;
            int c   = idx & 7;
            CPA16(stb + mat * AMAT + r * ASTR + c * 16,
                  kvsrc[mat] + ((size_t)(kb + r) * 64 + c * 8) * 2);
        }
        CPA_COMMIT();
    };

    int r0 = (lane >> 2);
    int ntiles = 2 * qt + 2;

    load_kv(0, 0);
    if (ntiles > 1) load_kv(1, 1);

    for (int tile = 0; tile < ntiles; tile++) {
        int kb = tile * 64;
        int st = tile & 1;
        if (tile + 1 < ntiles) { CPA_WAIT1(); } else { CPA_WAIT0(); }
        __syncthreads();

        uint32_t stb = sb + st * KVSTG;
        bool active = (kb <= qb + w * 16 + 15);   // skip fully-masked tiles

        if (active) {
            // ---- S = Q K^T ----
            float s[8][4];
#pragma unroll
            for (int j = 0; j < 8; j++)
#pragma unroll
                for (int u = 0; u < 4; u++) s[j][u] = 0.0f;

            {
                int b_row = (lane & 7) + 8 * (lane >> 4);
#pragma unroll
                for (int k = 0; k < 4; k++) {
                    uint32_t bcol = (uint32_t)((k * 16 + 8 * ((lane >> 3) & 1)) * 2);
                    uint32_t kF[8][2];
#pragma unroll
                    for (int tp = 0; tp < 4; tp++) {
                        uint32_t off = (uint32_t)((b_row + 16 * tp) * ASTR) + bcol;
                        ldsm_x4(&kF[2 * tp][0], stb + 0 * AMAT + off);
                    }
#pragma unroll
                    for (int j = 0; j < 8; j++) mma_f16(s[j], qF[k], kF[j]);
                }
            }

            // ---- mask (global row/col) ----
            if (kb + 63 > qb + w * 16) {
#pragma unroll
                for (int j = 0; j < 8; j++)
#pragma unroll
                    for (int u = 0; u < 4; u++) {
                        int row = qb + w * 16 + r0 + 8 * (u >> 1);
                        int col = kb + j * 8 + 2 * (lane & 3) + (u & 1);
                        if (col > row) s[j][u] = -1e30f;
                    }
            }

            // ---- online softmax (base 2), per row half ----
#pragma unroll
            for (int h = 0; h < 2; h++) {
                float mx = -1e30f;
#pragma unroll
                for (int j = 0; j < 8; j++) {
                    mx = fmaxf(mx, s[j][2 * h + 0]);
                    mx = fmaxf(mx, s[j][2 * h + 1]);
                }
                mx = fmaxf(mx, __shfl_xor_sync(0xffffffffu, mx, 1));
                mx = fmaxf(mx, __shfl_xor_sync(0xffffffffu, mx, 2));
                float mnew = fmaxf(m2[h], mx);
                float corr = ex2(m2[h] - mnew);
                m2[h] = mnew;
                float rs = 0.0f;
#pragma unroll
                for (int j = 0; j < 8; j++) {
                    float p0 = ex2(s[j][2 * h + 0] - mnew);
                    float p1 = ex2(s[j][2 * h + 1] - mnew);
                    s[j][2 * h + 0] = p0;
                    s[j][2 * h + 1] = p1;
                    rs += p0 + p1;
                }
                lsum[h] = lsum[h] * corr + rs;
#pragma unroll
                for (int j = 0; j < 8; j++) {
                    o[j][2 * h + 0] *= corr;
                    o[j][2 * h + 1] *= corr;
                }
            }

            // ---- P fragments (C->A remap, fp16) ----
            uint32_t pF[4][4];
#pragma unroll
            for (int kk = 0; kk < 4; kk++) {
                int j = 2 * kk;
#pragma unroll
                for (int q = 0; q < 4; q++) {
                    int jj = j + (q >> 1);
                    __half2 hp = __floats2half2_rn(s[jj][(q & 1) * 2 + 0],
                                                   s[jj][(q & 1) * 2 + 1]);
                    pF[kk][q] = *(uint32_t*)&hp;
                }
            }

            // ---- O += P V, V via ldmatrix.trans (mat 1) ----
            {
                int vrow = (lane & 7) + 8 * ((lane >> 3) & 1);
                uint32_t vcol = (uint32_t)(16 * (lane >> 4));
#pragma unroll
                for (int kk = 0; kk < 4; kk++) {
                    uint32_t vF[8][2];
#pragma unroll
                    for (int jj = 0; jj < 4; jj++) {
                        uint32_t off = (uint32_t)((kk * 16 + vrow) * ASTR) + (uint32_t)(jj * 32) + vcol;
                        ldsm_x4_t(&vF[2 * jj][0], stb + 1 * AMAT + off);
                    }
#pragma unroll
                    for (int j = 0; j < 8; j++) mma_f16(o[j], pF[kk], vF[j]);
                }
            }
        }

        __syncthreads();   // all warps done with stage st before refill
        if (tile + 2 < ntiles) load_kv(tile + 2, st);
    }

    // ---- epilogue: normalize, fp16, store ----
#pragma unroll
    for (int h = 0; h < 2; h++) {
        lsum[h] += __shfl_xor_sync(0xffffffffu, lsum[h], 1);
        lsum[h] += __shfl_xor_sync(0xffffffffu, lsum[h], 2);
        lsum[h] = 1.0f / lsum[h];
    }

    int b = bh >> 4, hh = bh & 15;
#pragma unroll
    for (int j = 0; j < 8; j++) {
        int dk = j * 8 + 2 * (lane & 3);
#pragma unroll
        for (int h = 0; h < 2; h++) {
            int srow = qb + w * 16 + r0 + 8 * h;
            float f0 = o[j][2 * h + 0] * lsum[h];
            float f1 = o[j][2 * h + 1] * lsum[h];
            size_t off = ((size_t)(b * SS + srow) * DD + hh * 64 + dk) >> 1;
            ((__half2*)g_Ah)[off] = __floats2half2_rn(f0, f1);
        }
    }
}

// ---------------------------------------------------------------------------
// Output projection GEMM: Y = attn @ Wo^T + X
// ---------------------------------------------------------------------------
__global__ __launch_bounds__(128, 2) void oproj_mma(const float* __restrict__ X) {
    extern __shared__ char dyn[];
    float acc[4][8][4];

    int m0 = blockIdx.y * 128;
    int n0 = blockIdx.x * 128;

    mma_gemm(g_Ah + (size_t)m0 * 1024, g_Woh + (size_t)n0 * 1024, dyn, acc);

    int t = threadIdx.x, lane = t & 31, wid = t >> 5;
    int wm = wid & 1, wn = wid >> 1;
#pragma unroll
    for (int tm = 0; tm < 4; tm++)
#pragma unroll
        for (int tn = 0; tn < 8; tn++) {
            int c = n0 + wn * 64 + tn * 8 + (lane & 3) * 2;
#pragma unroll
            for (int half = 0; half < 2; half++) {
                int m = m0 + wm * 64 + tm * 16 + (lane >> 2) + 8 * half;
                float2 xr = *(const float2*)&X[(size_t)m * 1024 + c];
                float2 v;
                v.x = acc[tm][tn][2 * half + 0] + xr.x;
                v.y = acc[tm][tn][2 * half + 1] + xr.y;
                *(float2*)&g_Y[(size_t)m * 1024 + c] = v;
            }
        }
}

// ---------------------------------------------------------------------------
// LayerNorm over D=1024 per row
// ---------------------------------------------------------------------------
__global__ void ln_kernel(const float* __restrict__ gamma,
                          const float* __restrict__ beta,
                          float* __restrict__ out)
{
    int row = blockIdx.x;
    int t   = threadIdx.x;
    const float* y = g_Y + (size_t)row * 1024;

    float x[4];
    float s = 0.0f;
#pragma unroll
    for (int u = 0; u < 4; u++) { x[u] = y[t + 256 * u]; s += x[u]; }

    __shared__ float red[32];
#pragma unroll
    for (int off = 16; off; off >>= 1) s += __shfl_xor_sync(0xffffffffu, s, off);
    if ((t & 31) == 0) red[t >> 5] = s;
    __syncthreads();
    if (t == 0) {
        float tot = 0.0f;
        for (int w = 0; w < 8; w++) tot += red[w];
        red[8] = tot;
    }
    __syncthreads();
    float mean = red[8] * (1.0f / 1024.0f);

    float vs = 0.0f;
#pragma unroll
    for (int u = 0; u < 4; u++) { float d = x[u] - mean; vs += d * d; }
#pragma unroll
    for (int off = 16; off; off >>= 1) vs += __shfl_xor_sync(0xffffffffu, vs, off);
    if ((t & 31) == 0) red[16 + (t >> 5)] = vs;
    __syncthreads();
    if (t == 0) {
        float tot = 0.0f;
        for (int w = 0; w < 8; w++) tot += red[16 + w];
        red[24] = tot;
    }
    __syncthreads();
    float var  = red[24] * (1.0f / 1024.0f);
    float rstd = rsqrtf(var + 1e-5f);

#pragma unroll
    for (int u = 0; u < 4; u++) {
        int c = t + 256 * u;
        out[(size_t)row * 1024 + c] = (x[u] - mean) * rstd * gamma[c] + beta[c];
    }
}

// ---------------------------------------------------------------------------
extern "C" void kernel_launch(void* const* d_in, const int* in_sizes, int n_in,
                              void* d_out, int out_size)
{
    const float* X     = (const float*)d_in[0];
    const float* Wq    = (const float*)d_in[1];
    const float* Wk    = (const float*)d_in[2];
    const float* Wv    = (const float*)d_in[3];
    const float* Wo    = (const float*)d_in[4];
    const float* alpha = (const float*)d_in[5];
    const float* lns   = (const float*)d_in[6];
    const float* lnb   = (const float*)d_in[7];
    float* out = (float*)d_out;

    static int attr_set = 0;
    if (!attr_set) {
        cudaFuncSetAttribute(qkv_mma,   cudaFuncAttributeMaxDynamicSharedMemorySize, DYN_SMEM);
        cudaFuncSetAttribute(oproj_mma, cudaFuncAttributeMaxDynamicSharedMemorySize, DYN_SMEM);
        attr_set = 1;
    }

    pe_kernel<<<(SS * DKK + 255) / 256, 256>>>();                 // 1
    convx_kernel<<<4096, 256>>>(X);                                // 2
    convw_kernel<<<4096, 256>>>(Wq, Wk, Wv, Wo);                   // 3
    qkv_mma<<<dim3(8, 32, 3), 128, DYN_SMEM>>>();                  // 4
    smear_kernel<<<(MM * DD) / 256, 256>>>(alpha);                 // 5
    attn_mma<<<dim3(16, 32), 256>>>();                             // 6
    oproj_mma<<<dim3(8, 32), 128, DYN_SMEM>>>(X);                  // 7
    ln_kernel<<<MM, 256>>>(lns, lnb, out);                         // 8
}